// round 3
// baseline (speedup 1.0000x reference)
#include <cuda_runtime.h>
#include <cuda_bf16.h>
#include <math.h>
#include <stdint.h>

// ---------------- problem constants ----------------
#define BB   4
#define TT   256
#define TAA  1500
#define DD   768
#define HH   12
#define LL   12
#define VV   51865
#define DHH  64
#define BT   (BB*TT)          // 1024
#define SCALE_Q 0.125f
#define BTAD ((size_t)BB*TAA*DD)

// ---------------- scratch ----------------
__device__ float g_x  [BT*DD];
__device__ float g_h  [BT*DD];
__device__ float g_q  [BT*DD];
__device__ float g_o  [BT*DD];
__device__ float g_sc [(size_t)BB*HH*TT*TAA];
__device__ float g_ckall[(size_t)LL*BTAD];      // cross keys, all layers
__device__ float g_cvall[(size_t)LL*BTAD];      // cross values, all layers
__device__ float g_hid[(size_t)BT*4*DD];

// ---------------- 3xTF32 tensor-core GEMM ----------------
// C = act((A@B(^T) + bias)*scale) + res ; optional mirror write for zb==0.
// Block 64x64x32, 256 threads, 8 warps (2x4), warp tile 32x16.
// Full-precision via hi/lo tf32 split: C += Ah*Bh + Ah*Bl + Al*Bh.
#define TBM 64
#define TBN 64
#define TBK 32
#define ALD 36   // lane addr 4g+tig mod 32 distinct -> conflict-free
#define BLD 72   // lane addr 8tig+g mod 32 distinct -> conflict-free

__device__ __forceinline__ float to_tf32(float x) {
    uint32_t u;
    asm("cvt.rna.tf32.f32 %0, %1;" : "=r"(u) : "f"(x));
    return __uint_as_float(u);
}

__device__ __forceinline__ void mma_tf32(float* c,
                                         const uint32_t* a, const uint32_t* b) {
    asm volatile(
        "mma.sync.aligned.m16n8k8.row.col.f32.tf32.tf32.f32 "
        "{%0,%1,%2,%3}, {%4,%5,%6,%7}, {%8,%9}, {%0,%1,%2,%3};"
        : "+f"(c[0]), "+f"(c[1]), "+f"(c[2]), "+f"(c[3])
        : "r"(a[0]), "r"(a[1]), "r"(a[2]), "r"(a[3]), "r"(b[0]), "r"(b[1]));
}

template <int NT>
__global__ __launch_bounds__(256, 2) void gemm3_kernel(
    int M, int N, int K,
    const float* __restrict__ A, int lda, long sA0, long sA1,
    const float* __restrict__ B, int ldb, long sB0, long sB1,
    float* __restrict__ C, int ldc, long sC0, long sC1,
    int Hd,
    const float* __restrict__ bias, long sBias,
    const float* __restrict__ res,
    float* __restrict__ Mir,
    float scale, int act)
{
    __shared__ float AsH[TBM][ALD];
    __shared__ float AsL[TBM][ALD];
    __shared__ float BsH[TBK][BLD];
    __shared__ float BsL[TBK][BLD];

    int z = blockIdx.z;
    int zb = z / Hd, zh = z % Hd;
    A += zb * sA0 + zh * sA1;
    B += zb * sB0 + zh * sB1;
    C += zb * sC0 + zh * sC1;
    const float* R = res ? (res + zb * sC0 + zh * sC1) : nullptr;
    float* Mr = (Mir && zb == 0) ? (Mir + zh * sC1) : nullptr;
    const float* Bi = bias ? (bias + zh * sBias) : nullptr;

    int tid  = threadIdx.x;
    int lane = tid & 31;
    int warp = tid >> 5;
    int g    = lane >> 2;
    int tig  = lane & 3;
    int m0w  = (warp & 1) * 32;
    int n0w  = (warp >> 1) * 16;

    int bm = blockIdx.y * TBM, bn = blockIdx.x * TBN;

    float c[2][2][4];
#pragma unroll
    for (int mi = 0; mi < 2; mi++)
#pragma unroll
        for (int ni = 0; ni < 2; ni++)
#pragma unroll
            for (int e = 0; e < 4; e++) c[mi][ni][e] = 0.f;

    int iters = (K + TBK - 1) / TBK;
    float ra[8], rb[8];

    // prefetch tile 0
    {
        int kk = 0;
#pragma unroll
        for (int i = 0; i < 8; i++) {
            int idx = i * 256 + tid;
            int r = idx >> 5, cc = idx & 31;
            ra[i] = (bm + r < M && kk + cc < K) ? A[(long)(bm + r) * lda + kk + cc] : 0.f;
        }
#pragma unroll
        for (int i = 0; i < 8; i++) {
            int idx = i * 256 + tid;
            if (NT) {
                int nc = idx >> 5, kr = idx & 31;
                rb[i] = (bn + nc < N && kk + kr < K) ? B[(long)(bn + nc) * ldb + kk + kr] : 0.f;
            } else {
                int kr = idx >> 6, nc = idx & 63;
                rb[i] = (kk + kr < K && bn + nc < N) ? B[(long)(kk + kr) * ldb + bn + nc] : 0.f;
            }
        }
    }

    for (int it = 0; it < iters; it++) {
        // store current tile with hi/lo split
#pragma unroll
        for (int i = 0; i < 8; i++) {
            int idx = i * 256 + tid;
            int r = idx >> 5, cc = idx & 31;
            float v = ra[i];
            float hi = to_tf32(v);
            AsH[r][cc] = hi;
            AsL[r][cc] = to_tf32(v - hi);
        }
#pragma unroll
        for (int i = 0; i < 8; i++) {
            int idx = i * 256 + tid;
            int kr, nc;
            if (NT) { nc = idx >> 5; kr = idx & 31; }
            else    { kr = idx >> 6; nc = idx & 63; }
            float v = rb[i];
            float hi = to_tf32(v);
            BsH[kr][nc] = hi;
            BsL[kr][nc] = to_tf32(v - hi);
        }
        __syncthreads();

        // prefetch next tile
        if (it + 1 < iters) {
            int kk = (it + 1) * TBK;
#pragma unroll
            for (int i = 0; i < 8; i++) {
                int idx = i * 256 + tid;
                int r = idx >> 5, cc = idx & 31;
                ra[i] = (bm + r < M && kk + cc < K) ? A[(long)(bm + r) * lda + kk + cc] : 0.f;
            }
#pragma unroll
            for (int i = 0; i < 8; i++) {
                int idx = i * 256 + tid;
                if (NT) {
                    int nc = idx >> 5, kr = idx & 31;
                    rb[i] = (bn + nc < N && kk + kr < K) ? B[(long)(bn + nc) * ldb + kk + kr] : 0.f;
                } else {
                    int kr = idx >> 6, nc = idx & 63;
                    rb[i] = (kk + kr < K && bn + nc < N) ? B[(long)(kk + kr) * ldb + bn + nc] : 0.f;
                }
            }
        }

#pragma unroll
        for (int k8 = 0; k8 < TBK; k8 += 8) {
            uint32_t aH[2][4], aL[2][4], bH[2][2], bL[2][2];
#pragma unroll
            for (int mi = 0; mi < 2; mi++) {
                int m = m0w + mi * 16 + g;
                aH[mi][0] = __float_as_uint(AsH[m    ][k8 + tig    ]);
                aH[mi][1] = __float_as_uint(AsH[m + 8][k8 + tig    ]);
                aH[mi][2] = __float_as_uint(AsH[m    ][k8 + tig + 4]);
                aH[mi][3] = __float_as_uint(AsH[m + 8][k8 + tig + 4]);
                aL[mi][0] = __float_as_uint(AsL[m    ][k8 + tig    ]);
                aL[mi][1] = __float_as_uint(AsL[m + 8][k8 + tig    ]);
                aL[mi][2] = __float_as_uint(AsL[m    ][k8 + tig + 4]);
                aL[mi][3] = __float_as_uint(AsL[m + 8][k8 + tig + 4]);
            }
#pragma unroll
            for (int ni = 0; ni < 2; ni++) {
                int n = n0w + ni * 8 + g;
                bH[ni][0] = __float_as_uint(BsH[k8 + tig    ][n]);
                bH[ni][1] = __float_as_uint(BsH[k8 + tig + 4][n]);
                bL[ni][0] = __float_as_uint(BsL[k8 + tig    ][n]);
                bL[ni][1] = __float_as_uint(BsL[k8 + tig + 4][n]);
            }
#pragma unroll
            for (int mi = 0; mi < 2; mi++)
#pragma unroll
                for (int ni = 0; ni < 2; ni++) {
                    mma_tf32(c[mi][ni], aH[mi], bL[ni]);
                    mma_tf32(c[mi][ni], aL[mi], bH[ni]);
                    mma_tf32(c[mi][ni], aH[mi], bH[ni]);
                }
        }
        __syncthreads();
    }

    // epilogue
#pragma unroll
    for (int mi = 0; mi < 2; mi++) {
#pragma unroll
        for (int ni = 0; ni < 2; ni++) {
#pragma unroll
            for (int e = 0; e < 4; e++) {
                int row = bm + m0w + mi * 16 + g + ((e >= 2) ? 8 : 0);
                int col = bn + n0w + ni * 8 + tig * 2 + (e & 1);
                if (row >= M || col >= N) continue;
                float v = c[mi][ni][e];
                if (Bi) v += Bi[col];
                v *= scale;
                if (act == 1) v = 0.5f * v * (1.f + erff(v * 0.70710678118654752f));
                long ci = (long)row * ldc + col;
                if (R) v += R[ci];
                C[ci] = v;
                if (Mr) Mr[ci] = v;
            }
        }
    }
}

// ---------------- elementwise / row kernels ----------------
__global__ __launch_bounds__(256) void embed_kernel(
    const int* __restrict__ tokens, const float* __restrict__ tok_emb,
    const float* __restrict__ pos_emb, float* __restrict__ x)
{
    int row = blockIdx.x;
    int t = row % TT;
    int tok = tokens[row];
    const float* te = tok_emb + (long)tok * DD;
    const float* pe = pos_emb + (long)t * DD;
    float* xr = x + (long)row * DD;
#pragma unroll
    for (int it = 0; it < 3; it++) {
        int j = threadIdx.x + it * 256;
        xr[j] = te[j] + pe[j];
    }
}

__global__ __launch_bounds__(256) void ln_kernel(
    const float* __restrict__ x, float* __restrict__ y,
    const float* __restrict__ g, const float* __restrict__ b)
{
    __shared__ float red[256];
    int row = blockIdx.x;
    const float* xr = x + (long)row * DD;
    float* yr = y + (long)row * DD;
    int tid = threadIdx.x;
    float v0 = xr[tid], v1 = xr[tid + 256], v2 = xr[tid + 512];
    float s = v0 + v1 + v2;
    red[tid] = s; __syncthreads();
    for (int st = 128; st > 0; st >>= 1) { if (tid < st) red[tid] += red[tid + st]; __syncthreads(); }
    float mean = red[0] * (1.f / DD);
    __syncthreads();
    float d0 = v0 - mean, d1 = v1 - mean, d2 = v2 - mean;
    red[tid] = d0 * d0 + d1 * d1 + d2 * d2; __syncthreads();
    for (int st = 128; st > 0; st >>= 1) { if (tid < st) red[tid] += red[tid + st]; __syncthreads(); }
    float inv = rsqrtf(red[0] * (1.f / DD) + 1e-5f);
    yr[tid]       = d0 * inv * g[tid]       + b[tid];
    yr[tid + 256] = d1 * inv * g[tid + 256] + b[tid + 256];
    yr[tid + 512] = d2 * inv * g[tid + 512] + b[tid + 512];
}

__global__ __launch_bounds__(256) void softmax_causal_kernel(float* __restrict__ S)
{
    __shared__ float red[256];
    int row = blockIdx.x;
    int i = row & (TT - 1);
    float* p = S + (long)row * TT;
    int tid = threadIdx.x;
    float v = (tid <= i) ? p[tid] : -1e30f;
    red[tid] = v; __syncthreads();
    for (int st = 128; st > 0; st >>= 1) { if (tid < st) red[tid] = fmaxf(red[tid], red[tid + st]); __syncthreads(); }
    float m = red[0]; __syncthreads();
    float e = (tid <= i) ? expf(v - m) : 0.f;
    red[tid] = e; __syncthreads();
    for (int st = 128; st > 0; st >>= 1) { if (tid < st) red[tid] += red[tid + st]; __syncthreads(); }
    p[tid] = e / red[0];
}

__global__ __launch_bounds__(256) void softmax_plain_kernel(float* __restrict__ S, int len)
{
    __shared__ float red[256];
    int row = blockIdx.x;
    float* p = S + (long)row * len;
    int tid = threadIdx.x;
    float vals[6];
    float m = -1e30f;
#pragma unroll
    for (int it = 0; it < 6; it++) {
        int j = tid + it * 256;
        float v = (j < len) ? p[j] : -1e30f;
        vals[it] = v;
        m = fmaxf(m, v);
    }
    red[tid] = m; __syncthreads();
    for (int st = 128; st > 0; st >>= 1) { if (tid < st) red[tid] = fmaxf(red[tid], red[tid + st]); __syncthreads(); }
    m = red[0]; __syncthreads();
    float s = 0.f;
#pragma unroll
    for (int it = 0; it < 6; it++) {
        int j = tid + it * 256;
        float e = (j < len) ? expf(vals[it] - m) : 0.f;
        vals[it] = e;
        s += e;
    }
    red[tid] = s; __syncthreads();
    for (int st = 128; st > 0; st >>= 1) { if (tid < st) red[tid] += red[tid + st]; __syncthreads(); }
    float inv = 1.f / red[0];
#pragma unroll
    for (int it = 0; it < 6; it++) {
        int j = tid + it * 256;
        if (j < len) p[j] = vals[it] * inv;
    }
}

// ---------------- host-side launch helpers ----------------
static inline void launch_nn(int M, int N, int K,
                             const float* A, int lda, long sA0, long sA1,
                             const float* B, int ldb, long sB0, long sB1,
                             float* C, int ldc, long sC0, long sC1,
                             int batch, int Hd,
                             const float* bias, long sBias,
                             const float* res, float scale, int act)
{
    dim3 grd((N + TBN - 1) / TBN, (M + TBM - 1) / TBM, batch);
    gemm3_kernel<0><<<grd, 256>>>(M, N, K, A, lda, sA0, sA1, B, ldb, sB0, sB1,
                                  C, ldc, sC0, sC1, Hd, bias, sBias, res,
                                  nullptr, scale, act);
}

static inline void launch_nt(int M, int N, int K,
                             const float* A, int lda, long sA0, long sA1,
                             const float* B, int ldb, long sB0, long sB1,
                             float* C, int ldc, long sC0, long sC1,
                             int batch, int Hd, float* mir, float scale)
{
    dim3 grd((N + TBN - 1) / TBN, (M + TBM - 1) / TBM, batch);
    gemm3_kernel<1><<<grd, 256>>>(M, N, K, A, lda, sA0, sA1, B, ldb, sB0, sB1,
                                  C, ldc, sC0, sC1, Hd, nullptr, 0, nullptr,
                                  mir, scale, 0);
}

extern "C" void kernel_launch(void* const* d_in, const int* in_sizes, int n_in,
                              void* d_out, int out_size)
{
    (void)in_sizes; (void)n_in; (void)out_size;

    const int*   tokens  = (const int*)  d_in[0];
    const float* xa      = (const float*)d_in[1];
    const float* tok_emb = (const float*)d_in[2];
    const float* pos_emb = (const float*)d_in[3];
    const float* Wq      = (const float*)d_in[4];
    const float* bq      = (const float*)d_in[5];
    const float* Wk      = (const float*)d_in[6];
    const float* Wv      = (const float*)d_in[7];
    const float* bv      = (const float*)d_in[8];
    const float* Wo      = (const float*)d_in[9];
    const float* bo      = (const float*)d_in[10];
    const float* ln1_g   = (const float*)d_in[11];
    const float* ln1_b   = (const float*)d_in[12];
    const float* Wcq     = (const float*)d_in[13];
    const float* bcq     = (const float*)d_in[14];
    const float* Wck     = (const float*)d_in[15];
    const float* Wcv     = (const float*)d_in[16];
    const float* bcv     = (const float*)d_in[17];
    const float* Wco     = (const float*)d_in[18];
    const float* bco     = (const float*)d_in[19];
    const float* ln2_g   = (const float*)d_in[20];
    const float* ln2_b   = (const float*)d_in[21];
    const float* W1      = (const float*)d_in[22];
    const float* b1      = (const float*)d_in[23];
    const float* W2      = (const float*)d_in[24];
    const float* b2      = (const float*)d_in[25];
    const float* ln3_g   = (const float*)d_in[26];
    const float* ln3_b   = (const float*)d_in[27];
    const float* lnf_g   = (const float*)d_in[28];
    const float* lnf_b   = (const float*)d_in[29];

    float* out = (float*)d_out;
    float* out_logits = out;
    float* out_chw    = out_logits + (size_t)BB * TT * VV;
    float* out_kv     = out_chw + (size_t)(LL / 2) * HH * TT * TAA;

    float *x, *h, *q, *o, *sc, *ckall, *cvall, *hid;
    cudaGetSymbolAddress((void**)&x,     g_x);
    cudaGetSymbolAddress((void**)&h,     g_h);
    cudaGetSymbolAddress((void**)&q,     g_q);
    cudaGetSymbolAddress((void**)&o,     g_o);
    cudaGetSymbolAddress((void**)&sc,    g_sc);
    cudaGetSymbolAddress((void**)&ckall, g_ckall);
    cudaGetSymbolAddress((void**)&cvall, g_cvall);
    cudaGetSymbolAddress((void**)&hid,   g_hid);

    embed_kernel<<<BT, 256>>>(tokens, tok_emb, pos_emb, x);

    const long DTD = (long)TT * DD;
    const long TAD = (long)TAA * DD;

    // cross K/V for ALL layers, batched over z=12 (independent of decoder state)
    launch_nn(BB * TAA, DD, DD,
              xa, DD, 0, 0,
              Wck, DD, 0, (long)DD * DD,
              ckall, DD, 0, (long)BTAD,
              LL, LL, nullptr, 0, nullptr, 1.f, 0);
    launch_nn(BB * TAA, DD, DD,
              xa, DD, 0, 0,
              Wcv, DD, 0, (long)DD * DD,
              cvall, DD, 0, (long)BTAD,
              LL, LL, bcv, DD, nullptr, 1.f, 0);

    for (int l = 0; l < LL; l++) {
        const float* Wq_l = Wq + (size_t)l * DD * DD;
        const float* Wk_l = Wk + (size_t)l * DD * DD;
        const float* Wv_l = Wv + (size_t)l * DD * DD;
        const float* Wo_l = Wo + (size_t)l * DD * DD;
        const float* Wcq_l = Wcq + (size_t)l * DD * DD;
        const float* Wco_l = Wco + (size_t)l * DD * DD;
        const float* W1_l = W1 + (size_t)l * DD * 4 * DD;
        const float* W2_l = W2 + (size_t)l * 4 * DD * DD;

        float* kout = out_kv + (size_t)(2 * l) * BT * DD;
        float* vout = out_kv + (size_t)(2 * l + 1) * BT * DD;
        float* ck_l = ckall + (size_t)l * BTAD;
        float* cv_l = cvall + (size_t)l * BTAD;

        // ---- self attention ----
        ln_kernel<<<BT, 256>>>(x, h, ln1_g + l * DD, ln1_b + l * DD);
        launch_nn(BT, DD, DD, h, DD, 0, 0, Wq_l, DD, 0, 0, q, DD, 0, 0, 1, 1,
                  bq + l * DD, 0, nullptr, SCALE_Q, 0);
        launch_nn(BT, DD, DD, h, DD, 0, 0, Wk_l, DD, 0, 0, kout, DD, 0, 0, 1, 1,
                  nullptr, 0, nullptr, 1.f, 0);
        launch_nn(BT, DD, DD, h, DD, 0, 0, Wv_l, DD, 0, 0, vout, DD, 0, 0, 1, 1,
                  bv + l * DD, 0, nullptr, 1.f, 0);
        launch_nt(TT, TT, DHH,
                  q,    DD, DTD, DHH,
                  kout, DD, DTD, DHH,
                  sc,   TT, (long)HH * TT * TT, (long)TT * TT,
                  BB * HH, HH, nullptr, 1.f);
        softmax_causal_kernel<<<BB * HH * TT, 256>>>(sc);
        launch_nn(TT, DHH, TT,
                  sc,   TT, (long)HH * TT * TT, (long)TT * TT,
                  vout, DD, DTD, DHH,
                  o,    DD, DTD, DHH,
                  BB * HH, HH, nullptr, 0, nullptr, 1.f, 0);
        launch_nn(BT, DD, DD, o, DD, 0, 0, Wo_l, DD, 0, 0, x, DD, 0, 0, 1, 1,
                  bo + l * DD, 0, x, 1.f, 0);

        // ---- cross attention ----
        ln_kernel<<<BT, 256>>>(x, h, ln2_g + l * DD, ln2_b + l * DD);
        launch_nn(BT, DD, DD, h, DD, 0, 0, Wcq_l, DD, 0, 0, q, DD, 0, 0, 1, 1,
                  bcq + l * DD, 0, nullptr, SCALE_Q, 0);
        float* mir = (l >= LL / 2)
                   ? out_chw + (size_t)(l - LL / 2) * HH * TT * TAA : nullptr;
        launch_nt(TT, TAA, DHH,
                  q,    DD, DTD, DHH,
                  ck_l, DD, TAD, DHH,
                  sc,   TAA, (long)HH * TT * TAA, (long)TT * TAA,
                  BB * HH, HH, mir, 1.f);
        softmax_plain_kernel<<<BB * HH * TT, 256>>>(sc, TAA);
        launch_nn(TT, DHH, TAA,
                  sc,   TAA, (long)HH * TT * TAA, (long)TT * TAA,
                  cv_l, DD, TAD, DHH,
                  o,    DD, DTD, DHH,
                  BB * HH, HH, nullptr, 0, nullptr, 1.f, 0);
        launch_nn(BT, DD, DD, o, DD, 0, 0, Wco_l, DD, 0, 0, x, DD, 0, 0, 1, 1,
                  bco + l * DD, 0, x, 1.f, 0);

        // ---- MLP ----
        ln_kernel<<<BT, 256>>>(x, h, ln3_g + l * DD, ln3_b + l * DD);
        launch_nn(BT, 4 * DD, DD, h, DD, 0, 0, W1_l, 4 * DD, 0, 0, hid, 4 * DD, 0, 0,
                  1, 1, b1 + (size_t)l * 4 * DD, 0, nullptr, 1.f, 1);
        launch_nn(BT, DD, 4 * DD, hid, 4 * DD, 0, 0, W2_l, DD, 0, 0, x, DD, 0, 0,
                  1, 1, b2 + l * DD, 0, x, 1.f, 0);
    }

    // final LN + tied-embedding logits
    ln_kernel<<<BT, 256>>>(x, h, lnf_g, lnf_b);
    launch_nt(BT, VV, DD,
              h, DD, 0, 0,
              tok_emb, DD, 0, 0,
              out_logits, VV, 0, 0,
              1, 1, nullptr, 1.f);
}

// round 4
// speedup vs baseline: 2.3186x; 2.3186x over previous
#include <cuda_runtime.h>
#include <cuda_bf16.h>
#include <math.h>
#include <stdint.h>

// ---------------- problem constants ----------------
#define BB   4
#define TT   256
#define TAA  1500
#define DD   768
#define HH   12
#define LL   12
#define VV   51865
#define DHH  64
#define BT   (BB*TT)          // 1024
#define SCALE_Q 0.125f
#define BTAD ((size_t)BB*TAA*DD)

// ---------------- scratch ----------------
__device__ float g_x  [BT*DD];
__device__ float g_h  [BT*DD];
__device__ float g_q  [BT*DD];
__device__ float g_o  [BT*DD];
__device__ float g_sc [(size_t)BB*HH*TT*TAA];
__device__ float g_ckall[(size_t)LL*BTAD];
__device__ float g_cvall[(size_t)LL*BTAD];
__device__ float g_hid[(size_t)BT*4*DD];

// ---------------- bf16 split GEMM (3-term: AhBh + AhBl + AlBh) ----------------
// Block 128x64x32, 256 threads = 8 warps (4m x 2n), warp tile 32x32.
// Segmented-N (QKV fusion): seg = bn/segW selects B/C/bias/scale set.
#define TBM 128
#define TBN 64
#define TBK 32
#define ALD 20   // u32 pad: frag lane addr 20g+tig distinct mod 32
#define BTLD 20  // NT B stored [n][kp]
#define BNLD 72  // NN B stored [kp][n]: frag lane addr 8tig+g distinct mod 32

struct GemmP {
    const float *A, *B0, *B1, *B2;
    float *C0, *C1, *C2;
    const float *bias0, *bias1, *bias2, *res;
    float *mir;
    int M, N, K, lda, ldb, ldc, Hd, segW, act;
    long sA0, sA1, sB0, sB1, sC0, sC1, sBias;
    float s0, s1, s2;
};

__device__ __forceinline__ uint32_t pack_bf(float a, float b) {
    __nv_bfloat162 t;
    t.x = __float2bfloat16_rn(a);
    t.y = __float2bfloat16_rn(b);
    return *(uint32_t*)&t;
}

__device__ __forceinline__ void split_pair(float2 v, uint32_t& hi, uint32_t& lo) {
    __nv_bfloat16 hx = __float2bfloat16_rn(v.x);
    __nv_bfloat16 hy = __float2bfloat16_rn(v.y);
    hi = pack_bf(v.x, v.y);
    lo = pack_bf(v.x - __bfloat162float(hx), v.y - __bfloat162float(hy));
}

__device__ __forceinline__ void mma_bf16(float* c, const uint32_t* a, const uint32_t* b) {
    asm volatile(
        "mma.sync.aligned.m16n8k16.row.col.f32.bf16.bf16.f32 "
        "{%0,%1,%2,%3}, {%4,%5,%6,%7}, {%8,%9}, {%0,%1,%2,%3};"
        : "+f"(c[0]), "+f"(c[1]), "+f"(c[2]), "+f"(c[3])
        : "r"(a[0]), "r"(a[1]), "r"(a[2]), "r"(a[3]), "r"(b[0]), "r"(b[1]));
}

template <int NT>
__global__ __launch_bounds__(256, 2) void gemm_bf3_kernel(GemmP p)
{
    __shared__ uint32_t AH[TBM][ALD];
    __shared__ uint32_t AL[TBM][ALD];
    __shared__ uint32_t BH[1280];
    __shared__ uint32_t BL[1280];

    int z = blockIdx.z;
    int zb = z / p.Hd, zh = z % p.Hd;
    int bm = blockIdx.y * TBM, bn = blockIdx.x * TBN;
    int seg = bn / p.segW;
    int bnl = bn - seg * p.segW;

    const float* A = p.A + zb * p.sA0 + zh * p.sA1;
    const float* B = (seg == 0 ? p.B0 : seg == 1 ? p.B1 : p.B2) + zb * p.sB0 + zh * p.sB1;
    float* C = (seg == 0 ? p.C0 : seg == 1 ? p.C1 : p.C2) + zb * p.sC0 + zh * p.sC1;
    const float* bias = (seg == 0 ? p.bias0 : seg == 1 ? p.bias1 : p.bias2);
    if (bias) bias += zh * p.sBias;
    float scl = seg == 0 ? p.s0 : seg == 1 ? p.s1 : p.s2;
    const float* R = (p.res && seg == 0) ? p.res + zb * p.sC0 + zh * p.sC1 : nullptr;
    float* Mr = (p.mir && zb == 0 && seg == 0) ? p.mir + zh * p.sC1 : nullptr;

    int M = p.M, N = p.N, K = p.K;
    int lda = p.lda, ldb = p.ldb, ldc = p.ldc;

    int tid  = threadIdx.x;
    int lane = tid & 31;
    int warp = tid >> 5;
    int g    = lane >> 2;
    int tig  = lane & 3;
    int m0w  = (warp & 3) * 32;
    int n0w  = (warp >> 2) * 32;

    float c[2][4][4];
#pragma unroll
    for (int mi = 0; mi < 2; mi++)
#pragma unroll
        for (int ni = 0; ni < 4; ni++)
#pragma unroll
            for (int e = 0; e < 4; e++) c[mi][ni][e] = 0.f;

    int iters = (K + TBK - 1) / TBK;
    float2 ra[8], rb[4];

    // --- prefetch tile 0 ---
    {
        int kk = 0;
#pragma unroll
        for (int i = 0; i < 8; i++) {
            int pidx = i * 256 + tid;
            int r = pidx >> 4, kp = pidx & 15;
            int gr = bm + r, k0 = kk + 2 * kp;
            float2 v = {0.f, 0.f};
            if (gr < M) {
                if (k0 + 1 < K)      v = *(const float2*)&A[(long)gr * lda + k0];
                else if (k0 < K)     v.x = A[(long)gr * lda + k0];
            }
            ra[i] = v;
        }
#pragma unroll
        for (int i = 0; i < 4; i++) {
            int pidx = i * 256 + tid;
            float2 v = {0.f, 0.f};
            if (NT) {
                int n = pidx >> 4, kp = pidx & 15;
                int k0 = kk + 2 * kp;
                if (bn + n < N) {
                    long base = (long)(bnl + n) * ldb;
                    if (k0 + 1 < K)  v = *(const float2*)&B[base + k0];
                    else if (k0 < K) v.x = B[base + k0];
                }
            } else {
                int n = pidx & 63, kp = pidx >> 6;
                int k0 = kk + 2 * kp;
                if (bn + n < N) {
                    if (k0 < K)     v.x = B[(long)k0 * ldb + bnl + n];
                    if (k0 + 1 < K) v.y = B[(long)(k0 + 1) * ldb + bnl + n];
                }
            }
            rb[i] = v;
        }
    }

    for (int it = 0; it < iters; it++) {
        // store staged tile (hi/lo split, packed bf16x2)
#pragma unroll
        for (int i = 0; i < 8; i++) {
            int pidx = i * 256 + tid;
            int r = pidx >> 4, kp = pidx & 15;
            uint32_t hi, lo;
            split_pair(ra[i], hi, lo);
            AH[r][kp] = hi;
            AL[r][kp] = lo;
        }
#pragma unroll
        for (int i = 0; i < 4; i++) {
            int pidx = i * 256 + tid;
            uint32_t hi, lo;
            split_pair(rb[i], hi, lo);
            if (NT) {
                int n = pidx >> 4, kp = pidx & 15;
                BH[n * BTLD + kp] = hi;
                BL[n * BTLD + kp] = lo;
            } else {
                int n = pidx & 63, kp = pidx >> 6;
                BH[kp * BNLD + n] = hi;
                BL[kp * BNLD + n] = lo;
            }
        }
        __syncthreads();

        // prefetch next tile
        if (it + 1 < iters) {
            int kk = (it + 1) * TBK;
#pragma unroll
            for (int i = 0; i < 8; i++) {
                int pidx = i * 256 + tid;
                int r = pidx >> 4, kp = pidx & 15;
                int gr = bm + r, k0 = kk + 2 * kp;
                float2 v = {0.f, 0.f};
                if (gr < M) {
                    if (k0 + 1 < K)  v = *(const float2*)&A[(long)gr * lda + k0];
                    else if (k0 < K) v.x = A[(long)gr * lda + k0];
                }
                ra[i] = v;
            }
#pragma unroll
            for (int i = 0; i < 4; i++) {
                int pidx = i * 256 + tid;
                float2 v = {0.f, 0.f};
                if (NT) {
                    int n = pidx >> 4, kp = pidx & 15;
                    int k0 = kk + 2 * kp;
                    if (bn + n < N) {
                        long base = (long)(bnl + n) * ldb;
                        if (k0 + 1 < K)  v = *(const float2*)&B[base + k0];
                        else if (k0 < K) v.x = B[base + k0];
                    }
                } else {
                    int n = pidx & 63, kp = pidx >> 6;
                    int k0 = kk + 2 * kp;
                    if (bn + n < N) {
                        if (k0 < K)     v.x = B[(long)k0 * ldb + bnl + n];
                        if (k0 + 1 < K) v.y = B[(long)(k0 + 1) * ldb + bnl + n];
                    }
                }
                rb[i] = v;
            }
        }

        // compute 2 x k16 halves
#pragma unroll
        for (int h = 0; h < 2; h++) {
            int kb = h * 8;
            uint32_t aH4[2][4], aL4[2][4];
#pragma unroll
            for (int mi = 0; mi < 2; mi++) {
                int m = m0w + mi * 16 + g;
                aH4[mi][0] = AH[m    ][kb + tig];
                aH4[mi][1] = AH[m + 8][kb + tig];
                aH4[mi][2] = AH[m    ][kb + tig + 4];
                aH4[mi][3] = AH[m + 8][kb + tig + 4];
                aL4[mi][0] = AL[m    ][kb + tig];
                aL4[mi][1] = AL[m + 8][kb + tig];
                aL4[mi][2] = AL[m    ][kb + tig + 4];
                aL4[mi][3] = AL[m + 8][kb + tig + 4];
            }
            uint32_t bh2[4][2], bl2[4][2];
#pragma unroll
            for (int ni = 0; ni < 4; ni++) {
                int n = n0w + ni * 8 + g;
                if (NT) {
                    bh2[ni][0] = BH[n * BTLD + kb + tig];
                    bh2[ni][1] = BH[n * BTLD + kb + tig + 4];
                    bl2[ni][0] = BL[n * BTLD + kb + tig];
                    bl2[ni][1] = BL[n * BTLD + kb + tig + 4];
                } else {
                    bh2[ni][0] = BH[(kb + tig) * BNLD + n];
                    bh2[ni][1] = BH[(kb + tig + 4) * BNLD + n];
                    bl2[ni][0] = BL[(kb + tig) * BNLD + n];
                    bl2[ni][1] = BL[(kb + tig + 4) * BNLD + n];
                }
            }
#pragma unroll
            for (int mi = 0; mi < 2; mi++)
#pragma unroll
                for (int ni = 0; ni < 4; ni++) {
                    mma_bf16(c[mi][ni], aH4[mi], bl2[ni]);
                    mma_bf16(c[mi][ni], aL4[mi], bh2[ni]);
                    mma_bf16(c[mi][ni], aH4[mi], bh2[ni]);
                }
        }
        __syncthreads();
    }

    // epilogue
#pragma unroll
    for (int mi = 0; mi < 2; mi++) {
#pragma unroll
        for (int ni = 0; ni < 4; ni++) {
#pragma unroll
            for (int e = 0; e < 4; e++) {
                int row = bm + m0w + mi * 16 + g + ((e >= 2) ? 8 : 0);
                int gcol = bn + n0w + ni * 8 + tig * 2 + (e & 1);
                if (row >= M || gcol >= N) continue;
                int lc = gcol - seg * p.segW;
                float v = c[mi][ni][e];
                if (bias) v += bias[lc];
                v *= scl;
                if (p.act == 1) v = 0.5f * v * (1.f + erff(v * 0.70710678118654752f));
                long ci = (long)row * ldc + lc;
                if (R) v += R[ci];
                C[ci] = v;
                if (Mr) Mr[ci] = v;
            }
        }
    }
}

// ---------------- elementwise / row kernels ----------------
__global__ __launch_bounds__(256) void embed_kernel(
    const int* __restrict__ tokens, const float* __restrict__ tok_emb,
    const float* __restrict__ pos_emb, float* __restrict__ x)
{
    int row = blockIdx.x;
    int t = row % TT;
    int tok = tokens[row];
    const float* te = tok_emb + (long)tok * DD;
    const float* pe = pos_emb + (long)t * DD;
    float* xr = x + (long)row * DD;
#pragma unroll
    for (int it = 0; it < 3; it++) {
        int j = threadIdx.x + it * 256;
        xr[j] = te[j] + pe[j];
    }
}

__global__ __launch_bounds__(256) void ln_kernel(
    const float* __restrict__ x, float* __restrict__ y,
    const float* __restrict__ g, const float* __restrict__ b)
{
    __shared__ float red[256];
    int row = blockIdx.x;
    const float* xr = x + (long)row * DD;
    float* yr = y + (long)row * DD;
    int tid = threadIdx.x;
    float v0 = xr[tid], v1 = xr[tid + 256], v2 = xr[tid + 512];
    float s = v0 + v1 + v2;
    red[tid] = s; __syncthreads();
    for (int st = 128; st > 0; st >>= 1) { if (tid < st) red[tid] += red[tid + st]; __syncthreads(); }
    float mean = red[0] * (1.f / DD);
    __syncthreads();
    float d0 = v0 - mean, d1 = v1 - mean, d2 = v2 - mean;
    red[tid] = d0 * d0 + d1 * d1 + d2 * d2; __syncthreads();
    for (int st = 128; st > 0; st >>= 1) { if (tid < st) red[tid] += red[tid + st]; __syncthreads(); }
    float inv = rsqrtf(red[0] * (1.f / DD) + 1e-5f);
    yr[tid]       = d0 * inv * g[tid]       + b[tid];
    yr[tid + 256] = d1 * inv * g[tid + 256] + b[tid + 256];
    yr[tid + 512] = d2 * inv * g[tid + 512] + b[tid + 512];
}

__global__ __launch_bounds__(256) void softmax_causal_kernel(float* __restrict__ S)
{
    __shared__ float red[256];
    int row = blockIdx.x;
    int i = row & (TT - 1);
    float* p = S + (long)row * TT;
    int tid = threadIdx.x;
    float v = (tid <= i) ? p[tid] : -1e30f;
    red[tid] = v; __syncthreads();
    for (int st = 128; st > 0; st >>= 1) { if (tid < st) red[tid] = fmaxf(red[tid], red[tid + st]); __syncthreads(); }
    float m = red[0]; __syncthreads();
    float e = (tid <= i) ? expf(v - m) : 0.f;
    red[tid] = e; __syncthreads();
    for (int st = 128; st > 0; st >>= 1) { if (tid < st) red[tid] += red[tid + st]; __syncthreads(); }
    p[tid] = e / red[0];
}

__global__ __launch_bounds__(256) void softmax_plain_kernel(float* __restrict__ S, int len)
{
    __shared__ float red[256];
    int row = blockIdx.x;
    float* p = S + (long)row * len;
    int tid = threadIdx.x;
    float vals[6];
    float m = -1e30f;
#pragma unroll
    for (int it = 0; it < 6; it++) {
        int j = tid + it * 256;
        float v = (j < len) ? p[j] : -1e30f;
        vals[it] = v;
        m = fmaxf(m, v);
    }
    red[tid] = m; __syncthreads();
    for (int st = 128; st > 0; st >>= 1) { if (tid < st) red[tid] = fmaxf(red[tid], red[tid + st]); __syncthreads(); }
    m = red[0]; __syncthreads();
    float s = 0.f;
#pragma unroll
    for (int it = 0; it < 6; it++) {
        int j = tid + it * 256;
        float e = (j < len) ? expf(vals[it] - m) : 0.f;
        vals[it] = e;
        s += e;
    }
    red[tid] = s; __syncthreads();
    for (int st = 128; st > 0; st >>= 1) { if (tid < st) red[tid] += red[tid + st]; __syncthreads(); }
    float inv = 1.f / red[0];
#pragma unroll
    for (int it = 0; it < 6; it++) {
        int j = tid + it * 256;
        if (j < len) p[j] = vals[it] * inv;
    }
}

// ---------------- host-side launch helpers ----------------
static GemmP base_p() {
    GemmP p;
    p.A = nullptr; p.B0 = p.B1 = p.B2 = nullptr;
    p.C0 = p.C1 = p.C2 = nullptr;
    p.bias0 = p.bias1 = p.bias2 = nullptr; p.res = nullptr; p.mir = nullptr;
    p.M = p.N = p.K = 0; p.lda = p.ldb = p.ldc = 0;
    p.Hd = 1; p.segW = 1 << 30; p.act = 0;
    p.sA0 = p.sA1 = p.sB0 = p.sB1 = p.sC0 = p.sC1 = p.sBias = 0;
    p.s0 = p.s1 = p.s2 = 1.f;
    return p;
}

template <int NT>
static inline void launch_g(const GemmP& p, int batch) {
    dim3 grd((p.N + TBN - 1) / TBN, (p.M + TBM - 1) / TBM, batch);
    gemm_bf3_kernel<NT><<<grd, 256>>>(p);
}

extern "C" void kernel_launch(void* const* d_in, const int* in_sizes, int n_in,
                              void* d_out, int out_size)
{
    (void)in_sizes; (void)n_in; (void)out_size;

    const int*   tokens  = (const int*)  d_in[0];
    const float* xa      = (const float*)d_in[1];
    const float* tok_emb = (const float*)d_in[2];
    const float* pos_emb = (const float*)d_in[3];
    const float* Wq      = (const float*)d_in[4];
    const float* bq      = (const float*)d_in[5];
    const float* Wk      = (const float*)d_in[6];
    const float* Wv      = (const float*)d_in[7];
    const float* bv      = (const float*)d_in[8];
    const float* Wo      = (const float*)d_in[9];
    const float* bo      = (const float*)d_in[10];
    const float* ln1_g   = (const float*)d_in[11];
    const float* ln1_b   = (const float*)d_in[12];
    const float* Wcq     = (const float*)d_in[13];
    const float* bcq     = (const float*)d_in[14];
    const float* Wck     = (const float*)d_in[15];
    const float* Wcv     = (const float*)d_in[16];
    const float* bcv     = (const float*)d_in[17];
    const float* Wco     = (const float*)d_in[18];
    const float* bco     = (const float*)d_in[19];
    const float* ln2_g   = (const float*)d_in[20];
    const float* ln2_b   = (const float*)d_in[21];
    const float* W1      = (const float*)d_in[22];
    const float* b1      = (const float*)d_in[23];
    const float* W2      = (const float*)d_in[24];
    const float* b2      = (const float*)d_in[25];
    const float* ln3_g   = (const float*)d_in[26];
    const float* ln3_b   = (const float*)d_in[27];
    const float* lnf_g   = (const float*)d_in[28];
    const float* lnf_b   = (const float*)d_in[29];

    float* out = (float*)d_out;
    float* out_logits = out;
    float* out_chw    = out_logits + (size_t)BB * TT * VV;
    float* out_kv     = out_chw + (size_t)(LL / 2) * HH * TT * TAA;

    float *x, *h, *q, *o, *sc, *ckall, *cvall, *hid;
    cudaGetSymbolAddress((void**)&x,     g_x);
    cudaGetSymbolAddress((void**)&h,     g_h);
    cudaGetSymbolAddress((void**)&q,     g_q);
    cudaGetSymbolAddress((void**)&o,     g_o);
    cudaGetSymbolAddress((void**)&sc,    g_sc);
    cudaGetSymbolAddress((void**)&ckall, g_ckall);
    cudaGetSymbolAddress((void**)&cvall, g_cvall);
    cudaGetSymbolAddress((void**)&hid,   g_hid);

    embed_kernel<<<BT, 256>>>(tokens, tok_emb, pos_emb, x);

    const long DTD = (long)TT * DD;
    const long TAD = (long)TAA * DD;

    // cross K/V for ALL layers, batched over z=12
    {
        GemmP p = base_p();
        p.A = xa; p.lda = DD;
        p.B0 = Wck; p.ldb = DD; p.sB1 = (long)DD * DD;
        p.C0 = ckall; p.ldc = DD; p.sC1 = (long)BTAD;
        p.M = BB * TAA; p.N = DD; p.K = DD; p.Hd = LL;
        launch_g<0>(p, LL);
        p.B0 = Wcv; p.C0 = cvall;
        p.bias0 = bcv; p.sBias = DD;
        launch_g<0>(p, LL);
    }

    for (int l = 0; l < LL; l++) {
        const float* Wq_l = Wq + (size_t)l * DD * DD;
        const float* Wk_l = Wk + (size_t)l * DD * DD;
        const float* Wv_l = Wv + (size_t)l * DD * DD;
        const float* Wo_l = Wo + (size_t)l * DD * DD;
        const float* Wcq_l = Wcq + (size_t)l * DD * DD;
        const float* Wco_l = Wco + (size_t)l * DD * DD;
        const float* W1_l = W1 + (size_t)l * DD * 4 * DD;
        const float* W2_l = W2 + (size_t)l * 4 * DD * DD;

        float* kout = out_kv + (size_t)(2 * l) * BT * DD;
        float* vout = out_kv + (size_t)(2 * l + 1) * BT * DD;
        float* ck_l = ckall + (size_t)l * BTAD;
        float* cv_l = cvall + (size_t)l * BTAD;

        // ---- self attention ----
        ln_kernel<<<BT, 256>>>(x, h, ln1_g + l * DD, ln1_b + l * DD);
        {   // fused QKV
            GemmP p = base_p();
            p.A = h; p.lda = DD;
            p.B0 = Wq_l; p.B1 = Wk_l; p.B2 = Wv_l; p.ldb = DD;
            p.C0 = q; p.C1 = kout; p.C2 = vout; p.ldc = DD;
            p.bias0 = bq + l * DD; p.bias1 = nullptr; p.bias2 = bv + l * DD;
            p.s0 = SCALE_Q; p.s1 = 1.f; p.s2 = 1.f;
            p.segW = DD;
            p.M = BT; p.N = 3 * DD; p.K = DD;
            launch_g<0>(p, 1);
        }
        {   // scores = q @ k^T
            GemmP p = base_p();
            p.A = q; p.lda = DD; p.sA0 = DTD; p.sA1 = DHH;
            p.B0 = kout; p.ldb = DD; p.sB0 = DTD; p.sB1 = DHH;
            p.C0 = sc; p.ldc = TT; p.sC0 = (long)HH * TT * TT; p.sC1 = (long)TT * TT;
            p.M = TT; p.N = TT; p.K = DHH; p.Hd = HH;
            launch_g<1>(p, BB * HH);
        }
        softmax_causal_kernel<<<BB * HH * TT, 256>>>(sc);
        {   // o = P @ v
            GemmP p = base_p();
            p.A = sc; p.lda = TT; p.sA0 = (long)HH * TT * TT; p.sA1 = (long)TT * TT;
            p.B0 = vout; p.ldb = DD; p.sB0 = DTD; p.sB1 = DHH;
            p.C0 = o; p.ldc = DD; p.sC0 = DTD; p.sC1 = DHH;
            p.M = TT; p.N = DHH; p.K = TT; p.Hd = HH;
            launch_g<0>(p, BB * HH);
        }
        {   // x += o @ Wo + bo
            GemmP p = base_p();
            p.A = o; p.lda = DD;
            p.B0 = Wo_l; p.ldb = DD;
            p.C0 = x; p.ldc = DD;
            p.bias0 = bo + l * DD; p.res = x;
            p.M = BT; p.N = DD; p.K = DD;
            launch_g<0>(p, 1);
        }

        // ---- cross attention ----
        ln_kernel<<<BT, 256>>>(x, h, ln2_g + l * DD, ln2_b + l * DD);
        {   // q2
            GemmP p = base_p();
            p.A = h; p.lda = DD;
            p.B0 = Wcq_l; p.ldb = DD;
            p.C0 = q; p.ldc = DD;
            p.bias0 = bcq + l * DD; p.s0 = SCALE_Q;
            p.M = BT; p.N = DD; p.K = DD;
            launch_g<0>(p, 1);
        }
        {   // qk2 = q2 @ ck^T (+mirror to chw for l >= L/2)
            GemmP p = base_p();
            p.A = q; p.lda = DD; p.sA0 = DTD; p.sA1 = DHH;
            p.B0 = ck_l; p.ldb = DD; p.sB0 = TAD; p.sB1 = DHH;
            p.C0 = sc; p.ldc = TAA; p.sC0 = (long)HH * TT * TAA; p.sC1 = (long)TT * TAA;
            p.mir = (l >= LL / 2)
                  ? out_chw + (size_t)(l - LL / 2) * HH * TT * TAA : nullptr;
            p.M = TT; p.N = TAA; p.K = DHH; p.Hd = HH;
            launch_g<1>(p, BB * HH);
        }
        softmax_plain_kernel<<<BB * HH * TT, 256>>>(sc, TAA);
        {   // o2 = P2 @ cv
            GemmP p = base_p();
            p.A = sc; p.lda = TAA; p.sA0 = (long)HH * TT * TAA; p.sA1 = (long)TT * TAA;
            p.B0 = cv_l; p.ldb = DD; p.sB0 = TAD; p.sB1 = DHH;
            p.C0 = o; p.ldc = DD; p.sC0 = DTD; p.sC1 = DHH;
            p.M = TT; p.N = DHH; p.K = TAA; p.Hd = HH;
            launch_g<0>(p, BB * HH);
        }
        {   // x += o2 @ Wco + bco
            GemmP p = base_p();
            p.A = o; p.lda = DD;
            p.B0 = Wco_l; p.ldb = DD;
            p.C0 = x; p.ldc = DD;
            p.bias0 = bco + l * DD; p.res = x;
            p.M = BT; p.N = DD; p.K = DD;
            launch_g<0>(p, 1);
        }

        // ---- MLP ----
        ln_kernel<<<BT, 256>>>(x, h, ln3_g + l * DD, ln3_b + l * DD);
        {
            GemmP p = base_p();
            p.A = h; p.lda = DD;
            p.B0 = W1_l; p.ldb = 4 * DD;
            p.C0 = hid; p.ldc = 4 * DD;
            p.bias0 = b1 + (size_t)l * 4 * DD; p.act = 1;
            p.M = BT; p.N = 4 * DD; p.K = DD;
            launch_g<0>(p, 1);
        }
        {
            GemmP p = base_p();
            p.A = hid; p.lda = 4 * DD;
            p.B0 = W2_l; p.ldb = DD;
            p.C0 = x; p.ldc = DD;
            p.bias0 = b2 + l * DD; p.res = x;
            p.M = BT; p.N = DD; p.K = 4 * DD;
            launch_g<0>(p, 1);
        }
    }

    // final LN + tied-embedding logits
    ln_kernel<<<BT, 256>>>(x, h, lnf_g, lnf_b);
    {
        GemmP p = base_p();
        p.A = h; p.lda = DD;
        p.B0 = tok_emb; p.ldb = DD;
        p.C0 = out_logits; p.ldc = VV;
        p.M = BT; p.N = VV; p.K = DD;
        launch_g<1>(p, 1);
    }
}

// round 5
// speedup vs baseline: 2.7087x; 1.1682x over previous
#include <cuda_runtime.h>
#include <cuda_bf16.h>
#include <math.h>
#include <stdint.h>

// ---------------- problem constants ----------------
#define BB   4
#define TT   256
#define TAA  1500
#define DD   768
#define HH   12
#define LL   12
#define VV   51865
#define DHH  64
#define BT   (BB*TT)          // 1024
#define SCALE_Q 0.125f
#define BTAD ((size_t)BB*TAA*DD)

// ---------------- scratch ----------------
__device__ float g_x  [BT*DD];
__device__ float g_h  [BT*DD];
__device__ float g_q  [BT*DD];
__device__ float g_o  [BT*DD];
__device__ float g_sc [(size_t)BB*HH*TT*TAA];
__device__ float g_ckall[(size_t)LL*BTAD];
__device__ float g_cvall[(size_t)LL*BTAD];
__device__ float g_hid[(size_t)BT*4*DD];

// ---------------- bf16 split GEMM (3-term) + split-K ----------------
#define TBM 128
#define TBN 64
#define TBK 32
#define ALD 20
#define BTLD 20
#define BNLD 72

struct GemmP {
    const float *A, *B0, *B1, *B2;
    float *C0, *C1, *C2;
    const float *bias0, *bias1, *bias2, *res;
    float *mir;
    int M, N, K, lda, ldb, ldc, Hd, segW, act, splitK, kc;
    long sA0, sA1, sB0, sB1, sC0, sC1, sBias;
    float s0, s1, s2;
};

__device__ __forceinline__ uint32_t pack_bf(float a, float b) {
    __nv_bfloat162 t;
    t.x = __float2bfloat16_rn(a);
    t.y = __float2bfloat16_rn(b);
    return *(uint32_t*)&t;
}

__device__ __forceinline__ void split_pair(float2 v, uint32_t& hi, uint32_t& lo) {
    __nv_bfloat16 hx = __float2bfloat16_rn(v.x);
    __nv_bfloat16 hy = __float2bfloat16_rn(v.y);
    hi = pack_bf(v.x, v.y);
    lo = pack_bf(v.x - __bfloat162float(hx), v.y - __bfloat162float(hy));
}

__device__ __forceinline__ void mma_bf16(float* c, const uint32_t* a, const uint32_t* b) {
    asm volatile(
        "mma.sync.aligned.m16n8k16.row.col.f32.bf16.bf16.f32 "
        "{%0,%1,%2,%3}, {%4,%5,%6,%7}, {%8,%9}, {%0,%1,%2,%3};"
        : "+f"(c[0]), "+f"(c[1]), "+f"(c[2]), "+f"(c[3])
        : "r"(a[0]), "r"(a[1]), "r"(a[2]), "r"(a[3]), "r"(b[0]), "r"(b[1]));
}

template <int NT>
__global__ __launch_bounds__(256, 2) void gemm_bf3_kernel(GemmP p)
{
    __shared__ uint32_t AH[TBM][ALD];
    __shared__ uint32_t AL[TBM][ALD];
    __shared__ uint32_t BH[1280];
    __shared__ uint32_t BL[1280];

    int z = blockIdx.z;
    int sk = z % p.splitK;
    int zz = z / p.splitK;
    int zb = zz / p.Hd, zh = zz % p.Hd;
    int bm = blockIdx.y * TBM, bn = blockIdx.x * TBN;
    int seg = bn / p.segW;
    int bnl = bn - seg * p.segW;

    const float* A = p.A + zb * p.sA0 + zh * p.sA1;
    const float* B = (seg == 0 ? p.B0 : seg == 1 ? p.B1 : p.B2) + zb * p.sB0 + zh * p.sB1;
    float* C = (seg == 0 ? p.C0 : seg == 1 ? p.C1 : p.C2) + zb * p.sC0 + zh * p.sC1;
    const float* bias = (seg == 0 ? p.bias0 : seg == 1 ? p.bias1 : p.bias2);
    if (bias) bias += zh * p.sBias;
    float scl = seg == 0 ? p.s0 : seg == 1 ? p.s1 : p.s2;
    const float* R = (p.res && seg == 0) ? p.res + zb * p.sC0 + zh * p.sC1 : nullptr;
    float* Mr = (p.mir && zb == 0 && seg == 0) ? p.mir + zh * p.sC1 : nullptr;
    bool atom = p.splitK > 1;

    int M = p.M, N = p.N;
    int lda = p.lda, ldb = p.ldb, ldc = p.ldc;
    int kstart = sk * p.kc;
    int kend = min(p.K, kstart + p.kc);

    int tid  = threadIdx.x;
    int lane = tid & 31;
    int warp = tid >> 5;
    int g    = lane >> 2;
    int tig  = lane & 3;
    int m0w  = (warp & 3) * 32;
    int n0w  = (warp >> 2) * 32;

    float c[2][4][4];
#pragma unroll
    for (int mi = 0; mi < 2; mi++)
#pragma unroll
        for (int ni = 0; ni < 4; ni++)
#pragma unroll
            for (int e = 0; e < 4; e++) c[mi][ni][e] = 0.f;

    int iters = (kend - kstart + TBK - 1) / TBK;
    float2 ra[8], rb[4];

    // --- prefetch tile 0 ---
    {
        int kk = kstart;
#pragma unroll
        for (int i = 0; i < 8; i++) {
            int pidx = i * 256 + tid;
            int r = pidx >> 4, kp = pidx & 15;
            int gr = bm + r, k0 = kk + 2 * kp;
            float2 v = {0.f, 0.f};
            if (gr < M) {
                if (k0 + 1 < kend)      v = *(const float2*)&A[(long)gr * lda + k0];
                else if (k0 < kend)     v.x = A[(long)gr * lda + k0];
            }
            ra[i] = v;
        }
#pragma unroll
        for (int i = 0; i < 4; i++) {
            int pidx = i * 256 + tid;
            float2 v = {0.f, 0.f};
            if (NT) {
                int n = pidx >> 4, kp = pidx & 15;
                int k0 = kk + 2 * kp;
                if (bn + n < N) {
                    long base = (long)(bnl + n) * ldb;
                    if (k0 + 1 < kend)  v = *(const float2*)&B[base + k0];
                    else if (k0 < kend) v.x = B[base + k0];
                }
            } else {
                int n = pidx & 63, kp = pidx >> 6;
                int k0 = kk + 2 * kp;
                if (bn + n < N) {
                    if (k0 < kend)     v.x = B[(long)k0 * ldb + bnl + n];
                    if (k0 + 1 < kend) v.y = B[(long)(k0 + 1) * ldb + bnl + n];
                }
            }
            rb[i] = v;
        }
    }

    for (int it = 0; it < iters; it++) {
#pragma unroll
        for (int i = 0; i < 8; i++) {
            int pidx = i * 256 + tid;
            int r = pidx >> 4, kp = pidx & 15;
            uint32_t hi, lo;
            split_pair(ra[i], hi, lo);
            AH[r][kp] = hi;
            AL[r][kp] = lo;
        }
#pragma unroll
        for (int i = 0; i < 4; i++) {
            int pidx = i * 256 + tid;
            uint32_t hi, lo;
            split_pair(rb[i], hi, lo);
            if (NT) {
                int n = pidx >> 4, kp = pidx & 15;
                BH[n * BTLD + kp] = hi;
                BL[n * BTLD + kp] = lo;
            } else {
                int n = pidx & 63, kp = pidx >> 6;
                BH[kp * BNLD + n] = hi;
                BL[kp * BNLD + n] = lo;
            }
        }
        __syncthreads();

        if (it + 1 < iters) {
            int kk = kstart + (it + 1) * TBK;
#pragma unroll
            for (int i = 0; i < 8; i++) {
                int pidx = i * 256 + tid;
                int r = pidx >> 4, kp = pidx & 15;
                int gr = bm + r, k0 = kk + 2 * kp;
                float2 v = {0.f, 0.f};
                if (gr < M) {
                    if (k0 + 1 < kend)  v = *(const float2*)&A[(long)gr * lda + k0];
                    else if (k0 < kend) v.x = A[(long)gr * lda + k0];
                }
                ra[i] = v;
            }
#pragma unroll
            for (int i = 0; i < 4; i++) {
                int pidx = i * 256 + tid;
                float2 v = {0.f, 0.f};
                if (NT) {
                    int n = pidx >> 4, kp = pidx & 15;
                    int k0 = kk + 2 * kp;
                    if (bn + n < N) {
                        long base = (long)(bnl + n) * ldb;
                        if (k0 + 1 < kend)  v = *(const float2*)&B[base + k0];
                        else if (k0 < kend) v.x = B[base + k0];
                    }
                } else {
                    int n = pidx & 63, kp = pidx >> 6;
                    int k0 = kk + 2 * kp;
                    if (bn + n < N) {
                        if (k0 < kend)     v.x = B[(long)k0 * ldb + bnl + n];
                        if (k0 + 1 < kend) v.y = B[(long)(k0 + 1) * ldb + bnl + n];
                    }
                }
                rb[i] = v;
            }
        }

#pragma unroll
        for (int h = 0; h < 2; h++) {
            int kb = h * 8;
            uint32_t aH4[2][4], aL4[2][4];
#pragma unroll
            for (int mi = 0; mi < 2; mi++) {
                int m = m0w + mi * 16 + g;
                aH4[mi][0] = AH[m    ][kb + tig];
                aH4[mi][1] = AH[m + 8][kb + tig];
                aH4[mi][2] = AH[m    ][kb + tig + 4];
                aH4[mi][3] = AH[m + 8][kb + tig + 4];
                aL4[mi][0] = AL[m    ][kb + tig];
                aL4[mi][1] = AL[m + 8][kb + tig];
                aL4[mi][2] = AL[m    ][kb + tig + 4];
                aL4[mi][3] = AL[m + 8][kb + tig + 4];
            }
            uint32_t bh2[4][2], bl2[4][2];
#pragma unroll
            for (int ni = 0; ni < 4; ni++) {
                int n = n0w + ni * 8 + g;
                if (NT) {
                    bh2[ni][0] = BH[n * BTLD + kb + tig];
                    bh2[ni][1] = BH[n * BTLD + kb + tig + 4];
                    bl2[ni][0] = BL[n * BTLD + kb + tig];
                    bl2[ni][1] = BL[n * BTLD + kb + tig + 4];
                } else {
                    bh2[ni][0] = BH[(kb + tig) * BNLD + n];
                    bh2[ni][1] = BH[(kb + tig + 4) * BNLD + n];
                    bl2[ni][0] = BL[(kb + tig) * BNLD + n];
                    bl2[ni][1] = BL[(kb + tig + 4) * BNLD + n];
                }
            }
#pragma unroll
            for (int mi = 0; mi < 2; mi++)
#pragma unroll
                for (int ni = 0; ni < 4; ni++) {
                    mma_bf16(c[mi][ni], aH4[mi], bl2[ni]);
                    mma_bf16(c[mi][ni], aL4[mi], bh2[ni]);
                    mma_bf16(c[mi][ni], aH4[mi], bh2[ni]);
                }
        }
        __syncthreads();
    }

    // epilogue
#pragma unroll
    for (int mi = 0; mi < 2; mi++) {
#pragma unroll
        for (int ni = 0; ni < 4; ni++) {
#pragma unroll
            for (int e = 0; e < 4; e++) {
                int row = bm + m0w + mi * 16 + g + ((e >= 2) ? 8 : 0);
                int gcol = bn + n0w + ni * 8 + tig * 2 + (e & 1);
                if (row >= M || gcol >= N) continue;
                int lc = gcol - seg * p.segW;
                float v = c[mi][ni][e];
                if (bias && (!atom || sk == 0)) v += bias[lc];
                v *= scl;
                long ci = (long)row * ldc + lc;
                if (atom) {
                    atomicAdd(&C[ci], v);
                } else {
                    if (p.act == 1) v = 0.5f * v * (1.f + erff(v * 0.70710678118654752f));
                    if (R) v += R[ci];
                    C[ci] = v;
                    if (Mr) Mr[ci] = v;
                }
            }
        }
    }
}

// ---------------- elementwise / row kernels ----------------
__global__ __launch_bounds__(256) void embed_kernel(
    const int* __restrict__ tokens, const float* __restrict__ tok_emb,
    const float* __restrict__ pos_emb, float* __restrict__ x)
{
    int row = blockIdx.x;
    int t = row % TT;
    int tok = tokens[row];
    const float* te = tok_emb + (long)tok * DD;
    const float* pe = pos_emb + (long)t * DD;
    float* xr = x + (long)row * DD;
#pragma unroll
    for (int it = 0; it < 3; it++) {
        int j = threadIdx.x + it * 256;
        xr[j] = te[j] + pe[j];
    }
}

__global__ __launch_bounds__(256) void ln_kernel(
    const float* __restrict__ x, float* __restrict__ y,
    const float* __restrict__ g, const float* __restrict__ b)
{
    __shared__ float red[256];
    int row = blockIdx.x;
    const float* xr = x + (long)row * DD;
    float* yr = y + (long)row * DD;
    int tid = threadIdx.x;
    float v0 = xr[tid], v1 = xr[tid + 256], v2 = xr[tid + 512];
    float s = v0 + v1 + v2;
    red[tid] = s; __syncthreads();
    for (int st = 128; st > 0; st >>= 1) { if (tid < st) red[tid] += red[tid + st]; __syncthreads(); }
    float mean = red[0] * (1.f / DD);
    __syncthreads();
    float d0 = v0 - mean, d1 = v1 - mean, d2 = v2 - mean;
    red[tid] = d0 * d0 + d1 * d1 + d2 * d2; __syncthreads();
    for (int st = 128; st > 0; st >>= 1) { if (tid < st) red[tid] += red[tid + st]; __syncthreads(); }
    float inv = rsqrtf(red[0] * (1.f / DD) + 1e-5f);
    yr[tid]       = d0 * inv * g[tid]       + b[tid];
    yr[tid + 256] = d1 * inv * g[tid + 256] + b[tid + 256];
    yr[tid + 512] = d2 * inv * g[tid + 512] + b[tid + 512];
}

__global__ __launch_bounds__(256) void softmax_causal_kernel(float* __restrict__ S)
{
    __shared__ float red[256];
    int row = blockIdx.x;
    int i = row & (TT - 1);
    float* p = S + (long)row * TT;
    int tid = threadIdx.x;
    float v = (tid <= i) ? p[tid] : -1e30f;
    red[tid] = v; __syncthreads();
    for (int st = 128; st > 0; st >>= 1) { if (tid < st) red[tid] = fmaxf(red[tid], red[tid + st]); __syncthreads(); }
    float m = red[0]; __syncthreads();
    float e = (tid <= i) ? expf(v - m) : 0.f;
    red[tid] = e; __syncthreads();
    for (int st = 128; st > 0; st >>= 1) { if (tid < st) red[tid] += red[tid + st]; __syncthreads(); }
    p[tid] = e / red[0];
}

__global__ __launch_bounds__(256) void softmax_plain_kernel(float* __restrict__ S, int len)
{
    __shared__ float red[256];
    int row = blockIdx.x;
    float* p = S + (long)row * len;
    int tid = threadIdx.x;
    float vals[6];
    float m = -1e30f;
#pragma unroll
    for (int it = 0; it < 6; it++) {
        int j = tid + it * 256;
        float v = (j < len) ? p[j] : -1e30f;
        vals[it] = v;
        m = fmaxf(m, v);
    }
    red[tid] = m; __syncthreads();
    for (int st = 128; st > 0; st >>= 1) { if (tid < st) red[tid] = fmaxf(red[tid], red[tid + st]); __syncthreads(); }
    m = red[0]; __syncthreads();
    float s = 0.f;
#pragma unroll
    for (int it = 0; it < 6; it++) {
        int j = tid + it * 256;
        float e = (j < len) ? expf(vals[it] - m) : 0.f;
        vals[it] = e;
        s += e;
    }
    red[tid] = s; __syncthreads();
    for (int st = 128; st > 0; st >>= 1) { if (tid < st) red[tid] += red[tid + st]; __syncthreads(); }
    float inv = 1.f / red[0];
#pragma unroll
    for (int it = 0; it < 6; it++) {
        int j = tid + it * 256;
        if (j < len) p[j] = vals[it] * inv;
    }
}

// ---------------- host-side launch helpers ----------------
static GemmP base_p() {
    GemmP p;
    p.A = nullptr; p.B0 = p.B1 = p.B2 = nullptr;
    p.C0 = p.C1 = p.C2 = nullptr;
    p.bias0 = p.bias1 = p.bias2 = nullptr; p.res = nullptr; p.mir = nullptr;
    p.M = p.N = p.K = 0; p.lda = p.ldb = p.ldc = 0;
    p.Hd = 1; p.segW = 1 << 30; p.act = 0; p.splitK = 1; p.kc = 0;
    p.sA0 = p.sA1 = p.sB0 = p.sB1 = p.sC0 = p.sC1 = p.sBias = 0;
    p.s0 = p.s1 = p.s2 = 1.f;
    return p;
}

template <int NT>
static inline void launch_g(GemmP p, int batch, int splitK = 1) {
    p.splitK = splitK;
    int kc = (p.K + splitK - 1) / splitK;
    p.kc = ((kc + TBK - 1) / TBK) * TBK;
    dim3 grd((p.N + TBN - 1) / TBN, (p.M + TBM - 1) / TBM, batch * splitK);
    gemm_bf3_kernel<NT><<<grd, 256>>>(p);
}

extern "C" void kernel_launch(void* const* d_in, const int* in_sizes, int n_in,
                              void* d_out, int out_size)
{
    (void)in_sizes; (void)n_in; (void)out_size;

    const int*   tokens  = (const int*)  d_in[0];
    const float* xa      = (const float*)d_in[1];
    const float* tok_emb = (const float*)d_in[2];
    const float* pos_emb = (const float*)d_in[3];
    const float* Wq      = (const float*)d_in[4];
    const float* bq      = (const float*)d_in[5];
    const float* Wk      = (const float*)d_in[6];
    const float* Wv      = (const float*)d_in[7];
    const float* bv      = (const float*)d_in[8];
    const float* Wo      = (const float*)d_in[9];
    const float* bo      = (const float*)d_in[10];
    const float* ln1_g   = (const float*)d_in[11];
    const float* ln1_b   = (const float*)d_in[12];
    const float* Wcq     = (const float*)d_in[13];
    const float* bcq     = (const float*)d_in[14];
    const float* Wck     = (const float*)d_in[15];
    const float* Wcv     = (const float*)d_in[16];
    const float* bcv     = (const float*)d_in[17];
    const float* Wco     = (const float*)d_in[18];
    const float* bco     = (const float*)d_in[19];
    const float* ln2_g   = (const float*)d_in[20];
    const float* ln2_b   = (const float*)d_in[21];
    const float* W1      = (const float*)d_in[22];
    const float* b1      = (const float*)d_in[23];
    const float* W2      = (const float*)d_in[24];
    const float* b2      = (const float*)d_in[25];
    const float* ln3_g   = (const float*)d_in[26];
    const float* ln3_b   = (const float*)d_in[27];
    const float* lnf_g   = (const float*)d_in[28];
    const float* lnf_b   = (const float*)d_in[29];

    float* out = (float*)d_out;
    float* out_logits = out;
    float* out_chw    = out_logits + (size_t)BB * TT * VV;
    float* out_kv     = out_chw + (size_t)(LL / 2) * HH * TT * TAA;

    float *x, *h, *q, *o, *sc, *ckall, *cvall, *hid;
    cudaGetSymbolAddress((void**)&x,     g_x);
    cudaGetSymbolAddress((void**)&h,     g_h);
    cudaGetSymbolAddress((void**)&q,     g_q);
    cudaGetSymbolAddress((void**)&o,     g_o);
    cudaGetSymbolAddress((void**)&sc,    g_sc);
    cudaGetSymbolAddress((void**)&ckall, g_ckall);
    cudaGetSymbolAddress((void**)&cvall, g_cvall);
    cudaGetSymbolAddress((void**)&hid,   g_hid);

    embed_kernel<<<BT, 256>>>(tokens, tok_emb, pos_emb, x);

    const long DTD = (long)TT * DD;
    const long TAD = (long)TAA * DD;
    const size_t XBYTES = (size_t)BT * DD * sizeof(float);

    // cross K/V for ALL layers, batched over z=12
    {
        GemmP p = base_p();
        p.A = xa; p.lda = DD;
        p.B0 = Wck; p.ldb = DD; p.sB1 = (long)DD * DD;
        p.C0 = ckall; p.ldc = DD; p.sC1 = (long)BTAD;
        p.M = BB * TAA; p.N = DD; p.K = DD; p.Hd = LL;
        launch_g<0>(p, LL);
        p.B0 = Wcv; p.C0 = cvall;
        p.bias0 = bcv; p.sBias = DD;
        launch_g<0>(p, LL);
    }

    for (int l = 0; l < LL; l++) {
        const float* Wq_l = Wq + (size_t)l * DD * DD;
        const float* Wk_l = Wk + (size_t)l * DD * DD;
        const float* Wv_l = Wv + (size_t)l * DD * DD;
        const float* Wo_l = Wo + (size_t)l * DD * DD;
        const float* Wcq_l = Wcq + (size_t)l * DD * DD;
        const float* Wco_l = Wco + (size_t)l * DD * DD;
        const float* W1_l = W1 + (size_t)l * DD * 4 * DD;
        const float* W2_l = W2 + (size_t)l * 4 * DD * DD;

        float* kout = out_kv + (size_t)(2 * l) * BT * DD;
        float* vout = out_kv + (size_t)(2 * l + 1) * BT * DD;
        float* ck_l = ckall + (size_t)l * BTAD;
        float* cv_l = cvall + (size_t)l * BTAD;

        // ---- self attention ----
        ln_kernel<<<BT, 256>>>(x, h, ln1_g + l * DD, ln1_b + l * DD);
        {   // fused QKV (288 blocks)
            GemmP p = base_p();
            p.A = h; p.lda = DD;
            p.B0 = Wq_l; p.B1 = Wk_l; p.B2 = Wv_l; p.ldb = DD;
            p.C0 = q; p.C1 = kout; p.C2 = vout; p.ldc = DD;
            p.bias0 = bq + l * DD; p.bias1 = nullptr; p.bias2 = bv + l * DD;
            p.s0 = SCALE_Q; p.s1 = 1.f; p.s2 = 1.f;
            p.segW = DD;
            p.M = BT; p.N = 3 * DD; p.K = DD;
            launch_g<0>(p, 1);
        }
        {   // scores = q @ k^T (384 blocks)
            GemmP p = base_p();
            p.A = q; p.lda = DD; p.sA0 = DTD; p.sA1 = DHH;
            p.B0 = kout; p.ldb = DD; p.sB0 = DTD; p.sB1 = DHH;
            p.C0 = sc; p.ldc = TT; p.sC0 = (long)HH * TT * TT; p.sC1 = (long)TT * TT;
            p.M = TT; p.N = TT; p.K = DHH; p.Hd = HH;
            launch_g<1>(p, BB * HH);
        }
        softmax_causal_kernel<<<BB * HH * TT, 256>>>(sc);
        cudaMemsetAsync(o, 0, XBYTES);
        {   // o = P @ v  (split-K 4 -> 384 blocks)
            GemmP p = base_p();
            p.A = sc; p.lda = TT; p.sA0 = (long)HH * TT * TT; p.sA1 = (long)TT * TT;
            p.B0 = vout; p.ldb = DD; p.sB0 = DTD; p.sB1 = DHH;
            p.C0 = o; p.ldc = DD; p.sC0 = DTD; p.sC1 = DHH;
            p.M = TT; p.N = DHH; p.K = TT; p.Hd = HH;
            launch_g<0>(p, BB * HH, 4);
        }
        {   // x += o @ Wo + bo  (split-K 4 atomics into residual)
            GemmP p = base_p();
            p.A = o; p.lda = DD;
            p.B0 = Wo_l; p.ldb = DD;
            p.C0 = x; p.ldc = DD;
            p.bias0 = bo + l * DD;
            p.M = BT; p.N = DD; p.K = DD;
            launch_g<0>(p, 1, 4);
        }

        // ---- cross attention ----
        ln_kernel<<<BT, 256>>>(x, h, ln2_g + l * DD, ln2_b + l * DD);
        cudaMemsetAsync(q, 0, XBYTES);
        {   // q2 (split-K 4)
            GemmP p = base_p();
            p.A = h; p.lda = DD;
            p.B0 = Wcq_l; p.ldb = DD;
            p.C0 = q; p.ldc = DD;
            p.bias0 = bcq + l * DD; p.s0 = SCALE_Q;
            p.M = BT; p.N = DD; p.K = DD;
            launch_g<0>(p, 1, 4);
        }
        {   // qk2 = q2 @ ck^T (+mirror, 2304 blocks)
            GemmP p = base_p();
            p.A = q; p.lda = DD; p.sA0 = DTD; p.sA1 = DHH;
            p.B0 = ck_l; p.ldb = DD; p.sB0 = TAD; p.sB1 = DHH;
            p.C0 = sc; p.ldc = TAA; p.sC0 = (long)HH * TT * TAA; p.sC1 = (long)TT * TAA;
            p.mir = (l >= LL / 2)
                  ? out_chw + (size_t)(l - LL / 2) * HH * TT * TAA : nullptr;
            p.M = TT; p.N = TAA; p.K = DHH; p.Hd = HH;
            launch_g<1>(p, BB * HH);
        }
        softmax_plain_kernel<<<BB * HH * TT, 256>>>(sc, TAA);
        cudaMemsetAsync(o, 0, XBYTES);
        {   // o2 = P2 @ cv  (split-K 8 -> 768 blocks)
            GemmP p = base_p();
            p.A = sc; p.lda = TAA; p.sA0 = (long)HH * TT * TAA; p.sA1 = (long)TT * TAA;
            p.B0 = cv_l; p.ldb = DD; p.sB0 = TAD; p.sB1 = DHH;
            p.C0 = o; p.ldc = DD; p.sC0 = DTD; p.sC1 = DHH;
            p.M = TT; p.N = DHH; p.K = TAA; p.Hd = HH;
            launch_g<0>(p, BB * HH, 8);
        }
        {   // x += o2 @ Wco + bco  (split-K 4)
            GemmP p = base_p();
            p.A = o; p.lda = DD;
            p.B0 = Wco_l; p.ldb = DD;
            p.C0 = x; p.ldc = DD;
            p.bias0 = bco + l * DD;
            p.M = BT; p.N = DD; p.K = DD;
            launch_g<0>(p, 1, 4);
        }

        // ---- MLP ----
        ln_kernel<<<BT, 256>>>(x, h, ln3_g + l * DD, ln3_b + l * DD);
        {   // hid = gelu(h @ W1 + b1)  (384 blocks)
            GemmP p = base_p();
            p.A = h; p.lda = DD;
            p.B0 = W1_l; p.ldb = 4 * DD;
            p.C0 = hid; p.ldc = 4 * DD;
            p.bias0 = b1 + (size_t)l * 4 * DD; p.act = 1;
            p.M = BT; p.N = 4 * DD; p.K = DD;
            launch_g<0>(p, 1);
        }
        {   // x += hid @ W2 + b2  (split-K 8)
            GemmP p = base_p();
            p.A = hid; p.lda = 4 * DD;
            p.B0 = W2_l; p.ldb = DD;
            p.C0 = x; p.ldc = DD;
            p.bias0 = b2 + l * DD;
            p.M = BT; p.N = DD; p.K = 4 * DD;
            launch_g<0>(p, 1, 8);
        }
    }

    // final LN + tied-embedding logits
    ln_kernel<<<BT, 256>>>(x, h, lnf_g, lnf_b);
    {
        GemmP p = base_p();
        p.A = h; p.lda = DD;
        p.B0 = tok_emb; p.ldb = DD;
        p.C0 = out_logits; p.ldc = VV;
        p.M = BT; p.N = VV; p.K = DD;
        launch_g<1>(p, 1);
    }
}

// round 6
// speedup vs baseline: 2.8790x; 1.0629x over previous
#include <cuda_runtime.h>
#include <cuda_bf16.h>
#include <math.h>
#include <stdint.h>

// ---------------- problem constants ----------------
#define BB   4
#define TT   256
#define TAA  1500
#define DD   768
#define HH   12
#define LL   12
#define VV   51865
#define DHH  64
#define BT   (BB*TT)          // 1024
#define SCALE_Q 0.125f
#define BTAD ((size_t)BB*TAA*DD)

// ---------------- scratch ----------------
__device__ float g_x  [BT*DD];
__device__ float g_h  [BT*DD];
__device__ float g_q  [BT*DD];
__device__ float g_o  [BT*DD];
__device__ float g_ckall[(size_t)LL*BTAD];
__device__ float g_cvall[(size_t)LL*BTAD];
__device__ float g_hid[(size_t)BT*4*DD];

// ---------------- shared helpers ----------------
__device__ __forceinline__ uint32_t pack_bf(float a, float b) {
    __nv_bfloat162 t;
    t.x = __float2bfloat16_rn(a);
    t.y = __float2bfloat16_rn(b);
    return *(uint32_t*)&t;
}

__device__ __forceinline__ void split_pair(float2 v, uint32_t& hi, uint32_t& lo) {
    __nv_bfloat16 hx = __float2bfloat16_rn(v.x);
    __nv_bfloat16 hy = __float2bfloat16_rn(v.y);
    hi = pack_bf(v.x, v.y);
    lo = pack_bf(v.x - __bfloat162float(hx), v.y - __bfloat162float(hy));
}

__device__ __forceinline__ uint32_t lo_pack(float a, float b) {
    float ra = a - __bfloat162float(__float2bfloat16_rn(a));
    float rb = b - __bfloat162float(__float2bfloat16_rn(b));
    return pack_bf(ra, rb);
}

__device__ __forceinline__ void mma_bf16(float* c, const uint32_t* a, const uint32_t* b) {
    asm volatile(
        "mma.sync.aligned.m16n8k16.row.col.f32.bf16.bf16.f32 "
        "{%0,%1,%2,%3}, {%4,%5,%6,%7}, {%8,%9}, {%0,%1,%2,%3};"
        : "+f"(c[0]), "+f"(c[1]), "+f"(c[2]), "+f"(c[3])
        : "r"(a[0]), "r"(a[1]), "r"(a[2]), "r"(a[3]), "r"(b[0]), "r"(b[1]));
}

// ---------------- bf16 split GEMM (3-term) + split-K ----------------
#define TBM 128
#define TBN 64
#define TBK 32
#define ALD 20
#define BTLD 20
#define BNLD 72

struct GemmP {
    const float *A, *B0, *B1, *B2;
    float *C0, *C1, *C2;
    const float *bias0, *bias1, *bias2, *res;
    float *mir;
    int M, N, K, lda, ldb, ldc, Hd, segW, act, splitK, kc;
    long sA0, sA1, sB0, sB1, sC0, sC1, sBias;
    float s0, s1, s2;
};

template <int NT>
__global__ __launch_bounds__(256, 2) void gemm_bf3_kernel(GemmP p)
{
    __shared__ uint32_t AH[TBM][ALD];
    __shared__ uint32_t AL[TBM][ALD];
    __shared__ uint32_t BH[1280];
    __shared__ uint32_t BL[1280];

    int z = blockIdx.z;
    int sk = z % p.splitK;
    int zz = z / p.splitK;
    int zb = zz / p.Hd, zh = zz % p.Hd;
    int bm = blockIdx.y * TBM, bn = blockIdx.x * TBN;
    int seg = bn / p.segW;
    int bnl = bn - seg * p.segW;

    const float* A = p.A + zb * p.sA0 + zh * p.sA1;
    const float* B = (seg == 0 ? p.B0 : seg == 1 ? p.B1 : p.B2) + zb * p.sB0 + zh * p.sB1;
    float* C = (seg == 0 ? p.C0 : seg == 1 ? p.C1 : p.C2) + zb * p.sC0 + zh * p.sC1;
    const float* bias = (seg == 0 ? p.bias0 : seg == 1 ? p.bias1 : p.bias2);
    if (bias) bias += zh * p.sBias;
    float scl = seg == 0 ? p.s0 : seg == 1 ? p.s1 : p.s2;
    const float* R = (p.res && seg == 0) ? p.res + zb * p.sC0 + zh * p.sC1 : nullptr;
    float* Mr = (p.mir && zb == 0 && seg == 0) ? p.mir + zh * p.sC1 : nullptr;
    bool atom = p.splitK > 1;

    int M = p.M, N = p.N;
    int lda = p.lda, ldb = p.ldb, ldc = p.ldc;
    int kstart = sk * p.kc;
    int kend = min(p.K, kstart + p.kc);

    int tid  = threadIdx.x;
    int lane = tid & 31;
    int warp = tid >> 5;
    int g    = lane >> 2;
    int tig  = lane & 3;
    int m0w  = (warp & 3) * 32;
    int n0w  = (warp >> 2) * 32;

    float c[2][4][4];
#pragma unroll
    for (int mi = 0; mi < 2; mi++)
#pragma unroll
        for (int ni = 0; ni < 4; ni++)
#pragma unroll
            for (int e = 0; e < 4; e++) c[mi][ni][e] = 0.f;

    int iters = (kend - kstart + TBK - 1) / TBK;
    float2 ra[8], rb[4];

    {
        int kk = kstart;
#pragma unroll
        for (int i = 0; i < 8; i++) {
            int pidx = i * 256 + tid;
            int r = pidx >> 4, kp = pidx & 15;
            int gr = bm + r, k0 = kk + 2 * kp;
            float2 v = {0.f, 0.f};
            if (gr < M) {
                if (k0 + 1 < kend)      v = *(const float2*)&A[(long)gr * lda + k0];
                else if (k0 < kend)     v.x = A[(long)gr * lda + k0];
            }
            ra[i] = v;
        }
#pragma unroll
        for (int i = 0; i < 4; i++) {
            int pidx = i * 256 + tid;
            float2 v = {0.f, 0.f};
            if (NT) {
                int n = pidx >> 4, kp = pidx & 15;
                int k0 = kk + 2 * kp;
                if (bn + n < N) {
                    long base = (long)(bnl + n) * ldb;
                    if (k0 + 1 < kend)  v = *(const float2*)&B[base + k0];
                    else if (k0 < kend) v.x = B[base + k0];
                }
            } else {
                int n = pidx & 63, kp = pidx >> 6;
                int k0 = kk + 2 * kp;
                if (bn + n < N) {
                    if (k0 < kend)     v.x = B[(long)k0 * ldb + bnl + n];
                    if (k0 + 1 < kend) v.y = B[(long)(k0 + 1) * ldb + bnl + n];
                }
            }
            rb[i] = v;
        }
    }

    for (int it = 0; it < iters; it++) {
#pragma unroll
        for (int i = 0; i < 8; i++) {
            int pidx = i * 256 + tid;
            int r = pidx >> 4, kp = pidx & 15;
            split_pair(ra[i], AH[r][kp], AL[r][kp]);
        }
#pragma unroll
        for (int i = 0; i < 4; i++) {
            int pidx = i * 256 + tid;
            uint32_t hi, lo;
            split_pair(rb[i], hi, lo);
            if (NT) {
                int n = pidx >> 4, kp = pidx & 15;
                BH[n * BTLD + kp] = hi;
                BL[n * BTLD + kp] = lo;
            } else {
                int n = pidx & 63, kp = pidx >> 6;
                BH[kp * BNLD + n] = hi;
                BL[kp * BNLD + n] = lo;
            }
        }
        __syncthreads();

        if (it + 1 < iters) {
            int kk = kstart + (it + 1) * TBK;
#pragma unroll
            for (int i = 0; i < 8; i++) {
                int pidx = i * 256 + tid;
                int r = pidx >> 4, kp = pidx & 15;
                int gr = bm + r, k0 = kk + 2 * kp;
                float2 v = {0.f, 0.f};
                if (gr < M) {
                    if (k0 + 1 < kend)  v = *(const float2*)&A[(long)gr * lda + k0];
                    else if (k0 < kend) v.x = A[(long)gr * lda + k0];
                }
                ra[i] = v;
            }
#pragma unroll
            for (int i = 0; i < 4; i++) {
                int pidx = i * 256 + tid;
                float2 v = {0.f, 0.f};
                if (NT) {
                    int n = pidx >> 4, kp = pidx & 15;
                    int k0 = kk + 2 * kp;
                    if (bn + n < N) {
                        long base = (long)(bnl + n) * ldb;
                        if (k0 + 1 < kend)  v = *(const float2*)&B[base + k0];
                        else if (k0 < kend) v.x = B[base + k0];
                    }
                } else {
                    int n = pidx & 63, kp = pidx >> 6;
                    int k0 = kk + 2 * kp;
                    if (bn + n < N) {
                        if (k0 < kend)     v.x = B[(long)k0 * ldb + bnl + n];
                        if (k0 + 1 < kend) v.y = B[(long)(k0 + 1) * ldb + bnl + n];
                    }
                }
                rb[i] = v;
            }
        }

#pragma unroll
        for (int h = 0; h < 2; h++) {
            int kb = h * 8;
            uint32_t aH4[2][4], aL4[2][4];
#pragma unroll
            for (int mi = 0; mi < 2; mi++) {
                int m = m0w + mi * 16 + g;
                aH4[mi][0] = AH[m    ][kb + tig];
                aH4[mi][1] = AH[m + 8][kb + tig];
                aH4[mi][2] = AH[m    ][kb + tig + 4];
                aH4[mi][3] = AH[m + 8][kb + tig + 4];
                aL4[mi][0] = AL[m    ][kb + tig];
                aL4[mi][1] = AL[m + 8][kb + tig];
                aL4[mi][2] = AL[m    ][kb + tig + 4];
                aL4[mi][3] = AL[m + 8][kb + tig + 4];
            }
            uint32_t bh2[4][2], bl2[4][2];
#pragma unroll
            for (int ni = 0; ni < 4; ni++) {
                int n = n0w + ni * 8 + g;
                if (NT) {
                    bh2[ni][0] = BH[n * BTLD + kb + tig];
                    bh2[ni][1] = BH[n * BTLD + kb + tig + 4];
                    bl2[ni][0] = BL[n * BTLD + kb + tig];
                    bl2[ni][1] = BL[n * BTLD + kb + tig + 4];
                } else {
                    bh2[ni][0] = BH[(kb + tig) * BNLD + n];
                    bh2[ni][1] = BH[(kb + tig + 4) * BNLD + n];
                    bl2[ni][0] = BL[(kb + tig) * BNLD + n];
                    bl2[ni][1] = BL[(kb + tig + 4) * BNLD + n];
                }
            }
#pragma unroll
            for (int mi = 0; mi < 2; mi++)
#pragma unroll
                for (int ni = 0; ni < 4; ni++) {
                    mma_bf16(c[mi][ni], aH4[mi], bl2[ni]);
                    mma_bf16(c[mi][ni], aL4[mi], bh2[ni]);
                    mma_bf16(c[mi][ni], aH4[mi], bh2[ni]);
                }
        }
        __syncthreads();
    }

#pragma unroll
    for (int mi = 0; mi < 2; mi++) {
#pragma unroll
        for (int ni = 0; ni < 4; ni++) {
#pragma unroll
            for (int e = 0; e < 4; e++) {
                int row = bm + m0w + mi * 16 + g + ((e >= 2) ? 8 : 0);
                int gcol = bn + n0w + ni * 8 + tig * 2 + (e & 1);
                if (row >= M || gcol >= N) continue;
                int lc = gcol - seg * p.segW;
                float v = c[mi][ni][e];
                if (bias && (!atom || sk == 0)) v += bias[lc];
                v *= scl;
                long ci = (long)row * ldc + lc;
                if (atom) {
                    atomicAdd(&C[ci], v);
                } else {
                    if (p.act == 1) v = 0.5f * v * (1.f + erff(v * 0.70710678118654752f));
                    if (R) v += R[ci];
                    C[ci] = v;
                    if (Mr) Mr[ci] = v;
                }
            }
        }
    }
}

// ---------------- fused flash attention ----------------
// One block: 64 query rows (one head), 128 threads = 4 warps (16 rows each).
// Online softmax, 3-term bf16-split mma for both QK^T and PV.
// Optional mirror write of pre-softmax scores (beam 0) for cross_head_weights.
__global__ __launch_bounds__(128) void flash_kernel(
    const float* __restrict__ Qb, const float* __restrict__ Kb,
    const float* __restrict__ Vb, float* __restrict__ Ob,
    float* __restrict__ mir, int lenKV, long kvBStride, int causal)
{
    __shared__ uint32_t Kh[64][36], Kl[64][36];
    __shared__ uint32_t Vh[64][33], Vl[64][33];

    int mt = blockIdx.x;
    int by = blockIdx.y;
    int b = by / HH, hh = by % HH;

    const float* Q = Qb + ((long)b * TT + mt * 64) * DD + hh * DHH;
    const float* K = Kb + (long)b * kvBStride + hh * DHH;
    const float* V = Vb + (long)b * kvBStride + hh * DHH;
    float* O = Ob + ((long)b * TT + mt * 64) * DD + hh * DHH;
    float* Mr = (mir && b == 0)
              ? mir + (size_t)hh * TT * TAA + (size_t)mt * 64 * TAA : nullptr;

    int tid = threadIdx.x;
    int lane = tid & 31, warp = tid >> 5;
    int g = lane >> 2, tig = lane & 3;
    int m0w = warp * 16;

    // Q fragments (held in registers for the whole block)
    uint32_t Qah[4][4], Qal[4][4];
#pragma unroll
    for (int kb = 0; kb < 4; kb++) {
        int c0 = 16 * kb + 2 * tig;
        const float* r0 = Q + (long)(m0w + g) * DD;
        const float* r1 = Q + (long)(m0w + g + 8) * DD;
        float2 v;
        v = *(const float2*)(r0 + c0);     split_pair(v, Qah[kb][0], Qal[kb][0]);
        v = *(const float2*)(r1 + c0);     split_pair(v, Qah[kb][1], Qal[kb][1]);
        v = *(const float2*)(r0 + c0 + 8); split_pair(v, Qah[kb][2], Qal[kb][2]);
        v = *(const float2*)(r1 + c0 + 8); split_pair(v, Qah[kb][3], Qal[kb][3]);
    }

    float acc[8][4];
#pragma unroll
    for (int j = 0; j < 8; j++)
#pragma unroll
        for (int e = 0; e < 4; e++) acc[j][e] = 0.f;
    float m0 = -1e30f, m1 = -1e30f, sum0 = 0.f, sum1 = 0.f;

    int nChunks = causal ? (mt + 1) : ((lenKV + 63) >> 6);
    for (int ch = 0; ch < nChunks; ch++) {
        int n0 = ch * 64;
        // stage K chunk [64 kv rows][32 d-pairs]
#pragma unroll
        for (int i = 0; i < 16; i++) {
            int idx = i * 128 + tid;
            int r = idx >> 5, c = idx & 31;
            float2 v = {0.f, 0.f};
            if (n0 + r < lenKV) v = *(const float2*)(K + (long)(n0 + r) * DD + 2 * c);
            split_pair(v, Kh[r][c], Kl[r][c]);
        }
        // stage V chunk transposed [64 d][32 kv-pairs]
#pragma unroll
        for (int i = 0; i < 16; i++) {
            int idx = i * 128 + tid;
            int d = idx & 63, pr = idx >> 6;
            float2 v = {0.f, 0.f};
            int r0i = n0 + 2 * pr;
            if (r0i < lenKV)     v.x = V[(long)r0i * DD + d];
            if (r0i + 1 < lenKV) v.y = V[(long)(r0i + 1) * DD + d];
            split_pair(v, Vh[d][pr], Vl[d][pr]);
        }
        __syncthreads();

        // S = Q @ K^T   (64 x 64, per warp 16 x 64)
        float s[8][4];
#pragma unroll
        for (int j = 0; j < 8; j++)
#pragma unroll
            for (int e = 0; e < 4; e++) s[j][e] = 0.f;
#pragma unroll
        for (int kb = 0; kb < 4; kb++) {
#pragma unroll
            for (int j = 0; j < 8; j++) {
                uint32_t bh[2] = { Kh[8 * j + g][8 * kb + tig], Kh[8 * j + g][8 * kb + tig + 4] };
                uint32_t bl[2] = { Kl[8 * j + g][8 * kb + tig], Kl[8 * j + g][8 * kb + tig + 4] };
                mma_bf16(s[j], Qah[kb], bl);
                mma_bf16(s[j], Qal[kb], bh);
                mma_bf16(s[j], Qah[kb], bh);
            }
        }

        // mirror pre-softmax scores (cross, beam 0)
        if (Mr) {
#pragma unroll
            for (int j = 0; j < 8; j++) {
                int col = n0 + 8 * j + 2 * tig;
                if (col < lenKV) {
                    float2 v0 = { s[j][0], s[j][1] };
                    float2 v1 = { s[j][2], s[j][3] };
                    *(float2*)&Mr[(long)(m0w + g) * TAA + col] = v0;
                    *(float2*)&Mr[(long)(m0w + g + 8) * TAA + col] = v1;
                }
            }
        }

        // masks
        if (causal && ch == mt) {
            int t0 = mt * 64 + m0w + g;
#pragma unroll
            for (int j = 0; j < 8; j++) {
                int col = n0 + 8 * j + 2 * tig;
                if (col     > t0)     s[j][0] = -1e30f;
                if (col + 1 > t0)     s[j][1] = -1e30f;
                if (col     > t0 + 8) s[j][2] = -1e30f;
                if (col + 1 > t0 + 8) s[j][3] = -1e30f;
            }
        }
        if (n0 + 64 > lenKV) {
#pragma unroll
            for (int j = 0; j < 8; j++) {
                int col = n0 + 8 * j + 2 * tig;
                if (col     >= lenKV) { s[j][0] = -1e30f; s[j][2] = -1e30f; }
                if (col + 1 >= lenKV) { s[j][1] = -1e30f; s[j][3] = -1e30f; }
            }
        }

        // online softmax
        float mx0 = -1e30f, mx1 = -1e30f;
#pragma unroll
        for (int j = 0; j < 8; j++) {
            mx0 = fmaxf(mx0, fmaxf(s[j][0], s[j][1]));
            mx1 = fmaxf(mx1, fmaxf(s[j][2], s[j][3]));
        }
        mx0 = fmaxf(mx0, __shfl_xor_sync(0xffffffffu, mx0, 1));
        mx0 = fmaxf(mx0, __shfl_xor_sync(0xffffffffu, mx0, 2));
        mx1 = fmaxf(mx1, __shfl_xor_sync(0xffffffffu, mx1, 1));
        mx1 = fmaxf(mx1, __shfl_xor_sync(0xffffffffu, mx1, 2));
        float mn0 = fmaxf(m0, mx0), mn1 = fmaxf(m1, mx1);
        float a0 = __expf(m0 - mn0), a1 = __expf(m1 - mn1);
        float ps0 = 0.f, ps1 = 0.f;
#pragma unroll
        for (int j = 0; j < 8; j++) {
            s[j][0] = __expf(s[j][0] - mn0);
            s[j][1] = __expf(s[j][1] - mn0);
            s[j][2] = __expf(s[j][2] - mn1);
            s[j][3] = __expf(s[j][3] - mn1);
            ps0 += s[j][0] + s[j][1];
            ps1 += s[j][2] + s[j][3];
        }
        ps0 += __shfl_xor_sync(0xffffffffu, ps0, 1);
        ps0 += __shfl_xor_sync(0xffffffffu, ps0, 2);
        ps1 += __shfl_xor_sync(0xffffffffu, ps1, 1);
        ps1 += __shfl_xor_sync(0xffffffffu, ps1, 2);
        sum0 = sum0 * a0 + ps0;
        sum1 = sum1 * a1 + ps1;
        m0 = mn0; m1 = mn1;
#pragma unroll
        for (int j = 0; j < 8; j++) {
            acc[j][0] *= a0; acc[j][1] *= a0;
            acc[j][2] *= a1; acc[j][3] *= a1;
        }

        // O += P @ V
#pragma unroll
        for (int kb = 0; kb < 4; kb++) {
            int j0 = 2 * kb, j1 = 2 * kb + 1;
            uint32_t Ah[4], Al[4];
            Ah[0] = pack_bf(s[j0][0], s[j0][1]);  Al[0] = lo_pack(s[j0][0], s[j0][1]);
            Ah[1] = pack_bf(s[j0][2], s[j0][3]);  Al[1] = lo_pack(s[j0][2], s[j0][3]);
            Ah[2] = pack_bf(s[j1][0], s[j1][1]);  Al[2] = lo_pack(s[j1][0], s[j1][1]);
            Ah[3] = pack_bf(s[j1][2], s[j1][3]);  Al[3] = lo_pack(s[j1][2], s[j1][3]);
#pragma unroll
            for (int jd = 0; jd < 8; jd++) {
                uint32_t bh[2] = { Vh[8 * jd + g][8 * kb + tig], Vh[8 * jd + g][8 * kb + tig + 4] };
                uint32_t bl[2] = { Vl[8 * jd + g][8 * kb + tig], Vl[8 * jd + g][8 * kb + tig + 4] };
                mma_bf16(acc[jd], Ah, bl);
                mma_bf16(acc[jd], Al, bh);
                mma_bf16(acc[jd], Ah, bh);
            }
        }
        __syncthreads();
    }

    // normalize + write
    float i0 = 1.f / sum0, i1 = 1.f / sum1;
#pragma unroll
    for (int jd = 0; jd < 8; jd++) {
        int col = 8 * jd + 2 * tig;
        float2 v0 = { acc[jd][0] * i0, acc[jd][1] * i0 };
        float2 v1 = { acc[jd][2] * i1, acc[jd][3] * i1 };
        *(float2*)&O[(long)(m0w + g) * DD + col] = v0;
        *(float2*)&O[(long)(m0w + g + 8) * DD + col] = v1;
    }
}

// ---------------- elementwise / row kernels ----------------
__global__ __launch_bounds__(256) void embed_kernel(
    const int* __restrict__ tokens, const float* __restrict__ tok_emb,
    const float* __restrict__ pos_emb, float* __restrict__ x)
{
    int row = blockIdx.x;
    int t = row % TT;
    int tok = tokens[row];
    const float* te = tok_emb + (long)tok * DD;
    const float* pe = pos_emb + (long)t * DD;
    float* xr = x + (long)row * DD;
#pragma unroll
    for (int it = 0; it < 3; it++) {
        int j = threadIdx.x + it * 256;
        xr[j] = te[j] + pe[j];
    }
}

__global__ __launch_bounds__(256) void ln_kernel(
    const float* __restrict__ x, float* __restrict__ y,
    const float* __restrict__ g, const float* __restrict__ b)
{
    __shared__ float red[256];
    int row = blockIdx.x;
    const float* xr = x + (long)row * DD;
    float* yr = y + (long)row * DD;
    int tid = threadIdx.x;
    float v0 = xr[tid], v1 = xr[tid + 256], v2 = xr[tid + 512];
    float s = v0 + v1 + v2;
    red[tid] = s; __syncthreads();
    for (int st = 128; st > 0; st >>= 1) { if (tid < st) red[tid] += red[tid + st]; __syncthreads(); }
    float mean = red[0] * (1.f / DD);
    __syncthreads();
    float d0 = v0 - mean, d1 = v1 - mean, d2 = v2 - mean;
    red[tid] = d0 * d0 + d1 * d1 + d2 * d2; __syncthreads();
    for (int st = 128; st > 0; st >>= 1) { if (tid < st) red[tid] += red[tid + st]; __syncthreads(); }
    float inv = rsqrtf(red[0] * (1.f / DD) + 1e-5f);
    yr[tid]       = d0 * inv * g[tid]       + b[tid];
    yr[tid + 256] = d1 * inv * g[tid + 256] + b[tid + 256];
    yr[tid + 512] = d2 * inv * g[tid + 512] + b[tid + 512];
}

// ---------------- host-side launch helpers ----------------
static GemmP base_p() {
    GemmP p;
    p.A = nullptr; p.B0 = p.B1 = p.B2 = nullptr;
    p.C0 = p.C1 = p.C2 = nullptr;
    p.bias0 = p.bias1 = p.bias2 = nullptr; p.res = nullptr; p.mir = nullptr;
    p.M = p.N = p.K = 0; p.lda = p.ldb = p.ldc = 0;
    p.Hd = 1; p.segW = 1 << 30; p.act = 0; p.splitK = 1; p.kc = 0;
    p.sA0 = p.sA1 = p.sB0 = p.sB1 = p.sC0 = p.sC1 = p.sBias = 0;
    p.s0 = p.s1 = p.s2 = 1.f;
    return p;
}

template <int NT>
static inline void launch_g(GemmP p, int batch, int splitK = 1) {
    p.splitK = splitK;
    int kc = (p.K + splitK - 1) / splitK;
    p.kc = ((kc + TBK - 1) / TBK) * TBK;
    dim3 grd((p.N + TBN - 1) / TBN, (p.M + TBM - 1) / TBM, batch * splitK);
    gemm_bf3_kernel<NT><<<grd, 256>>>(p);
}

extern "C" void kernel_launch(void* const* d_in, const int* in_sizes, int n_in,
                              void* d_out, int out_size)
{
    (void)in_sizes; (void)n_in; (void)out_size;

    const int*   tokens  = (const int*)  d_in[0];
    const float* xa      = (const float*)d_in[1];
    const float* tok_emb = (const float*)d_in[2];
    const float* pos_emb = (const float*)d_in[3];
    const float* Wq      = (const float*)d_in[4];
    const float* bq      = (const float*)d_in[5];
    const float* Wk      = (const float*)d_in[6];
    const float* Wv      = (const float*)d_in[7];
    const float* bv      = (const float*)d_in[8];
    const float* Wo      = (const float*)d_in[9];
    const float* bo      = (const float*)d_in[10];
    const float* ln1_g   = (const float*)d_in[11];
    const float* ln1_b   = (const float*)d_in[12];
    const float* Wcq     = (const float*)d_in[13];
    const float* bcq     = (const float*)d_in[14];
    const float* Wck     = (const float*)d_in[15];
    const float* Wcv     = (const float*)d_in[16];
    const float* bcv     = (const float*)d_in[17];
    const float* Wco     = (const float*)d_in[18];
    const float* bco     = (const float*)d_in[19];
    const float* ln2_g   = (const float*)d_in[20];
    const float* ln2_b   = (const float*)d_in[21];
    const float* W1      = (const float*)d_in[22];
    const float* b1      = (const float*)d_in[23];
    const float* W2      = (const float*)d_in[24];
    const float* b2      = (const float*)d_in[25];
    const float* ln3_g   = (const float*)d_in[26];
    const float* ln3_b   = (const float*)d_in[27];
    const float* lnf_g   = (const float*)d_in[28];
    const float* lnf_b   = (const float*)d_in[29];

    float* out = (float*)d_out;
    float* out_logits = out;
    float* out_chw    = out_logits + (size_t)BB * TT * VV;
    float* out_kv     = out_chw + (size_t)(LL / 2) * HH * TT * TAA;

    float *x, *h, *q, *o, *ckall, *cvall, *hid;
    cudaGetSymbolAddress((void**)&x,     g_x);
    cudaGetSymbolAddress((void**)&h,     g_h);
    cudaGetSymbolAddress((void**)&q,     g_q);
    cudaGetSymbolAddress((void**)&o,     g_o);
    cudaGetSymbolAddress((void**)&ckall, g_ckall);
    cudaGetSymbolAddress((void**)&cvall, g_cvall);
    cudaGetSymbolAddress((void**)&hid,   g_hid);

    embed_kernel<<<BT, 256>>>(tokens, tok_emb, pos_emb, x);

    const long DTD = (long)TT * DD;
    const long TAD = (long)TAA * DD;
    const size_t XBYTES = (size_t)BT * DD * sizeof(float);
    const dim3 fgrid(TT / 64, BB * HH);

    // cross K/V for ALL layers, batched over z=12
    {
        GemmP p = base_p();
        p.A = xa; p.lda = DD;
        p.B0 = Wck; p.ldb = DD; p.sB1 = (long)DD * DD;
        p.C0 = ckall; p.ldc = DD; p.sC1 = (long)BTAD;
        p.M = BB * TAA; p.N = DD; p.K = DD; p.Hd = LL;
        launch_g<0>(p, LL);
        p.B0 = Wcv; p.C0 = cvall;
        p.bias0 = bcv; p.sBias = DD;
        launch_g<0>(p, LL);
    }

    for (int l = 0; l < LL; l++) {
        const float* Wq_l = Wq + (size_t)l * DD * DD;
        const float* Wk_l = Wk + (size_t)l * DD * DD;
        const float* Wv_l = Wv + (size_t)l * DD * DD;
        const float* Wo_l = Wo + (size_t)l * DD * DD;
        const float* Wcq_l = Wcq + (size_t)l * DD * DD;
        const float* Wco_l = Wco + (size_t)l * DD * DD;
        const float* W1_l = W1 + (size_t)l * DD * 4 * DD;
        const float* W2_l = W2 + (size_t)l * 4 * DD * DD;

        float* kout = out_kv + (size_t)(2 * l) * BT * DD;
        float* vout = out_kv + (size_t)(2 * l + 1) * BT * DD;
        float* ck_l = ckall + (size_t)l * BTAD;
        float* cv_l = cvall + (size_t)l * BTAD;

        // ---- self attention ----
        ln_kernel<<<BT, 256>>>(x, h, ln1_g + l * DD, ln1_b + l * DD);
        {   // fused QKV
            GemmP p = base_p();
            p.A = h; p.lda = DD;
            p.B0 = Wq_l; p.B1 = Wk_l; p.B2 = Wv_l; p.ldb = DD;
            p.C0 = q; p.C1 = kout; p.C2 = vout; p.ldc = DD;
            p.bias0 = bq + l * DD; p.bias1 = nullptr; p.bias2 = bv + l * DD;
            p.s0 = SCALE_Q; p.s1 = 1.f; p.s2 = 1.f;
            p.segW = DD;
            p.M = BT; p.N = 3 * DD; p.K = DD;
            launch_g<0>(p, 1);
        }
        flash_kernel<<<fgrid, 128>>>(q, kout, vout, o, nullptr, TT, DTD, 1);
        {   // x += o @ Wo + bo
            GemmP p = base_p();
            p.A = o; p.lda = DD;
            p.B0 = Wo_l; p.ldb = DD;
            p.C0 = x; p.ldc = DD;
            p.bias0 = bo + l * DD;
            p.M = BT; p.N = DD; p.K = DD;
            launch_g<0>(p, 1, 4);
        }

        // ---- cross attention ----
        ln_kernel<<<BT, 256>>>(x, h, ln2_g + l * DD, ln2_b + l * DD);
        cudaMemsetAsync(q, 0, XBYTES);
        {   // q2 (split-K 4)
            GemmP p = base_p();
            p.A = h; p.lda = DD;
            p.B0 = Wcq_l; p.ldb = DD;
            p.C0 = q; p.ldc = DD;
            p.bias0 = bcq + l * DD; p.s0 = SCALE_Q;
            p.M = BT; p.N = DD; p.K = DD;
            launch_g<0>(p, 1, 4);
        }
        {
            float* mir = (l >= LL / 2)
                       ? out_chw + (size_t)(l - LL / 2) * HH * TT * TAA : nullptr;
            flash_kernel<<<fgrid, 128>>>(q, ck_l, cv_l, o, mir, TAA, TAD, 0);
        }
        {   // x += o @ Wco + bco
            GemmP p = base_p();
            p.A = o; p.lda = DD;
            p.B0 = Wco_l; p.ldb = DD;
            p.C0 = x; p.ldc = DD;
            p.bias0 = bco + l * DD;
            p.M = BT; p.N = DD; p.K = DD;
            launch_g<0>(p, 1, 4);
        }

        // ---- MLP ----
        ln_kernel<<<BT, 256>>>(x, h, ln3_g + l * DD, ln3_b + l * DD);
        {
            GemmP p = base_p();
            p.A = h; p.lda = DD;
            p.B0 = W1_l; p.ldb = 4 * DD;
            p.C0 = hid; p.ldc = 4 * DD;
            p.bias0 = b1 + (size_t)l * 4 * DD; p.act = 1;
            p.M = BT; p.N = 4 * DD; p.K = DD;
            launch_g<0>(p, 1);
        }
        {
            GemmP p = base_p();
            p.A = hid; p.lda = 4 * DD;
            p.B0 = W2_l; p.ldb = DD;
            p.C0 = x; p.ldc = DD;
            p.bias0 = b2 + l * DD;
            p.M = BT; p.N = DD; p.K = 4 * DD;
            launch_g<0>(p, 1, 8);
        }
    }

    // final LN + tied-embedding logits
    ln_kernel<<<BT, 256>>>(x, h, lnf_g, lnf_b);
    {
        GemmP p = base_p();
        p.A = h; p.lda = DD;
        p.B0 = tok_emb; p.ldb = DD;
        p.C0 = out_logits; p.ldc = VV;
        p.M = BT; p.N = VV; p.K = DD;
        launch_g<1>(p, 1);
    }
}

// round 7
// speedup vs baseline: 3.1023x; 1.0776x over previous
#include <cuda_runtime.h>
#include <cuda_bf16.h>
#include <math.h>
#include <stdint.h>

// ---------------- problem constants ----------------
#define BB   4
#define TT   256
#define TAA  1500
#define DD   768
#define HH   12
#define LL   12
#define VV   51865
#define DHH  64
#define BT   (BB*TT)          // 1024
#define SCALE_Q 0.125f
#define BTAD ((size_t)BB*TAA*DD)
#define NSPLIT 4

// ---------------- scratch ----------------
__device__ float g_x  [BT*DD];
__device__ float g_h  [BT*DD];
__device__ float g_q  [BT*DD];
__device__ float g_o  [BT*DD];
__device__ float g_ckall[(size_t)LL*BTAD];
__device__ float g_cvall[(size_t)LL*BTAD];
__device__ float g_hid[(size_t)BT*4*DD];
__device__ float g_opart[(size_t)NSPLIT*BT*DD];
__device__ float2 g_msum[(size_t)NSPLIT*BB*HH*TT];

// ---------------- shared helpers ----------------
__device__ __forceinline__ uint32_t pack_bf(float a, float b) {
    __nv_bfloat162 t;
    t.x = __float2bfloat16_rn(a);
    t.y = __float2bfloat16_rn(b);
    return *(uint32_t*)&t;
}

__device__ __forceinline__ void split_pair(float2 v, uint32_t& hi, uint32_t& lo) {
    __nv_bfloat16 hx = __float2bfloat16_rn(v.x);
    __nv_bfloat16 hy = __float2bfloat16_rn(v.y);
    hi = pack_bf(v.x, v.y);
    lo = pack_bf(v.x - __bfloat162float(hx), v.y - __bfloat162float(hy));
}

__device__ __forceinline__ uint32_t lo_pack(float a, float b) {
    float ra = a - __bfloat162float(__float2bfloat16_rn(a));
    float rb = b - __bfloat162float(__float2bfloat16_rn(b));
    return pack_bf(ra, rb);
}

__device__ __forceinline__ void mma_bf16(float* c, const uint32_t* a, const uint32_t* b) {
    asm volatile(
        "mma.sync.aligned.m16n8k16.row.col.f32.bf16.bf16.f32 "
        "{%0,%1,%2,%3}, {%4,%5,%6,%7}, {%8,%9}, {%0,%1,%2,%3};"
        : "+f"(c[0]), "+f"(c[1]), "+f"(c[2]), "+f"(c[3])
        : "r"(a[0]), "r"(a[1]), "r"(a[2]), "r"(a[3]), "r"(b[0]), "r"(b[1]));
}

// ---------------- bf16 split GEMM (3-term) + split-K ----------------
#define TBM 128
#define TBN 64
#define TBK 32
#define ALD 20
#define BTLD 20
#define BNLD 72

struct GemmP {
    const float *A, *B0, *B1, *B2;
    float *C0, *C1, *C2;
    const float *bias0, *bias1, *bias2, *res;
    float *mir;
    int M, N, K, lda, ldb, ldc, Hd, segW, act, splitK, kc;
    long sA0, sA1, sB0, sB1, sC0, sC1, sBias;
    float s0, s1, s2;
};

template <int NT>
__global__ __launch_bounds__(256, 2) void gemm_bf3_kernel(GemmP p)
{
    __shared__ uint32_t AH[TBM][ALD];
    __shared__ uint32_t AL[TBM][ALD];
    __shared__ uint32_t BH[1280];
    __shared__ uint32_t BL[1280];

    int z = blockIdx.z;
    int sk = z % p.splitK;
    int zz = z / p.splitK;
    int zb = zz / p.Hd, zh = zz % p.Hd;
    int bm = blockIdx.y * TBM, bn = blockIdx.x * TBN;
    int seg = bn / p.segW;
    int bnl = bn - seg * p.segW;

    const float* A = p.A + zb * p.sA0 + zh * p.sA1;
    const float* B = (seg == 0 ? p.B0 : seg == 1 ? p.B1 : p.B2) + zb * p.sB0 + zh * p.sB1;
    float* C = (seg == 0 ? p.C0 : seg == 1 ? p.C1 : p.C2) + zb * p.sC0 + zh * p.sC1;
    const float* bias = (seg == 0 ? p.bias0 : seg == 1 ? p.bias1 : p.bias2);
    if (bias) bias += zh * p.sBias;
    float scl = seg == 0 ? p.s0 : seg == 1 ? p.s1 : p.s2;
    const float* R = (p.res && seg == 0) ? p.res + zb * p.sC0 + zh * p.sC1 : nullptr;
    float* Mr = (p.mir && zb == 0 && seg == 0) ? p.mir + zh * p.sC1 : nullptr;
    bool atom = p.splitK > 1;

    int M = p.M, N = p.N;
    int lda = p.lda, ldb = p.ldb, ldc = p.ldc;
    int kstart = sk * p.kc;
    int kend = min(p.K, kstart + p.kc);

    int tid  = threadIdx.x;
    int lane = tid & 31;
    int warp = tid >> 5;
    int g    = lane >> 2;
    int tig  = lane & 3;
    int m0w  = (warp & 3) * 32;
    int n0w  = (warp >> 2) * 32;

    float c[2][4][4];
#pragma unroll
    for (int mi = 0; mi < 2; mi++)
#pragma unroll
        for (int ni = 0; ni < 4; ni++)
#pragma unroll
            for (int e = 0; e < 4; e++) c[mi][ni][e] = 0.f;

    int iters = (kend - kstart + TBK - 1) / TBK;
    float2 ra[8], rb[4];

    {
        int kk = kstart;
#pragma unroll
        for (int i = 0; i < 8; i++) {
            int pidx = i * 256 + tid;
            int r = pidx >> 4, kp = pidx & 15;
            int gr = bm + r, k0 = kk + 2 * kp;
            float2 v = {0.f, 0.f};
            if (gr < M) {
                if (k0 + 1 < kend)      v = *(const float2*)&A[(long)gr * lda + k0];
                else if (k0 < kend)     v.x = A[(long)gr * lda + k0];
            }
            ra[i] = v;
        }
#pragma unroll
        for (int i = 0; i < 4; i++) {
            int pidx = i * 256 + tid;
            float2 v = {0.f, 0.f};
            if (NT) {
                int n = pidx >> 4, kp = pidx & 15;
                int k0 = kk + 2 * kp;
                if (bn + n < N) {
                    long base = (long)(bnl + n) * ldb;
                    if (k0 + 1 < kend)  v = *(const float2*)&B[base + k0];
                    else if (k0 < kend) v.x = B[base + k0];
                }
            } else {
                int n = pidx & 63, kp = pidx >> 6;
                int k0 = kk + 2 * kp;
                if (bn + n < N) {
                    if (k0 < kend)     v.x = B[(long)k0 * ldb + bnl + n];
                    if (k0 + 1 < kend) v.y = B[(long)(k0 + 1) * ldb + bnl + n];
                }
            }
            rb[i] = v;
        }
    }

    for (int it = 0; it < iters; it++) {
#pragma unroll
        for (int i = 0; i < 8; i++) {
            int pidx = i * 256 + tid;
            int r = pidx >> 4, kp = pidx & 15;
            split_pair(ra[i], AH[r][kp], AL[r][kp]);
        }
#pragma unroll
        for (int i = 0; i < 4; i++) {
            int pidx = i * 256 + tid;
            uint32_t hi, lo;
            split_pair(rb[i], hi, lo);
            if (NT) {
                int n = pidx >> 4, kp = pidx & 15;
                BH[n * BTLD + kp] = hi;
                BL[n * BTLD + kp] = lo;
            } else {
                int n = pidx & 63, kp = pidx >> 6;
                BH[kp * BNLD + n] = hi;
                BL[kp * BNLD + n] = lo;
            }
        }
        __syncthreads();

        if (it + 1 < iters) {
            int kk = kstart + (it + 1) * TBK;
#pragma unroll
            for (int i = 0; i < 8; i++) {
                int pidx = i * 256 + tid;
                int r = pidx >> 4, kp = pidx & 15;
                int gr = bm + r, k0 = kk + 2 * kp;
                float2 v = {0.f, 0.f};
                if (gr < M) {
                    if (k0 + 1 < kend)  v = *(const float2*)&A[(long)gr * lda + k0];
                    else if (k0 < kend) v.x = A[(long)gr * lda + k0];
                }
                ra[i] = v;
            }
#pragma unroll
            for (int i = 0; i < 4; i++) {
                int pidx = i * 256 + tid;
                float2 v = {0.f, 0.f};
                if (NT) {
                    int n = pidx >> 4, kp = pidx & 15;
                    int k0 = kk + 2 * kp;
                    if (bn + n < N) {
                        long base = (long)(bnl + n) * ldb;
                        if (k0 + 1 < kend)  v = *(const float2*)&B[base + k0];
                        else if (k0 < kend) v.x = B[base + k0];
                    }
                } else {
                    int n = pidx & 63, kp = pidx >> 6;
                    int k0 = kk + 2 * kp;
                    if (bn + n < N) {
                        if (k0 < kend)     v.x = B[(long)k0 * ldb + bnl + n];
                        if (k0 + 1 < kend) v.y = B[(long)(k0 + 1) * ldb + bnl + n];
                    }
                }
                rb[i] = v;
            }
        }

#pragma unroll
        for (int h = 0; h < 2; h++) {
            int kb = h * 8;
            uint32_t aH4[2][4], aL4[2][4];
#pragma unroll
            for (int mi = 0; mi < 2; mi++) {
                int m = m0w + mi * 16 + g;
                aH4[mi][0] = AH[m    ][kb + tig];
                aH4[mi][1] = AH[m + 8][kb + tig];
                aH4[mi][2] = AH[m    ][kb + tig + 4];
                aH4[mi][3] = AH[m + 8][kb + tig + 4];
                aL4[mi][0] = AL[m    ][kb + tig];
                aL4[mi][1] = AL[m + 8][kb + tig];
                aL4[mi][2] = AL[m    ][kb + tig + 4];
                aL4[mi][3] = AL[m + 8][kb + tig + 4];
            }
            uint32_t bh2[4][2], bl2[4][2];
#pragma unroll
            for (int ni = 0; ni < 4; ni++) {
                int n = n0w + ni * 8 + g;
                if (NT) {
                    bh2[ni][0] = BH[n * BTLD + kb + tig];
                    bh2[ni][1] = BH[n * BTLD + kb + tig + 4];
                    bl2[ni][0] = BL[n * BTLD + kb + tig];
                    bl2[ni][1] = BL[n * BTLD + kb + tig + 4];
                } else {
                    bh2[ni][0] = BH[(kb + tig) * BNLD + n];
                    bh2[ni][1] = BH[(kb + tig + 4) * BNLD + n];
                    bl2[ni][0] = BL[(kb + tig) * BNLD + n];
                    bl2[ni][1] = BL[(kb + tig + 4) * BNLD + n];
                }
            }
#pragma unroll
            for (int mi = 0; mi < 2; mi++)
#pragma unroll
                for (int ni = 0; ni < 4; ni++) {
                    mma_bf16(c[mi][ni], aH4[mi], bl2[ni]);
                    mma_bf16(c[mi][ni], aL4[mi], bh2[ni]);
                    mma_bf16(c[mi][ni], aH4[mi], bh2[ni]);
                }
        }
        __syncthreads();
    }

#pragma unroll
    for (int mi = 0; mi < 2; mi++) {
#pragma unroll
        for (int ni = 0; ni < 4; ni++) {
#pragma unroll
            for (int e = 0; e < 4; e++) {
                int row = bm + m0w + mi * 16 + g + ((e >= 2) ? 8 : 0);
                int gcol = bn + n0w + ni * 8 + tig * 2 + (e & 1);
                if (row >= M || gcol >= N) continue;
                int lc = gcol - seg * p.segW;
                float v = c[mi][ni][e];
                if (bias && (!atom || sk == 0)) v += bias[lc];
                v *= scl;
                long ci = (long)row * ldc + lc;
                if (atom) {
                    atomicAdd(&C[ci], v);
                } else {
                    if (p.act == 1) v = 0.5f * v * (1.f + erff(v * 0.70710678118654752f));
                    if (R) v += R[ci];
                    C[ci] = v;
                    if (Mr) Mr[ci] = v;
                }
            }
        }
    }
}

// ---------------- fused flash attention (optionally KV-split) ----------------
// Block: 64 query rows of one head, 128 threads = 4 warps.
// blockIdx.z = KV split; kvChunk columns per split (multiple of 64).
// If Opart != nullptr: write unnormalized acc + (m,sum) partials; else final O.
__global__ __launch_bounds__(128) void flash_kernel(
    const float* __restrict__ Qb, const float* __restrict__ Kb,
    const float* __restrict__ Vb, float* __restrict__ Ob,
    float* __restrict__ mir, int lenKV, long kvBStride, int causal,
    float* __restrict__ Opart, float2* __restrict__ Msum, int kvChunk)
{
    __shared__ uint32_t Kh[64][36], Kl[64][36];
    __shared__ uint32_t Vh[64][33], Vl[64][33];

    int mt = blockIdx.x;
    int by = blockIdx.y;
    int sp = blockIdx.z;
    int b = by / HH, hh = by % HH;

    int kvStart = sp * kvChunk;
    int kvEnd = min(lenKV, kvStart + kvChunk);

    const float* Q = Qb + ((long)b * TT + mt * 64) * DD + hh * DHH;
    const float* K = Kb + (long)b * kvBStride + hh * DHH;
    const float* V = Vb + (long)b * kvBStride + hh * DHH;
    float* Mr = (mir && b == 0)
              ? mir + (size_t)hh * TT * TAA + (size_t)mt * 64 * TAA : nullptr;

    int tid = threadIdx.x;
    int lane = tid & 31, warp = tid >> 5;
    int g = lane >> 2, tig = lane & 3;
    int m0w = warp * 16;

    // Q fragments
    uint32_t Qah[4][4], Qal[4][4];
#pragma unroll
    for (int kb = 0; kb < 4; kb++) {
        int c0 = 16 * kb + 2 * tig;
        const float* r0 = Q + (long)(m0w + g) * DD;
        const float* r1 = Q + (long)(m0w + g + 8) * DD;
        float2 v;
        v = *(const float2*)(r0 + c0);     split_pair(v, Qah[kb][0], Qal[kb][0]);
        v = *(const float2*)(r1 + c0);     split_pair(v, Qah[kb][1], Qal[kb][1]);
        v = *(const float2*)(r0 + c0 + 8); split_pair(v, Qah[kb][2], Qal[kb][2]);
        v = *(const float2*)(r1 + c0 + 8); split_pair(v, Qah[kb][3], Qal[kb][3]);
    }

    float acc[8][4];
#pragma unroll
    for (int j = 0; j < 8; j++)
#pragma unroll
        for (int e = 0; e < 4; e++) acc[j][e] = 0.f;
    float m0 = -1e30f, m1 = -1e30f, sum0 = 0.f, sum1 = 0.f;

    int chBeg = kvStart >> 6;
    int chEnd = (kvEnd + 63) >> 6;
    if (causal) chEnd = min(chEnd, mt + 1);

    for (int ch = chBeg; ch < chEnd; ch++) {
        int n0 = ch * 64;
#pragma unroll
        for (int i = 0; i < 16; i++) {
            int idx = i * 128 + tid;
            int r = idx >> 5, c = idx & 31;
            float2 v = {0.f, 0.f};
            if (n0 + r < kvEnd) v = *(const float2*)(K + (long)(n0 + r) * DD + 2 * c);
            split_pair(v, Kh[r][c], Kl[r][c]);
        }
#pragma unroll
        for (int i = 0; i < 16; i++) {
            int idx = i * 128 + tid;
            int d = idx & 63, pr = idx >> 6;
            float2 v = {0.f, 0.f};
            int r0i = n0 + 2 * pr;
            if (r0i < kvEnd)     v.x = V[(long)r0i * DD + d];
            if (r0i + 1 < kvEnd) v.y = V[(long)(r0i + 1) * DD + d];
            split_pair(v, Vh[d][pr], Vl[d][pr]);
        }
        __syncthreads();

        float s[8][4];
#pragma unroll
        for (int j = 0; j < 8; j++)
#pragma unroll
            for (int e = 0; e < 4; e++) s[j][e] = 0.f;
#pragma unroll
        for (int kb = 0; kb < 4; kb++) {
#pragma unroll
            for (int j = 0; j < 8; j++) {
                uint32_t bh[2] = { Kh[8 * j + g][8 * kb + tig], Kh[8 * j + g][8 * kb + tig + 4] };
                uint32_t bl[2] = { Kl[8 * j + g][8 * kb + tig], Kl[8 * j + g][8 * kb + tig + 4] };
                mma_bf16(s[j], Qah[kb], bl);
                mma_bf16(s[j], Qal[kb], bh);
                mma_bf16(s[j], Qah[kb], bh);
            }
        }

        if (Mr) {
#pragma unroll
            for (int j = 0; j < 8; j++) {
                int col = n0 + 8 * j + 2 * tig;
                if (col < kvEnd) {
                    float2 v0 = { s[j][0], s[j][1] };
                    float2 v1 = { s[j][2], s[j][3] };
                    *(float2*)&Mr[(long)(m0w + g) * TAA + col] = v0;
                    *(float2*)&Mr[(long)(m0w + g + 8) * TAA + col] = v1;
                }
            }
        }

        if (causal && ch == mt) {
            int t0 = mt * 64 + m0w + g;
#pragma unroll
            for (int j = 0; j < 8; j++) {
                int col = n0 + 8 * j + 2 * tig;
                if (col     > t0)     s[j][0] = -1e30f;
                if (col + 1 > t0)     s[j][1] = -1e30f;
                if (col     > t0 + 8) s[j][2] = -1e30f;
                if (col + 1 > t0 + 8) s[j][3] = -1e30f;
            }
        }
        if (n0 + 64 > kvEnd) {
#pragma unroll
            for (int j = 0; j < 8; j++) {
                int col = n0 + 8 * j + 2 * tig;
                if (col     >= kvEnd) { s[j][0] = -1e30f; s[j][2] = -1e30f; }
                if (col + 1 >= kvEnd) { s[j][1] = -1e30f; s[j][3] = -1e30f; }
            }
        }

        float mx0 = -1e30f, mx1 = -1e30f;
#pragma unroll
        for (int j = 0; j < 8; j++) {
            mx0 = fmaxf(mx0, fmaxf(s[j][0], s[j][1]));
            mx1 = fmaxf(mx1, fmaxf(s[j][2], s[j][3]));
        }
        mx0 = fmaxf(mx0, __shfl_xor_sync(0xffffffffu, mx0, 1));
        mx0 = fmaxf(mx0, __shfl_xor_sync(0xffffffffu, mx0, 2));
        mx1 = fmaxf(mx1, __shfl_xor_sync(0xffffffffu, mx1, 1));
        mx1 = fmaxf(mx1, __shfl_xor_sync(0xffffffffu, mx1, 2));
        float mn0 = fmaxf(m0, mx0), mn1 = fmaxf(m1, mx1);
        float a0 = __expf(m0 - mn0), a1 = __expf(m1 - mn1);
        float ps0 = 0.f, ps1 = 0.f;
#pragma unroll
        for (int j = 0; j < 8; j++) {
            s[j][0] = __expf(s[j][0] - mn0);
            s[j][1] = __expf(s[j][1] - mn0);
            s[j][2] = __expf(s[j][2] - mn1);
            s[j][3] = __expf(s[j][3] - mn1);
            ps0 += s[j][0] + s[j][1];
            ps1 += s[j][2] + s[j][3];
        }
        ps0 += __shfl_xor_sync(0xffffffffu, ps0, 1);
        ps0 += __shfl_xor_sync(0xffffffffu, ps0, 2);
        ps1 += __shfl_xor_sync(0xffffffffu, ps1, 1);
        ps1 += __shfl_xor_sync(0xffffffffu, ps1, 2);
        sum0 = sum0 * a0 + ps0;
        sum1 = sum1 * a1 + ps1;
        m0 = mn0; m1 = mn1;
#pragma unroll
        for (int j = 0; j < 8; j++) {
            acc[j][0] *= a0; acc[j][1] *= a0;
            acc[j][2] *= a1; acc[j][3] *= a1;
        }

#pragma unroll
        for (int kb = 0; kb < 4; kb++) {
            int j0 = 2 * kb, j1 = 2 * kb + 1;
            uint32_t Ah[4], Al[4];
            Ah[0] = pack_bf(s[j0][0], s[j0][1]);  Al[0] = lo_pack(s[j0][0], s[j0][1]);
            Ah[1] = pack_bf(s[j0][2], s[j0][3]);  Al[1] = lo_pack(s[j0][2], s[j0][3]);
            Ah[2] = pack_bf(s[j1][0], s[j1][1]);  Al[2] = lo_pack(s[j1][0], s[j1][1]);
            Ah[3] = pack_bf(s[j1][2], s[j1][3]);  Al[3] = lo_pack(s[j1][2], s[j1][3]);
#pragma unroll
            for (int jd = 0; jd < 8; jd++) {
                uint32_t bh[2] = { Vh[8 * jd + g][8 * kb + tig], Vh[8 * jd + g][8 * kb + tig + 4] };
                uint32_t bl[2] = { Vl[8 * jd + g][8 * kb + tig], Vl[8 * jd + g][8 * kb + tig + 4] };
                mma_bf16(acc[jd], Ah, bl);
                mma_bf16(acc[jd], Al, bh);
                mma_bf16(acc[jd], Ah, bh);
            }
        }
        __syncthreads();
    }

    if (Opart) {
        // unnormalized partial write + (m,sum)
        float* OP = Opart + (((long)sp * BT) + (long)b * TT + mt * 64) * DD + hh * DHH;
#pragma unroll
        for (int jd = 0; jd < 8; jd++) {
            int col = 8 * jd + 2 * tig;
            float2 v0 = { acc[jd][0], acc[jd][1] };
            float2 v1 = { acc[jd][2], acc[jd][3] };
            *(float2*)&OP[(long)(m0w + g) * DD + col] = v0;
            *(float2*)&OP[(long)(m0w + g + 8) * DD + col] = v1;
        }
        if (tig == 0) {
            long base = (((long)sp * BB + b) * HH + hh) * TT + mt * 64;
            Msum[base + m0w + g]     = make_float2(m0, sum0);
            Msum[base + m0w + g + 8] = make_float2(m1, sum1);
        }
    } else {
        float* O = Ob + ((long)b * TT + mt * 64) * DD + hh * DHH;
        float i0 = 1.f / sum0, i1 = 1.f / sum1;
#pragma unroll
        for (int jd = 0; jd < 8; jd++) {
            int col = 8 * jd + 2 * tig;
            float2 v0 = { acc[jd][0] * i0, acc[jd][1] * i0 };
            float2 v1 = { acc[jd][2] * i1, acc[jd][3] * i1 };
            *(float2*)&O[(long)(m0w + g) * DD + col] = v0;
            *(float2*)&O[(long)(m0w + g + 8) * DD + col] = v1;
        }
    }
}

// combine NSPLIT partial flash results
__global__ __launch_bounds__(256) void flash_merge_kernel(
    const float* __restrict__ Opart, const float2* __restrict__ Msum,
    float* __restrict__ O)
{
    __shared__ float wgt[HH][NSPLIT];
    int row = blockIdx.x;            // b*TT + t
    int b = row / TT, t = row % TT;
    int tid = threadIdx.x;
    if (tid < HH) {
        int h = tid;
        float ms[NSPLIT], ss[NSPLIT];
        float m = -1e30f;
#pragma unroll
        for (int s = 0; s < NSPLIT; s++) {
            float2 v = Msum[(((long)s * BB + b) * HH + h) * TT + t];
            ms[s] = v.x; ss[s] = v.y;
            m = fmaxf(m, v.x);
        }
        float den = 0.f;
#pragma unroll
        for (int s = 0; s < NSPLIT; s++) den += ss[s] * __expf(ms[s] - m);
        float iden = 1.f / den;
#pragma unroll
        for (int s = 0; s < NSPLIT; s++) wgt[h][s] = __expf(ms[s] - m) * iden;
    }
    __syncthreads();
#pragma unroll
    for (int it = 0; it < 3; it++) {
        int d = tid + it * 256;
        int h = d >> 6;
        float acc = 0.f;
#pragma unroll
        for (int s = 0; s < NSPLIT; s++)
            acc += Opart[(((long)s * BT) + row) * DD + d] * wgt[h][s];
        O[(long)row * DD + d] = acc;
    }
}

// ---------------- elementwise / row kernels ----------------
__global__ __launch_bounds__(256) void embed_kernel(
    const int* __restrict__ tokens, const float* __restrict__ tok_emb,
    const float* __restrict__ pos_emb, float* __restrict__ x)
{
    int row = blockIdx.x;
    int t = row % TT;
    int tok = tokens[row];
    const float* te = tok_emb + (long)tok * DD;
    const float* pe = pos_emb + (long)t * DD;
    float* xr = x + (long)row * DD;
#pragma unroll
    for (int it = 0; it < 3; it++) {
        int j = threadIdx.x + it * 256;
        xr[j] = te[j] + pe[j];
    }
}

__global__ __launch_bounds__(256) void ln_kernel(
    const float* __restrict__ x, float* __restrict__ y,
    const float* __restrict__ g, const float* __restrict__ b)
{
    __shared__ float red[256];
    int row = blockIdx.x;
    const float* xr = x + (long)row * DD;
    float* yr = y + (long)row * DD;
    int tid = threadIdx.x;
    float v0 = xr[tid], v1 = xr[tid + 256], v2 = xr[tid + 512];
    float s = v0 + v1 + v2;
    red[tid] = s; __syncthreads();
    for (int st = 128; st > 0; st >>= 1) { if (tid < st) red[tid] += red[tid + st]; __syncthreads(); }
    float mean = red[0] * (1.f / DD);
    __syncthreads();
    float d0 = v0 - mean, d1 = v1 - mean, d2 = v2 - mean;
    red[tid] = d0 * d0 + d1 * d1 + d2 * d2; __syncthreads();
    for (int st = 128; st > 0; st >>= 1) { if (tid < st) red[tid] += red[tid + st]; __syncthreads(); }
    float inv = rsqrtf(red[0] * (1.f / DD) + 1e-5f);
    yr[tid]       = d0 * inv * g[tid]       + b[tid];
    yr[tid + 256] = d1 * inv * g[tid + 256] + b[tid + 256];
    yr[tid + 512] = d2 * inv * g[tid + 512] + b[tid + 512];
}

// ---------------- host-side launch helpers ----------------
static GemmP base_p() {
    GemmP p;
    p.A = nullptr; p.B0 = p.B1 = p.B2 = nullptr;
    p.C0 = p.C1 = p.C2 = nullptr;
    p.bias0 = p.bias1 = p.bias2 = nullptr; p.res = nullptr; p.mir = nullptr;
    p.M = p.N = p.K = 0; p.lda = p.ldb = p.ldc = 0;
    p.Hd = 1; p.segW = 1 << 30; p.act = 0; p.splitK = 1; p.kc = 0;
    p.sA0 = p.sA1 = p.sB0 = p.sB1 = p.sC0 = p.sC1 = p.sBias = 0;
    p.s0 = p.s1 = p.s2 = 1.f;
    return p;
}

template <int NT>
static inline void launch_g(GemmP p, int batch, int splitK = 1) {
    p.splitK = splitK;
    int kc = (p.K + splitK - 1) / splitK;
    p.kc = ((kc + TBK - 1) / TBK) * TBK;
    dim3 grd((p.N + TBN - 1) / TBN, (p.M + TBM - 1) / TBM, batch * splitK);
    gemm_bf3_kernel<NT><<<grd, 256>>>(p);
}

extern "C" void kernel_launch(void* const* d_in, const int* in_sizes, int n_in,
                              void* d_out, int out_size)
{
    (void)in_sizes; (void)n_in; (void)out_size;

    const int*   tokens  = (const int*)  d_in[0];
    const float* xa      = (const float*)d_in[1];
    const float* tok_emb = (const float*)d_in[2];
    const float* pos_emb = (const float*)d_in[3];
    const float* Wq      = (const float*)d_in[4];
    const float* bq      = (const float*)d_in[5];
    const float* Wk      = (const float*)d_in[6];
    const float* Wv      = (const float*)d_in[7];
    const float* bv      = (const float*)d_in[8];
    const float* Wo      = (const float*)d_in[9];
    const float* bo      = (const float*)d_in[10];
    const float* ln1_g   = (const float*)d_in[11];
    const float* ln1_b   = (const float*)d_in[12];
    const float* Wcq     = (const float*)d_in[13];
    const float* bcq     = (const float*)d_in[14];
    const float* Wck     = (const float*)d_in[15];
    const float* Wcv     = (const float*)d_in[16];
    const float* bcv     = (const float*)d_in[17];
    const float* Wco     = (const float*)d_in[18];
    const float* bco     = (const float*)d_in[19];
    const float* ln2_g   = (const float*)d_in[20];
    const float* ln2_b   = (const float*)d_in[21];
    const float* W1      = (const float*)d_in[22];
    const float* b1      = (const float*)d_in[23];
    const float* W2      = (const float*)d_in[24];
    const float* b2      = (const float*)d_in[25];
    const float* ln3_g   = (const float*)d_in[26];
    const float* ln3_b   = (const float*)d_in[27];
    const float* lnf_g   = (const float*)d_in[28];
    const float* lnf_b   = (const float*)d_in[29];

    float* out = (float*)d_out;
    float* out_logits = out;
    float* out_chw    = out_logits + (size_t)BB * TT * VV;
    float* out_kv     = out_chw + (size_t)(LL / 2) * HH * TT * TAA;

    float *x, *h, *q, *o, *ckall, *cvall, *hid, *opart;
    float2* msum;
    cudaGetSymbolAddress((void**)&x,     g_x);
    cudaGetSymbolAddress((void**)&h,     g_h);
    cudaGetSymbolAddress((void**)&q,     g_q);
    cudaGetSymbolAddress((void**)&o,     g_o);
    cudaGetSymbolAddress((void**)&ckall, g_ckall);
    cudaGetSymbolAddress((void**)&cvall, g_cvall);
    cudaGetSymbolAddress((void**)&hid,   g_hid);
    cudaGetSymbolAddress((void**)&opart, g_opart);
    cudaGetSymbolAddress((void**)&msum,  g_msum);

    embed_kernel<<<BT, 256>>>(tokens, tok_emb, pos_emb, x);

    const long DTD = (long)TT * DD;
    const long TAD = (long)TAA * DD;
    const size_t XBYTES = (size_t)BT * DD * sizeof(float);
    const int KVCH = ((TAA + NSPLIT * 64 - 1) / (NSPLIT * 64)) * 64;   // 384

    // cross K/V for ALL layers, batched over z=12
    {
        GemmP p = base_p();
        p.A = xa; p.lda = DD;
        p.B0 = Wck; p.ldb = DD; p.sB1 = (long)DD * DD;
        p.C0 = ckall; p.ldc = DD; p.sC1 = (long)BTAD;
        p.M = BB * TAA; p.N = DD; p.K = DD; p.Hd = LL;
        launch_g<0>(p, LL);
        p.B0 = Wcv; p.C0 = cvall;
        p.bias0 = bcv; p.sBias = DD;
        launch_g<0>(p, LL);
    }

    for (int l = 0; l < LL; l++) {
        const float* Wq_l = Wq + (size_t)l * DD * DD;
        const float* Wk_l = Wk + (size_t)l * DD * DD;
        const float* Wv_l = Wv + (size_t)l * DD * DD;
        const float* Wo_l = Wo + (size_t)l * DD * DD;
        const float* Wcq_l = Wcq + (size_t)l * DD * DD;
        const float* Wco_l = Wco + (size_t)l * DD * DD;
        const float* W1_l = W1 + (size_t)l * DD * 4 * DD;
        const float* W2_l = W2 + (size_t)l * 4 * DD * DD;

        float* kout = out_kv + (size_t)(2 * l) * BT * DD;
        float* vout = out_kv + (size_t)(2 * l + 1) * BT * DD;
        float* ck_l = ckall + (size_t)l * BTAD;
        float* cv_l = cvall + (size_t)l * BTAD;

        // ---- self attention ----
        ln_kernel<<<BT, 256>>>(x, h, ln1_g + l * DD, ln1_b + l * DD);
        {   // fused QKV
            GemmP p = base_p();
            p.A = h; p.lda = DD;
            p.B0 = Wq_l; p.B1 = Wk_l; p.B2 = Wv_l; p.ldb = DD;
            p.C0 = q; p.C1 = kout; p.C2 = vout; p.ldc = DD;
            p.bias0 = bq + l * DD; p.bias1 = nullptr; p.bias2 = bv + l * DD;
            p.s0 = SCALE_Q; p.s1 = 1.f; p.s2 = 1.f;
            p.segW = DD;
            p.M = BT; p.N = 3 * DD; p.K = DD;
            launch_g<0>(p, 1);
        }
        flash_kernel<<<dim3(TT / 64, BB * HH, 1), 128>>>(
            q, kout, vout, o, nullptr, TT, DTD, 1, nullptr, nullptr, TT);
        {   // x += o @ Wo + bo
            GemmP p = base_p();
            p.A = o; p.lda = DD;
            p.B0 = Wo_l; p.ldb = DD;
            p.C0 = x; p.ldc = DD;
            p.bias0 = bo + l * DD;
            p.M = BT; p.N = DD; p.K = DD;
            launch_g<0>(p, 1, 4);
        }

        // ---- cross attention ----
        ln_kernel<<<BT, 256>>>(x, h, ln2_g + l * DD, ln2_b + l * DD);
        cudaMemsetAsync(q, 0, XBYTES);
        {   // q2 (split-K 4)
            GemmP p = base_p();
            p.A = h; p.lda = DD;
            p.B0 = Wcq_l; p.ldb = DD;
            p.C0 = q; p.ldc = DD;
            p.bias0 = bcq + l * DD; p.s0 = SCALE_Q;
            p.M = BT; p.N = DD; p.K = DD;
            launch_g<0>(p, 1, 4);
        }
        {
            float* mir = (l >= LL / 2)
                       ? out_chw + (size_t)(l - LL / 2) * HH * TT * TAA : nullptr;
            flash_kernel<<<dim3(TT / 64, BB * HH, NSPLIT), 128>>>(
                q, ck_l, cv_l, nullptr, mir, TAA, TAD, 0, opart, msum, KVCH);
            flash_merge_kernel<<<BT, 256>>>(opart, msum, o);
        }
        {   // x += o @ Wco + bco
            GemmP p = base_p();
            p.A = o; p.lda = DD;
            p.B0 = Wco_l; p.ldb = DD;
            p.C0 = x; p.ldc = DD;
            p.bias0 = bco + l * DD;
            p.M = BT; p.N = DD; p.K = DD;
            launch_g<0>(p, 1, 4);
        }

        // ---- MLP ----
        ln_kernel<<<BT, 256>>>(x, h, ln3_g + l * DD, ln3_b + l * DD);
        {
            GemmP p = base_p();
            p.A = h; p.lda = DD;
            p.B0 = W1_l; p.ldb = 4 * DD;
            p.C0 = hid; p.ldc = 4 * DD;
            p.bias0 = b1 + (size_t)l * 4 * DD; p.act = 1;
            p.M = BT; p.N = 4 * DD; p.K = DD;
            launch_g<0>(p, 1);
        }
        {
            GemmP p = base_p();
            p.A = hid; p.lda = 4 * DD;
            p.B0 = W2_l; p.ldb = DD;
            p.C0 = x; p.ldc = DD;
            p.bias0 = b2 + l * DD;
            p.M = BT; p.N = DD; p.K = 4 * DD;
            launch_g<0>(p, 1, 8);
        }
    }

    // final LN + tied-embedding logits
    ln_kernel<<<BT, 256>>>(x, h, lnf_g, lnf_b);
    {
        GemmP p = base_p();
        p.A = h; p.lda = DD;
        p.B0 = tok_emb; p.ldb = DD;
        p.C0 = out_logits; p.ldc = VV;
        p.M = BT; p.N = VV; p.K = DD;
        launch_g<1>(p, 1);
    }
}

// round 9
// speedup vs baseline: 3.2631x; 1.0518x over previous
#include <cuda_runtime.h>
#include <cuda_bf16.h>
#include <math.h>
#include <stdint.h>

// ---------------- problem constants ----------------
#define BB   4
#define TT   256
#define TAA  1500
#define DD   768
#define HH   12
#define LL   12
#define VV   51865
#define DHH  64
#define BT   (BB*TT)          // 1024
#define SCALE_Q 0.125f
#define BTAD ((size_t)BB*TAA*DD)
#define NSPLIT 4

// ---------------- scratch ----------------
__device__ float g_x  [BT*DD];
__device__ float g_h  [BT*DD];
__device__ float g_q  [BT*DD];
__device__ float g_o  [BT*DD];
__device__ float g_ckall[(size_t)LL*BTAD];
__device__ float g_cvall[(size_t)LL*BTAD];
__device__ float g_hid[(size_t)BT*4*DD];
__device__ float g_opart[(size_t)NSPLIT*BT*DD];
__device__ float2 g_msum[(size_t)NSPLIT*BB*HH*TT];

// ---------------- shared helpers ----------------
__device__ __forceinline__ uint32_t pack_bf(float a, float b) {
    __nv_bfloat162 t;
    t.x = __float2bfloat16_rn(a);
    t.y = __float2bfloat16_rn(b);
    return *(uint32_t*)&t;
}

__device__ __forceinline__ void split_pair(float2 v, uint32_t& hi, uint32_t& lo) {
    __nv_bfloat16 hx = __float2bfloat16_rn(v.x);
    __nv_bfloat16 hy = __float2bfloat16_rn(v.y);
    hi = pack_bf(v.x, v.y);
    lo = pack_bf(v.x - __bfloat162float(hx), v.y - __bfloat162float(hy));
}

__device__ __forceinline__ uint32_t lo_pack(float a, float b) {
    float ra = a - __bfloat162float(__float2bfloat16_rn(a));
    float rb = b - __bfloat162float(__float2bfloat16_rn(b));
    return pack_bf(ra, rb);
}

__device__ __forceinline__ void mma_bf16(float* c, const uint32_t* a, const uint32_t* b) {
    asm volatile(
        "mma.sync.aligned.m16n8k16.row.col.f32.bf16.bf16.f32 "
        "{%0,%1,%2,%3}, {%4,%5,%6,%7}, {%8,%9}, {%0,%1,%2,%3};"
        : "+f"(c[0]), "+f"(c[1]), "+f"(c[2]), "+f"(c[3])
        : "r"(a[0]), "r"(a[1]), "r"(a[2]), "r"(a[3]), "r"(b[0]), "r"(b[1]));
}

// ---------------- bf16 split GEMM (3-term) + split-K ----------------
// BIG=0: 128x64 tile, 256 thr (8 warps 4x2). BIG=1: 128x128 tile, 512 thr (16 warps 4x4).
// Warp tile 32x32 in both. K chunk 32.
#define TBK 32

struct GemmP {
    const float *A, *B0, *B1, *B2;
    float *C0, *C1, *C2;
    const float *bias0, *bias1, *bias2;
    int M, N, K, lda, ldb, ldc, Hd, segW, act, splitK, kc;
    long sA0, sA1, sB0, sB1, sC0, sC1, sBias;
    float s0, s1, s2;
};

template <int NT, int BIG>
__global__ __launch_bounds__(BIG ? 512 : 256, BIG ? 1 : 2) void gemm_bf3_kernel(GemmP p)
{
    constexpr int BN   = BIG ? 128 : 64;
    constexpr int NTHR = BIG ? 512 : 256;
    constexpr int AIT  = 2048 / NTHR;        // A pairs per thread
    constexpr int BIT  = (BN * 16) / NTHR;   // 4
    constexpr int BLDN = BIG ? 136 : 72;     // NN layout stride
    constexpr int BSZ  = BIG ? 2560 : 1280;

    __shared__ uint32_t AH[128][20];
    __shared__ uint32_t AL[128][20];
    __shared__ uint32_t BH[BSZ];
    __shared__ uint32_t BL[BSZ];

    int z = blockIdx.z;
    int sk = z % p.splitK;
    int zz = z / p.splitK;
    int zb = zz / p.Hd, zh = zz % p.Hd;
    int bm = blockIdx.y * 128, bn = blockIdx.x * BN;
    int seg = bn / p.segW;
    int bnl = bn - seg * p.segW;

    const float* A = p.A + zb * p.sA0 + zh * p.sA1;
    const float* B = (seg == 0 ? p.B0 : seg == 1 ? p.B1 : p.B2) + zb * p.sB0 + zh * p.sB1;
    float* C = (seg == 0 ? p.C0 : seg == 1 ? p.C1 : p.C2) + zb * p.sC0 + zh * p.sC1;
    const float* bias = (seg == 0 ? p.bias0 : seg == 1 ? p.bias1 : p.bias2);
    if (bias) bias += zh * p.sBias;
    float scl = seg == 0 ? p.s0 : seg == 1 ? p.s1 : p.s2;
    bool atom = p.splitK > 1;

    int M = p.M, N = p.N;
    int lda = p.lda, ldb = p.ldb, ldc = p.ldc;
    int kstart = sk * p.kc;
    int kend = min(p.K, kstart + p.kc);

    int tid  = threadIdx.x;
    int lane = tid & 31;
    int warp = tid >> 5;
    int g    = lane >> 2;
    int tig  = lane & 3;
    int m0w  = (warp & 3) * 32;
    int n0w  = (warp >> 2) * 32;

    float c[2][4][4];
#pragma unroll
    for (int mi = 0; mi < 2; mi++)
#pragma unroll
        for (int ni = 0; ni < 4; ni++)
#pragma unroll
            for (int e = 0; e < 4; e++) c[mi][ni][e] = 0.f;

    int iters = (kend - kstart + TBK - 1) / TBK;
    float2 ra[AIT], rb[BIT];

    // --- prefetch tile 0 ---
    {
        int kk = kstart;
#pragma unroll
        for (int i = 0; i < AIT; i++) {
            int pidx = i * NTHR + tid;
            int r = pidx >> 4, kp = pidx & 15;
            int gr = bm + r, k0 = kk + 2 * kp;
            float2 v = {0.f, 0.f};
            if (gr < M) {
                if (k0 + 1 < kend)      v = *(const float2*)&A[(long)gr * lda + k0];
                else if (k0 < kend)     v.x = A[(long)gr * lda + k0];
            }
            ra[i] = v;
        }
#pragma unroll
        for (int i = 0; i < BIT; i++) {
            int pidx = i * NTHR + tid;
            float2 v = {0.f, 0.f};
            if (NT) {
                int n = pidx >> 4, kp = pidx & 15;
                int k0 = kk + 2 * kp;
                if (bn + n < N) {
                    long base = (long)(bnl + n) * ldb;
                    if (k0 + 1 < kend)  v = *(const float2*)&B[base + k0];
                    else if (k0 < kend) v.x = B[base + k0];
                }
            } else {
                int n = pidx & (BN - 1), kp = pidx / BN;
                int k0 = kk + 2 * kp;
                if (bn + n < N) {
                    if (k0 < kend)     v.x = B[(long)k0 * ldb + bnl + n];
                    if (k0 + 1 < kend) v.y = B[(long)(k0 + 1) * ldb + bnl + n];
                }
            }
            rb[i] = v;
        }
    }

    for (int it = 0; it < iters; it++) {
#pragma unroll
        for (int i = 0; i < AIT; i++) {
            int pidx = i * NTHR + tid;
            int r = pidx >> 4, kp = pidx & 15;
            split_pair(ra[i], AH[r][kp], AL[r][kp]);
        }
#pragma unroll
        for (int i = 0; i < BIT; i++) {
            int pidx = i * NTHR + tid;
            uint32_t hi, lo;
            split_pair(rb[i], hi, lo);
            if (NT) {
                int n = pidx >> 4, kp = pidx & 15;
                BH[n * 20 + kp] = hi;
                BL[n * 20 + kp] = lo;
            } else {
                int n = pidx & (BN - 1), kp = pidx / BN;
                BH[kp * BLDN + n] = hi;
                BL[kp * BLDN + n] = lo;
            }
        }
        __syncthreads();

        if (it + 1 < iters) {
            int kk = kstart + (it + 1) * TBK;
#pragma unroll
            for (int i = 0; i < AIT; i++) {
                int pidx = i * NTHR + tid;
                int r = pidx >> 4, kp = pidx & 15;
                int gr = bm + r, k0 = kk + 2 * kp;
                float2 v = {0.f, 0.f};
                if (gr < M) {
                    if (k0 + 1 < kend)  v = *(const float2*)&A[(long)gr * lda + k0];
                    else if (k0 < kend) v.x = A[(long)gr * lda + k0];
                }
                ra[i] = v;
            }
#pragma unroll
            for (int i = 0; i < BIT; i++) {
                int pidx = i * NTHR + tid;
                float2 v = {0.f, 0.f};
                if (NT) {
                    int n = pidx >> 4, kp = pidx & 15;
                    int k0 = kk + 2 * kp;
                    if (bn + n < N) {
                        long base = (long)(bnl + n) * ldb;
                        if (k0 + 1 < kend)  v = *(const float2*)&B[base + k0];
                        else if (k0 < kend) v.x = B[base + k0];
                    }
                } else {
                    int n = pidx & (BN - 1), kp = pidx / BN;
                    int k0 = kk + 2 * kp;
                    if (bn + n < N) {
                        if (k0 < kend)     v.x = B[(long)k0 * ldb + bnl + n];
                        if (k0 + 1 < kend) v.y = B[(long)(k0 + 1) * ldb + bnl + n];
                    }
                }
                rb[i] = v;
            }
        }

#pragma unroll
        for (int h = 0; h < 2; h++) {
            int kb = h * 8;
            uint32_t aH4[2][4], aL4[2][4];
#pragma unroll
            for (int mi = 0; mi < 2; mi++) {
                int m = m0w + mi * 16 + g;
                aH4[mi][0] = AH[m    ][kb + tig];
                aH4[mi][1] = AH[m + 8][kb + tig];
                aH4[mi][2] = AH[m    ][kb + tig + 4];
                aH4[mi][3] = AH[m + 8][kb + tig + 4];
                aL4[mi][0] = AL[m    ][kb + tig];
                aL4[mi][1] = AL[m + 8][kb + tig];
                aL4[mi][2] = AL[m    ][kb + tig + 4];
                aL4[mi][3] = AL[m + 8][kb + tig + 4];
            }
            uint32_t bh2[4][2], bl2[4][2];
#pragma unroll
            for (int ni = 0; ni < 4; ni++) {
                int n = n0w + ni * 8 + g;
                if (NT) {
                    bh2[ni][0] = BH[n * 20 + kb + tig];
                    bh2[ni][1] = BH[n * 20 + kb + tig + 4];
                    bl2[ni][0] = BL[n * 20 + kb + tig];
                    bl2[ni][1] = BL[n * 20 + kb + tig + 4];
                } else {
                    bh2[ni][0] = BH[(kb + tig) * BLDN + n];
                    bh2[ni][1] = BH[(kb + tig + 4) * BLDN + n];
                    bl2[ni][0] = BL[(kb + tig) * BLDN + n];
                    bl2[ni][1] = BL[(kb + tig + 4) * BLDN + n];
                }
            }
#pragma unroll
            for (int mi = 0; mi < 2; mi++)
#pragma unroll
                for (int ni = 0; ni < 4; ni++) {
                    mma_bf16(c[mi][ni], aH4[mi], bl2[ni]);
                    mma_bf16(c[mi][ni], aL4[mi], bh2[ni]);
                    mma_bf16(c[mi][ni], aH4[mi], bh2[ni]);
                }
        }
        __syncthreads();
    }

#pragma unroll
    for (int mi = 0; mi < 2; mi++) {
#pragma unroll
        for (int ni = 0; ni < 4; ni++) {
#pragma unroll
            for (int e = 0; e < 4; e++) {
                int row = bm + m0w + mi * 16 + g + ((e >= 2) ? 8 : 0);
                int gcol = bn + n0w + ni * 8 + tig * 2 + (e & 1);
                if (row >= M || gcol >= N) continue;
                int lc = gcol - seg * p.segW;
                float v = c[mi][ni][e];
                if (bias && (!atom || sk == 0)) v += bias[lc];
                v *= scl;
                long ci = (long)row * ldc + lc;
                if (atom) {
                    atomicAdd(&C[ci], v);
                } else {
                    if (p.act == 1) v = 0.5f * v * (1.f + erff(v * 0.70710678118654752f));
                    C[ci] = v;
                }
            }
        }
    }
}

// ---------------- fused flash attention (optionally KV-split) ----------------
__global__ __launch_bounds__(128) void flash_kernel(
    const float* __restrict__ Qb, const float* __restrict__ Kb,
    const float* __restrict__ Vb, float* __restrict__ Ob,
    float* __restrict__ mir, int lenKV, long kvBStride, int causal,
    float* __restrict__ Opart, float2* __restrict__ Msum, int kvChunk)
{
    __shared__ uint32_t Kh[64][36], Kl[64][36];
    __shared__ uint32_t Vh[64][33], Vl[64][33];

    int mt = blockIdx.x;
    int by = blockIdx.y;
    int sp = blockIdx.z;
    int b = by / HH, hh = by % HH;

    int kvStart = sp * kvChunk;
    int kvEnd = min(lenKV, kvStart + kvChunk);

    const float* Q = Qb + ((long)b * TT + mt * 64) * DD + hh * DHH;
    const float* K = Kb + (long)b * kvBStride + hh * DHH;
    const float* V = Vb + (long)b * kvBStride + hh * DHH;
    float* Mr = (mir && b == 0)
              ? mir + (size_t)hh * TT * TAA + (size_t)mt * 64 * TAA : nullptr;

    int tid = threadIdx.x;
    int lane = tid & 31, warp = tid >> 5;
    int g = lane >> 2, tig = lane & 3;
    int m0w = warp * 16;

    uint32_t Qah[4][4], Qal[4][4];
#pragma unroll
    for (int kb = 0; kb < 4; kb++) {
        int c0 = 16 * kb + 2 * tig;
        const float* r0 = Q + (long)(m0w + g) * DD;
        const float* r1 = Q + (long)(m0w + g + 8) * DD;
        float2 v;
        v = *(const float2*)(r0 + c0);     split_pair(v, Qah[kb][0], Qal[kb][0]);
        v = *(const float2*)(r1 + c0);     split_pair(v, Qah[kb][1], Qal[kb][1]);
        v = *(const float2*)(r0 + c0 + 8); split_pair(v, Qah[kb][2], Qal[kb][2]);
        v = *(const float2*)(r1 + c0 + 8); split_pair(v, Qah[kb][3], Qal[kb][3]);
    }

    float acc[8][4];
#pragma unroll
    for (int j = 0; j < 8; j++)
#pragma unroll
        for (int e = 0; e < 4; e++) acc[j][e] = 0.f;
    float m0 = -1e30f, m1 = -1e30f, sum0 = 0.f, sum1 = 0.f;

    int chBeg = kvStart >> 6;
    int chEnd = (kvEnd + 63) >> 6;
    if (causal) chEnd = min(chEnd, mt + 1);

    for (int ch = chBeg; ch < chEnd; ch++) {
        int n0 = ch * 64;
#pragma unroll
        for (int i = 0; i < 16; i++) {
            int idx = i * 128 + tid;
            int r = idx >> 5, c = idx & 31;
            float2 v = {0.f, 0.f};
            if (n0 + r < kvEnd) v = *(const float2*)(K + (long)(n0 + r) * DD + 2 * c);
            split_pair(v, Kh[r][c], Kl[r][c]);
        }
#pragma unroll
        for (int i = 0; i < 16; i++) {
            int idx = i * 128 + tid;
            int d = idx & 63, pr = idx >> 6;
            float2 v = {0.f, 0.f};
            int r0i = n0 + 2 * pr;
            if (r0i < kvEnd)     v.x = V[(long)r0i * DD + d];
            if (r0i + 1 < kvEnd) v.y = V[(long)(r0i + 1) * DD + d];
            split_pair(v, Vh[d][pr], Vl[d][pr]);
        }
        __syncthreads();

        float s[8][4];
#pragma unroll
        for (int j = 0; j < 8; j++)
#pragma unroll
            for (int e = 0; e < 4; e++) s[j][e] = 0.f;
#pragma unroll
        for (int kb = 0; kb < 4; kb++) {
#pragma unroll
            for (int j = 0; j < 8; j++) {
                uint32_t bh[2] = { Kh[8 * j + g][8 * kb + tig], Kh[8 * j + g][8 * kb + tig + 4] };
                uint32_t bl[2] = { Kl[8 * j + g][8 * kb + tig], Kl[8 * j + g][8 * kb + tig + 4] };
                mma_bf16(s[j], Qah[kb], bl);
                mma_bf16(s[j], Qal[kb], bh);
                mma_bf16(s[j], Qah[kb], bh);
            }
        }

        if (Mr) {
#pragma unroll
            for (int j = 0; j < 8; j++) {
                int col = n0 + 8 * j + 2 * tig;
                if (col < kvEnd) {
                    float2 v0 = { s[j][0], s[j][1] };
                    float2 v1 = { s[j][2], s[j][3] };
                    *(float2*)&Mr[(long)(m0w + g) * TAA + col] = v0;
                    *(float2*)&Mr[(long)(m0w + g + 8) * TAA + col] = v1;
                }
            }
        }

        if (causal && ch == mt) {
            int t0 = mt * 64 + m0w + g;
#pragma unroll
            for (int j = 0; j < 8; j++) {
                int col = n0 + 8 * j + 2 * tig;
                if (col     > t0)     s[j][0] = -1e30f;
                if (col + 1 > t0)     s[j][1] = -1e30f;
                if (col     > t0 + 8) s[j][2] = -1e30f;
                if (col + 1 > t0 + 8) s[j][3] = -1e30f;
            }
        }
        if (n0 + 64 > kvEnd) {
#pragma unroll
            for (int j = 0; j < 8; j++) {
                int col = n0 + 8 * j + 2 * tig;
                if (col     >= kvEnd) { s[j][0] = -1e30f; s[j][2] = -1e30f; }
                if (col + 1 >= kvEnd) { s[j][1] = -1e30f; s[j][3] = -1e30f; }
            }
        }

        float mx0 = -1e30f, mx1 = -1e30f;
#pragma unroll
        for (int j = 0; j < 8; j++) {
            mx0 = fmaxf(mx0, fmaxf(s[j][0], s[j][1]));
            mx1 = fmaxf(mx1, fmaxf(s[j][2], s[j][3]));
        }
        mx0 = fmaxf(mx0, __shfl_xor_sync(0xffffffffu, mx0, 1));
        mx0 = fmaxf(mx0, __shfl_xor_sync(0xffffffffu, mx0, 2));
        mx1 = fmaxf(mx1, __shfl_xor_sync(0xffffffffu, mx1, 1));
        mx1 = fmaxf(mx1, __shfl_xor_sync(0xffffffffu, mx1, 2));
        float mn0 = fmaxf(m0, mx0), mn1 = fmaxf(m1, mx1);
        float a0 = __expf(m0 - mn0), a1 = __expf(m1 - mn1);
        float ps0 = 0.f, ps1 = 0.f;
#pragma unroll
        for (int j = 0; j < 8; j++) {
            s[j][0] = __expf(s[j][0] - mn0);
            s[j][1] = __expf(s[j][1] - mn0);
            s[j][2] = __expf(s[j][2] - mn1);
            s[j][3] = __expf(s[j][3] - mn1);
            ps0 += s[j][0] + s[j][1];
            ps1 += s[j][2] + s[j][3];
        }
        ps0 += __shfl_xor_sync(0xffffffffu, ps0, 1);
        ps0 += __shfl_xor_sync(0xffffffffu, ps0, 2);
        ps1 += __shfl_xor_sync(0xffffffffu, ps1, 1);
        ps1 += __shfl_xor_sync(0xffffffffu, ps1, 2);
        sum0 = sum0 * a0 + ps0;
        sum1 = sum1 * a1 + ps1;
        m0 = mn0; m1 = mn1;
#pragma unroll
        for (int j = 0; j < 8; j++) {
            acc[j][0] *= a0; acc[j][1] *= a0;
            acc[j][2] *= a1; acc[j][3] *= a1;
        }

#pragma unroll
        for (int kb = 0; kb < 4; kb++) {
            int j0 = 2 * kb, j1 = 2 * kb + 1;
            uint32_t Ah[4], Al[4];
            Ah[0] = pack_bf(s[j0][0], s[j0][1]);  Al[0] = lo_pack(s[j0][0], s[j0][1]);
            Ah[1] = pack_bf(s[j0][2], s[j0][3]);  Al[1] = lo_pack(s[j0][2], s[j0][3]);
            Ah[2] = pack_bf(s[j1][0], s[j1][1]);  Al[2] = lo_pack(s[j1][0], s[j1][1]);
            Ah[3] = pack_bf(s[j1][2], s[j1][3]);  Al[3] = lo_pack(s[j1][2], s[j1][3]);
#pragma unroll
            for (int jd = 0; jd < 8; jd++) {
                uint32_t bh[2] = { Vh[8 * jd + g][8 * kb + tig], Vh[8 * jd + g][8 * kb + tig + 4] };
                uint32_t bl[2] = { Vl[8 * jd + g][8 * kb + tig], Vl[8 * jd + g][8 * kb + tig + 4] };
                mma_bf16(acc[jd], Ah, bl);
                mma_bf16(acc[jd], Al, bh);
                mma_bf16(acc[jd], Ah, bh);
            }
        }
        __syncthreads();
    }

    if (Opart) {
        float* OP = Opart + (((long)sp * BT) + (long)b * TT + mt * 64) * DD + hh * DHH;
#pragma unroll
        for (int jd = 0; jd < 8; jd++) {
            int col = 8 * jd + 2 * tig;
            float2 v0 = { acc[jd][0], acc[jd][1] };
            float2 v1 = { acc[jd][2], acc[jd][3] };
            *(float2*)&OP[(long)(m0w + g) * DD + col] = v0;
            *(float2*)&OP[(long)(m0w + g + 8) * DD + col] = v1;
        }
        if (tig == 0) {
            long base = (((long)sp * BB + b) * HH + hh) * TT + mt * 64;
            Msum[base + m0w + g]     = make_float2(m0, sum0);
            Msum[base + m0w + g + 8] = make_float2(m1, sum1);
        }
    } else {
        float* O = Ob + ((long)b * TT + mt * 64) * DD + hh * DHH;
        float i0 = 1.f / sum0, i1 = 1.f / sum1;
#pragma unroll
        for (int jd = 0; jd < 8; jd++) {
            int col = 8 * jd + 2 * tig;
            float2 v0 = { acc[jd][0] * i0, acc[jd][1] * i0 };
            float2 v1 = { acc[jd][2] * i1, acc[jd][3] * i1 };
            *(float2*)&O[(long)(m0w + g) * DD + col] = v0;
            *(float2*)&O[(long)(m0w + g + 8) * DD + col] = v1;
        }
    }
}

__global__ __launch_bounds__(256) void flash_merge_kernel(
    const float* __restrict__ Opart, const float2* __restrict__ Msum,
    float* __restrict__ O)
{
    __shared__ float wgt[HH][NSPLIT];
    int row = blockIdx.x;
    int b = row / TT, t = row % TT;
    int tid = threadIdx.x;
    if (tid < HH) {
        int h = tid;
        float ms[NSPLIT], ss[NSPLIT];
        float m = -1e30f;
#pragma unroll
        for (int s = 0; s < NSPLIT; s++) {
            float2 v = Msum[(((long)s * BB + b) * HH + h) * TT + t];
            ms[s] = v.x; ss[s] = v.y;
            m = fmaxf(m, v.x);
        }
        float den = 0.f;
#pragma unroll
        for (int s = 0; s < NSPLIT; s++) den += ss[s] * __expf(ms[s] - m);
        float iden = 1.f / den;
#pragma unroll
        for (int s = 0; s < NSPLIT; s++) wgt[h][s] = __expf(ms[s] - m) * iden;
    }
    __syncthreads();
#pragma unroll
    for (int it = 0; it < 3; it++) {
        int d = tid + it * 256;
        int h = d >> 6;
        float acc = 0.f;
#pragma unroll
        for (int s = 0; s < NSPLIT; s++)
            acc += Opart[(((long)s * BT) + row) * DD + d] * wgt[h][s];
        O[(long)row * DD + d] = acc;
    }
}

// ---------------- elementwise / row kernels ----------------
__global__ __launch_bounds__(256) void embed_kernel(
    const int* __restrict__ tokens, const float* __restrict__ tok_emb,
    const float* __restrict__ pos_emb, float* __restrict__ x)
{
    int row = blockIdx.x;
    int t = row % TT;
    int tok = tokens[row];
    const float* te = tok_emb + (long)tok * DD;
    const float* pe = pos_emb + (long)t * DD;
    float* xr = x + (long)row * DD;
#pragma unroll
    for (int it = 0; it < 3; it++) {
        int j = threadIdx.x + it * 256;
        xr[j] = te[j] + pe[j];
    }
}

__global__ __launch_bounds__(256) void ln_kernel(
    const float* __restrict__ x, float* __restrict__ y,
    const float* __restrict__ g, const float* __restrict__ b)
{
    __shared__ float red[256];
    int row = blockIdx.x;
    const float* xr = x + (long)row * DD;
    float* yr = y + (long)row * DD;
    int tid = threadIdx.x;
    float v0 = xr[tid], v1 = xr[tid + 256], v2 = xr[tid + 512];
    float s = v0 + v1 + v2;
    red[tid] = s; __syncthreads();
    for (int st = 128; st > 0; st >>= 1) { if (tid < st) red[tid] += red[tid + st]; __syncthreads(); }
    float mean = red[0] * (1.f / DD);
    __syncthreads();
    float d0 = v0 - mean, d1 = v1 - mean, d2 = v2 - mean;
    red[tid] = d0 * d0 + d1 * d1 + d2 * d2; __syncthreads();
    for (int st = 128; st > 0; st >>= 1) { if (tid < st) red[tid] += red[tid + st]; __syncthreads(); }
    float inv = rsqrtf(red[0] * (1.f / DD) + 1e-5f);
    yr[tid]       = d0 * inv * g[tid]       + b[tid];
    yr[tid + 256] = d1 * inv * g[tid + 256] + b[tid + 256];
    yr[tid + 512] = d2 * inv * g[tid + 512] + b[tid + 512];
}

// ---------------- host-side launch helpers ----------------
static GemmP base_p() {
    GemmP p;
    p.A = nullptr; p.B0 = p.B1 = p.B2 = nullptr;
    p.C0 = p.C1 = p.C2 = nullptr;
    p.bias0 = p.bias1 = p.bias2 = nullptr;
    p.M = p.N = p.K = 0; p.lda = p.ldb = p.ldc = 0;
    p.Hd = 1; p.segW = 1 << 30; p.act = 0; p.splitK = 1; p.kc = 0;
    p.sA0 = p.sA1 = p.sB0 = p.sB1 = p.sC0 = p.sC1 = p.sBias = 0;
    p.s0 = p.s1 = p.s2 = 1.f;
    return p;
}

template <int NT, int BIG>
static inline void launch_g(GemmP p, int batch, int splitK = 1) {
    p.splitK = splitK;
    int kc = (p.K + splitK - 1) / splitK;
    p.kc = ((kc + TBK - 1) / TBK) * TBK;
    constexpr int BN = BIG ? 128 : 64;
    constexpr int NTHR = BIG ? 512 : 256;
    dim3 grd((p.N + BN - 1) / BN, (p.M + 127) / 128, batch * splitK);
    gemm_bf3_kernel<NT, BIG><<<grd, NTHR>>>(p);
}

extern "C" void kernel_launch(void* const* d_in, const int* in_sizes, int n_in,
                              void* d_out, int out_size)
{
    (void)in_sizes; (void)n_in; (void)out_size;

    const int*   tokens  = (const int*)  d_in[0];
    const float* xa      = (const float*)d_in[1];
    const float* tok_emb = (const float*)d_in[2];
    const float* pos_emb = (const float*)d_in[3];
    const float* Wq      = (const float*)d_in[4];
    const float* bq      = (const float*)d_in[5];
    const float* Wk      = (const float*)d_in[6];
    const float* Wv      = (const float*)d_in[7];
    const float* bv      = (const float*)d_in[8];
    const float* Wo      = (const float*)d_in[9];
    const float* bo      = (const float*)d_in[10];
    const float* ln1_g   = (const float*)d_in[11];
    const float* ln1_b   = (const float*)d_in[12];
    const float* Wcq     = (const float*)d_in[13];
    const float* bcq     = (const float*)d_in[14];
    const float* Wck     = (const float*)d_in[15];
    const float* Wcv     = (const float*)d_in[16];
    const float* bcv     = (const float*)d_in[17];
    const float* Wco     = (const float*)d_in[18];
    const float* bco     = (const float*)d_in[19];
    const float* ln2_g   = (const float*)d_in[20];
    const float* ln2_b   = (const float*)d_in[21];
    const float* W1      = (const float*)d_in[22];
    const float* b1      = (const float*)d_in[23];
    const float* W2      = (const float*)d_in[24];
    const float* b2      = (const float*)d_in[25];
    const float* ln3_g   = (const float*)d_in[26];
    const float* ln3_b   = (const float*)d_in[27];
    const float* lnf_g   = (const float*)d_in[28];
    const float* lnf_b   = (const float*)d_in[29];

    float* out = (float*)d_out;
    float* out_logits = out;
    float* out_chw    = out_logits + (size_t)BB * TT * VV;
    float* out_kv     = out_chw + (size_t)(LL / 2) * HH * TT * TAA;

    float *x, *h, *q, *o, *ckall, *cvall, *hid, *opart;
    float2* msum;
    cudaGetSymbolAddress((void**)&x,     g_x);
    cudaGetSymbolAddress((void**)&h,     g_h);
    cudaGetSymbolAddress((void**)&q,     g_q);
    cudaGetSymbolAddress((void**)&o,     g_o);
    cudaGetSymbolAddress((void**)&ckall, g_ckall);
    cudaGetSymbolAddress((void**)&cvall, g_cvall);
    cudaGetSymbolAddress((void**)&hid,   g_hid);
    cudaGetSymbolAddress((void**)&opart, g_opart);
    cudaGetSymbolAddress((void**)&msum,  g_msum);

    embed_kernel<<<BT, 256>>>(tokens, tok_emb, pos_emb, x);

    const long DTD = (long)TT * DD;
    const long TAD = (long)TAA * DD;
    const size_t XBYTES = (size_t)BT * DD * sizeof(float);
    const int KVCH = ((TAA + NSPLIT * 64 - 1) / (NSPLIT * 64)) * 64;   // 384

    // cross K/V for ALL layers, batched over z=12 (BIG tiles)
    {
        GemmP p = base_p();
        p.A = xa; p.lda = DD;
        p.B0 = Wck; p.ldb = DD; p.sB1 = (long)DD * DD;
        p.C0 = ckall; p.ldc = DD; p.sC1 = (long)BTAD;
        p.M = BB * TAA; p.N = DD; p.K = DD; p.Hd = LL;
        launch_g<0, 1>(p, LL);
        p.B0 = Wcv; p.C0 = cvall;
        p.bias0 = bcv; p.sBias = DD;
        launch_g<0, 1>(p, LL);
    }

    for (int l = 0; l < LL; l++) {
        const float* Wq_l = Wq + (size_t)l * DD * DD;
        const float* Wk_l = Wk + (size_t)l * DD * DD;
        const float* Wv_l = Wv + (size_t)l * DD * DD;
        const float* Wo_l = Wo + (size_t)l * DD * DD;
        const float* Wcq_l = Wcq + (size_t)l * DD * DD;
        const float* Wco_l = Wco + (size_t)l * DD * DD;
        const float* W1_l = W1 + (size_t)l * DD * 4 * DD;
        const float* W2_l = W2 + (size_t)l * 4 * DD * DD;

        float* kout = out_kv + (size_t)(2 * l) * BT * DD;
        float* vout = out_kv + (size_t)(2 * l + 1) * BT * DD;
        float* ck_l = ckall + (size_t)l * BTAD;
        float* cv_l = cvall + (size_t)l * BTAD;

        // ---- self attention ----
        ln_kernel<<<BT, 256>>>(x, h, ln1_g + l * DD, ln1_b + l * DD);
        {   // fused QKV (BIG tiles; 768 % 128 == 0 so segments align)
            GemmP p = base_p();
            p.A = h; p.lda = DD;
            p.B0 = Wq_l; p.B1 = Wk_l; p.B2 = Wv_l; p.ldb = DD;
            p.C0 = q; p.C1 = kout; p.C2 = vout; p.ldc = DD;
            p.bias0 = bq + l * DD; p.bias1 = nullptr; p.bias2 = bv + l * DD;
            p.s0 = SCALE_Q; p.s1 = 1.f; p.s2 = 1.f;
            p.segW = DD;
            p.M = BT; p.N = 3 * DD; p.K = DD;
            launch_g<0, 1>(p, 1);
        }
        flash_kernel<<<dim3(TT / 64, BB * HH, 1), 128>>>(
            q, kout, vout, o, nullptr, TT, DTD, 1, nullptr, nullptr, TT);
        {   // x += o @ Wo + bo  (small tiles, split-K atomics)
            GemmP p = base_p();
            p.A = o; p.lda = DD;
            p.B0 = Wo_l; p.ldb = DD;
            p.C0 = x; p.ldc = DD;
            p.bias0 = bo + l * DD;
            p.M = BT; p.N = DD; p.K = DD;
            launch_g<0, 0>(p, 1, 4);
        }

        // ---- cross attention ----
        ln_kernel<<<BT, 256>>>(x, h, ln2_g + l * DD, ln2_b + l * DD);
        cudaMemsetAsync(q, 0, XBYTES);
        {   // q2 (small tiles, split-K atomics)
            GemmP p = base_p();
            p.A = h; p.lda = DD;
            p.B0 = Wcq_l; p.ldb = DD;
            p.C0 = q; p.ldc = DD;
            p.bias0 = bcq + l * DD; p.s0 = SCALE_Q;
            p.M = BT; p.N = DD; p.K = DD;
            launch_g<0, 0>(p, 1, 4);
        }
        {
            float* mir = (l >= LL / 2)
                       ? out_chw + (size_t)(l - LL / 2) * HH * TT * TAA : nullptr;
            flash_kernel<<<dim3(TT / 64, BB * HH, NSPLIT), 128>>>(
                q, ck_l, cv_l, nullptr, mir, TAA, TAD, 0, opart, msum, KVCH);
            flash_merge_kernel<<<BT, 256>>>(opart, msum, o);
        }
        {   // x += o @ Wco + bco  (small tiles, split-K atomics)
            GemmP p = base_p();
            p.A = o; p.lda = DD;
            p.B0 = Wco_l; p.ldb = DD;
            p.C0 = x; p.ldc = DD;
            p.bias0 = bco + l * DD;
            p.M = BT; p.N = DD; p.K = DD;
            launch_g<0, 0>(p, 1, 4);
        }

        // ---- MLP ----
        ln_kernel<<<BT, 256>>>(x, h, ln3_g + l * DD, ln3_b + l * DD);
        {   // hid = gelu(h @ W1 + b1)  (BIG tiles)
            GemmP p = base_p();
            p.A = h; p.lda = DD;
            p.B0 = W1_l; p.ldb = 4 * DD;
            p.C0 = hid; p.ldc = 4 * DD;
            p.bias0 = b1 + (size_t)l * 4 * DD; p.act = 1;
            p.M = BT; p.N = 4 * DD; p.K = DD;
            launch_g<0, 1>(p, 1);
        }
        {   // x += hid @ W2 + b2  (BIG tiles, split-K 8)
            GemmP p = base_p();
            p.A = hid; p.lda = 4 * DD;
            p.B0 = W2_l; p.ldb = DD;
            p.C0 = x; p.ldc = DD;
            p.bias0 = b2 + l * DD;
            p.M = BT; p.N = DD; p.K = 4 * DD;
            launch_g<0, 1>(p, 1, 8);
        }
    }

    // final LN + tied-embedding logits (BIG tiles)
    ln_kernel<<<BT, 256>>>(x, h, lnf_g, lnf_b);
    {
        GemmP p = base_p();
        p.A = h; p.lda = DD;
        p.B0 = tok_emb; p.ldb = DD;
        p.C0 = out_logits; p.ldc = VV;
        p.M = BT; p.N = VV; p.K = DD;
        launch_g<1, 1>(p, 1);
    }
}

// round 10
// speedup vs baseline: 3.2862x; 1.0071x over previous
#include <cuda_runtime.h>
#include <cuda_bf16.h>
#include <math.h>
#include <stdint.h>

// ---------------- problem constants ----------------
#define BB   4
#define TT   256
#define TAA  1500
#define DD   768
#define HH   12
#define LL   12
#define VV   51865
#define DHH  64
#define BT   (BB*TT)          // 1024
#define SCALE_Q 0.125f
#define BTAD ((size_t)BB*TAA*DD)
#define NSPLIT 4

// ---------------- scratch ----------------
__device__ float g_x  [BT*DD];
__device__ float g_h  [BT*DD];
__device__ float g_q  [BT*DD];
__device__ float g_o  [BT*DD];
__device__ float g_ckall[(size_t)LL*BTAD];
__device__ float g_cvall[(size_t)LL*BTAD];
__device__ float g_hid[(size_t)BT*4*DD];
__device__ float g_opart[(size_t)NSPLIT*BT*DD];
__device__ float2 g_msum[(size_t)NSPLIT*BB*HH*TT];

// ---------------- shared helpers ----------------
__device__ __forceinline__ uint32_t pack_bf(float a, float b) {
    __nv_bfloat162 t;
    t.x = __float2bfloat16_rn(a);
    t.y = __float2bfloat16_rn(b);
    return *(uint32_t*)&t;
}

__device__ __forceinline__ void split_pair(float2 v, uint32_t& hi, uint32_t& lo) {
    __nv_bfloat16 hx = __float2bfloat16_rn(v.x);
    __nv_bfloat16 hy = __float2bfloat16_rn(v.y);
    hi = pack_bf(v.x, v.y);
    lo = pack_bf(v.x - __bfloat162float(hx), v.y - __bfloat162float(hy));
}

__device__ __forceinline__ uint32_t lo_pack(float a, float b) {
    float ra = a - __bfloat162float(__float2bfloat16_rn(a));
    float rb = b - __bfloat162float(__float2bfloat16_rn(b));
    return pack_bf(ra, rb);
}

__device__ __forceinline__ void mma_bf16(float* c, const uint32_t* a, const uint32_t* b) {
    asm volatile(
        "mma.sync.aligned.m16n8k16.row.col.f32.bf16.bf16.f32 "
        "{%0,%1,%2,%3}, {%4,%5,%6,%7}, {%8,%9}, {%0,%1,%2,%3};"
        : "+f"(c[0]), "+f"(c[1]), "+f"(c[2]), "+f"(c[3])
        : "r"(a[0]), "r"(a[1]), "r"(a[2]), "r"(a[3]), "r"(b[0]), "r"(b[1]));
}

// ---------------- bf16 split GEMM (3-term) + split-K ----------------
// BIG=0: 128x64 tile, 256 thr, TBK=32. BIG=1: 128x128 tile, 512 thr, TBK=64.
// Warp tile 32x32 in both.
struct GemmP {
    const float *A, *B0, *B1, *B2;
    float *C0, *C1, *C2;
    const float *bias0, *bias1, *bias2;
    int M, N, K, lda, ldb, ldc, Hd, segW, act, splitK, kc;
    long sA0, sA1, sB0, sB1, sC0, sC1, sBias;
    float s0, s1, s2;
};

template <int NT, int BIG>
__global__ __launch_bounds__(BIG ? 512 : 256, BIG ? 1 : 2) void gemm_bf3_kernel(GemmP p)
{
    constexpr int BN   = BIG ? 128 : 64;
    constexpr int NTHR = BIG ? 512 : 256;
    constexpr int TBKv = BIG ? 64 : 32;
    constexpr int KP   = TBKv / 2;            // bf16x2 pairs per row
    constexpr int ALD  = BIG ? 36 : 20;       // A / NT-B smem stride (conflict-free)
    constexpr int BLDN = BIG ? 136 : 72;      // NN-B smem stride (≡8 mod 32)
    constexpr int AIT  = 128 * KP / NTHR;     // 8
    constexpr int BIT  = BN * KP / NTHR;      // BIG 8, small 4
    constexpr int BSZ  = BIG ? (128 * 36) : (64 * 20);   // covers NT (BN*ALD) and NN (KP*BLDN)

    __shared__ uint32_t AH[128][ALD];
    __shared__ uint32_t AL[128][ALD];
    __shared__ uint32_t BH[BSZ];
    __shared__ uint32_t BL[BSZ];

    int z = blockIdx.z;
    int sk = z % p.splitK;
    int zz = z / p.splitK;
    int zb = zz / p.Hd, zh = zz % p.Hd;
    int bm = blockIdx.y * 128, bn = blockIdx.x * BN;
    int seg = bn / p.segW;
    int bnl = bn - seg * p.segW;

    const float* A = p.A + zb * p.sA0 + zh * p.sA1;
    const float* B = (seg == 0 ? p.B0 : seg == 1 ? p.B1 : p.B2) + zb * p.sB0 + zh * p.sB1;
    float* C = (seg == 0 ? p.C0 : seg == 1 ? p.C1 : p.C2) + zb * p.sC0 + zh * p.sC1;
    const float* bias = (seg == 0 ? p.bias0 : seg == 1 ? p.bias1 : p.bias2);
    if (bias) bias += zh * p.sBias;
    float scl = seg == 0 ? p.s0 : seg == 1 ? p.s1 : p.s2;
    bool atom = p.splitK > 1;

    int M = p.M, N = p.N;
    int lda = p.lda, ldb = p.ldb, ldc = p.ldc;
    int kstart = sk * p.kc;
    int kend = min(p.K, kstart + p.kc);

    int tid  = threadIdx.x;
    int lane = tid & 31;
    int warp = tid >> 5;
    int g    = lane >> 2;
    int tig  = lane & 3;
    int m0w  = (warp & 3) * 32;
    int n0w  = (warp >> 2) * 32;

    float c[2][4][4];
#pragma unroll
    for (int mi = 0; mi < 2; mi++)
#pragma unroll
        for (int ni = 0; ni < 4; ni++)
#pragma unroll
            for (int e = 0; e < 4; e++) c[mi][ni][e] = 0.f;

    int iters = (kend - kstart + TBKv - 1) / TBKv;
    float2 ra[AIT], rb[BIT];

    // --- prefetch tile 0 ---
    {
        int kk = kstart;
#pragma unroll
        for (int i = 0; i < AIT; i++) {
            int pidx = i * NTHR + tid;
            int r = pidx / KP, kp = pidx % KP;
            int gr = bm + r, k0 = kk + 2 * kp;
            float2 v = {0.f, 0.f};
            if (gr < M) {
                if (k0 + 1 < kend)      v = *(const float2*)&A[(long)gr * lda + k0];
                else if (k0 < kend)     v.x = A[(long)gr * lda + k0];
            }
            ra[i] = v;
        }
#pragma unroll
        for (int i = 0; i < BIT; i++) {
            int pidx = i * NTHR + tid;
            float2 v = {0.f, 0.f};
            if (NT) {
                int n = pidx / KP, kp = pidx % KP;
                int k0 = kk + 2 * kp;
                if (bn + n < N) {
                    long base = (long)(bnl + n) * ldb;
                    if (k0 + 1 < kend)  v = *(const float2*)&B[base + k0];
                    else if (k0 < kend) v.x = B[base + k0];
                }
            } else {
                int n = pidx % BN, kp = pidx / BN;
                int k0 = kk + 2 * kp;
                if (bn + n < N) {
                    if (k0 < kend)     v.x = B[(long)k0 * ldb + bnl + n];
                    if (k0 + 1 < kend) v.y = B[(long)(k0 + 1) * ldb + bnl + n];
                }
            }
            rb[i] = v;
        }
    }

    for (int it = 0; it < iters; it++) {
#pragma unroll
        for (int i = 0; i < AIT; i++) {
            int pidx = i * NTHR + tid;
            int r = pidx / KP, kp = pidx % KP;
            split_pair(ra[i], AH[r][kp], AL[r][kp]);
        }
#pragma unroll
        for (int i = 0; i < BIT; i++) {
            int pidx = i * NTHR + tid;
            uint32_t hi, lo;
            split_pair(rb[i], hi, lo);
            if (NT) {
                int n = pidx / KP, kp = pidx % KP;
                BH[n * ALD + kp] = hi;
                BL[n * ALD + kp] = lo;
            } else {
                int n = pidx % BN, kp = pidx / BN;
                BH[kp * BLDN + n] = hi;
                BL[kp * BLDN + n] = lo;
            }
        }
        __syncthreads();

        if (it + 1 < iters) {
            int kk = kstart + (it + 1) * TBKv;
#pragma unroll
            for (int i = 0; i < AIT; i++) {
                int pidx = i * NTHR + tid;
                int r = pidx / KP, kp = pidx % KP;
                int gr = bm + r, k0 = kk + 2 * kp;
                float2 v = {0.f, 0.f};
                if (gr < M) {
                    if (k0 + 1 < kend)  v = *(const float2*)&A[(long)gr * lda + k0];
                    else if (k0 < kend) v.x = A[(long)gr * lda + k0];
                }
                ra[i] = v;
            }
#pragma unroll
            for (int i = 0; i < BIT; i++) {
                int pidx = i * NTHR + tid;
                float2 v = {0.f, 0.f};
                if (NT) {
                    int n = pidx / KP, kp = pidx % KP;
                    int k0 = kk + 2 * kp;
                    if (bn + n < N) {
                        long base = (long)(bnl + n) * ldb;
                        if (k0 + 1 < kend)  v = *(const float2*)&B[base + k0];
                        else if (k0 < kend) v.x = B[base + k0];
                    }
                } else {
                    int n = pidx % BN, kp = pidx / BN;
                    int k0 = kk + 2 * kp;
                    if (bn + n < N) {
                        if (k0 < kend)     v.x = B[(long)k0 * ldb + bnl + n];
                        if (k0 + 1 < kend) v.y = B[(long)(k0 + 1) * ldb + bnl + n];
                    }
                }
                rb[i] = v;
            }
        }

#pragma unroll
        for (int h = 0; h < TBKv / 16; h++) {
            int kb = h * 8;
            uint32_t aH4[2][4], aL4[2][4];
#pragma unroll
            for (int mi = 0; mi < 2; mi++) {
                int m = m0w + mi * 16 + g;
                aH4[mi][0] = AH[m    ][kb + tig];
                aH4[mi][1] = AH[m + 8][kb + tig];
                aH4[mi][2] = AH[m    ][kb + tig + 4];
                aH4[mi][3] = AH[m + 8][kb + tig + 4];
                aL4[mi][0] = AL[m    ][kb + tig];
                aL4[mi][1] = AL[m + 8][kb + tig];
                aL4[mi][2] = AL[m    ][kb + tig + 4];
                aL4[mi][3] = AL[m + 8][kb + tig + 4];
            }
            uint32_t bh2[4][2], bl2[4][2];
#pragma unroll
            for (int ni = 0; ni < 4; ni++) {
                int n = n0w + ni * 8 + g;
                if (NT) {
                    bh2[ni][0] = BH[n * ALD + kb + tig];
                    bh2[ni][1] = BH[n * ALD + kb + tig + 4];
                    bl2[ni][0] = BL[n * ALD + kb + tig];
                    bl2[ni][1] = BL[n * ALD + kb + tig + 4];
                } else {
                    bh2[ni][0] = BH[(kb + tig) * BLDN + n];
                    bh2[ni][1] = BH[(kb + tig + 4) * BLDN + n];
                    bl2[ni][0] = BL[(kb + tig) * BLDN + n];
                    bl2[ni][1] = BL[(kb + tig + 4) * BLDN + n];
                }
            }
#pragma unroll
            for (int mi = 0; mi < 2; mi++)
#pragma unroll
                for (int ni = 0; ni < 4; ni++) {
                    mma_bf16(c[mi][ni], aH4[mi], bl2[ni]);
                    mma_bf16(c[mi][ni], aL4[mi], bh2[ni]);
                    mma_bf16(c[mi][ni], aH4[mi], bh2[ni]);
                }
        }
        __syncthreads();
    }

#pragma unroll
    for (int mi = 0; mi < 2; mi++) {
#pragma unroll
        for (int ni = 0; ni < 4; ni++) {
#pragma unroll
            for (int e = 0; e < 4; e++) {
                int row = bm + m0w + mi * 16 + g + ((e >= 2) ? 8 : 0);
                int gcol = bn + n0w + ni * 8 + tig * 2 + (e & 1);
                if (row >= M || gcol >= N) continue;
                int lc = gcol - seg * p.segW;
                float v = c[mi][ni][e];
                if (bias && (!atom || sk == 0)) v += bias[lc];
                v *= scl;
                long ci = (long)row * ldc + lc;
                if (atom) {
                    atomicAdd(&C[ci], v);
                } else {
                    if (p.act == 1) v = 0.5f * v * (1.f + erff(v * 0.70710678118654752f));
                    C[ci] = v;
                }
            }
        }
    }
}

// ---------------- fused flash attention (optionally KV-split) ----------------
__global__ __launch_bounds__(128) void flash_kernel(
    const float* __restrict__ Qb, const float* __restrict__ Kb,
    const float* __restrict__ Vb, float* __restrict__ Ob,
    float* __restrict__ mir, int lenKV, long kvBStride, int causal,
    float* __restrict__ Opart, float2* __restrict__ Msum, int kvChunk)
{
    __shared__ uint32_t Kh[64][36], Kl[64][36];
    __shared__ uint32_t Vh[64][33], Vl[64][33];

    int mt = blockIdx.x;
    int by = blockIdx.y;
    int sp = blockIdx.z;
    int b = by / HH, hh = by % HH;

    int kvStart = sp * kvChunk;
    int kvEnd = min(lenKV, kvStart + kvChunk);

    const float* Q = Qb + ((long)b * TT + mt * 64) * DD + hh * DHH;
    const float* K = Kb + (long)b * kvBStride + hh * DHH;
    const float* V = Vb + (long)b * kvBStride + hh * DHH;
    float* Mr = (mir && b == 0)
              ? mir + (size_t)hh * TT * TAA + (size_t)mt * 64 * TAA : nullptr;

    int tid = threadIdx.x;
    int lane = tid & 31, warp = tid >> 5;
    int g = lane >> 2, tig = lane & 3;
    int m0w = warp * 16;

    uint32_t Qah[4][4], Qal[4][4];
#pragma unroll
    for (int kb = 0; kb < 4; kb++) {
        int c0 = 16 * kb + 2 * tig;
        const float* r0 = Q + (long)(m0w + g) * DD;
        const float* r1 = Q + (long)(m0w + g + 8) * DD;
        float2 v;
        v = *(const float2*)(r0 + c0);     split_pair(v, Qah[kb][0], Qal[kb][0]);
        v = *(const float2*)(r1 + c0);     split_pair(v, Qah[kb][1], Qal[kb][1]);
        v = *(const float2*)(r0 + c0 + 8); split_pair(v, Qah[kb][2], Qal[kb][2]);
        v = *(const float2*)(r1 + c0 + 8); split_pair(v, Qah[kb][3], Qal[kb][3]);
    }

    float acc[8][4];
#pragma unroll
    for (int j = 0; j < 8; j++)
#pragma unroll
        for (int e = 0; e < 4; e++) acc[j][e] = 0.f;
    float m0 = -1e30f, m1 = -1e30f, sum0 = 0.f, sum1 = 0.f;

    int chBeg = kvStart >> 6;
    int chEnd = (kvEnd + 63) >> 6;
    if (causal) chEnd = min(chEnd, mt + 1);

    for (int ch = chBeg; ch < chEnd; ch++) {
        int n0 = ch * 64;
#pragma unroll
        for (int i = 0; i < 16; i++) {
            int idx = i * 128 + tid;
            int r = idx >> 5, c = idx & 31;
            float2 v = {0.f, 0.f};
            if (n0 + r < kvEnd) v = *(const float2*)(K + (long)(n0 + r) * DD + 2 * c);
            split_pair(v, Kh[r][c], Kl[r][c]);
        }
#pragma unroll
        for (int i = 0; i < 16; i++) {
            int idx = i * 128 + tid;
            int d = idx & 63, pr = idx >> 6;
            float2 v = {0.f, 0.f};
            int r0i = n0 + 2 * pr;
            if (r0i < kvEnd)     v.x = V[(long)r0i * DD + d];
            if (r0i + 1 < kvEnd) v.y = V[(long)(r0i + 1) * DD + d];
            split_pair(v, Vh[d][pr], Vl[d][pr]);
        }
        __syncthreads();

        float s[8][4];
#pragma unroll
        for (int j = 0; j < 8; j++)
#pragma unroll
            for (int e = 0; e < 4; e++) s[j][e] = 0.f;
#pragma unroll
        for (int kb = 0; kb < 4; kb++) {
#pragma unroll
            for (int j = 0; j < 8; j++) {
                uint32_t bh[2] = { Kh[8 * j + g][8 * kb + tig], Kh[8 * j + g][8 * kb + tig + 4] };
                uint32_t bl[2] = { Kl[8 * j + g][8 * kb + tig], Kl[8 * j + g][8 * kb + tig + 4] };
                mma_bf16(s[j], Qah[kb], bl);
                mma_bf16(s[j], Qal[kb], bh);
                mma_bf16(s[j], Qah[kb], bh);
            }
        }

        if (Mr) {
#pragma unroll
            for (int j = 0; j < 8; j++) {
                int col = n0 + 8 * j + 2 * tig;
                if (col < kvEnd) {
                    float2 v0 = { s[j][0], s[j][1] };
                    float2 v1 = { s[j][2], s[j][3] };
                    *(float2*)&Mr[(long)(m0w + g) * TAA + col] = v0;
                    *(float2*)&Mr[(long)(m0w + g + 8) * TAA + col] = v1;
                }
            }
        }

        if (causal && ch == mt) {
            int t0 = mt * 64 + m0w + g;
#pragma unroll
            for (int j = 0; j < 8; j++) {
                int col = n0 + 8 * j + 2 * tig;
                if (col     > t0)     s[j][0] = -1e30f;
                if (col + 1 > t0)     s[j][1] = -1e30f;
                if (col     > t0 + 8) s[j][2] = -1e30f;
                if (col + 1 > t0 + 8) s[j][3] = -1e30f;
            }
        }
        if (n0 + 64 > kvEnd) {
#pragma unroll
            for (int j = 0; j < 8; j++) {
                int col = n0 + 8 * j + 2 * tig;
                if (col     >= kvEnd) { s[j][0] = -1e30f; s[j][2] = -1e30f; }
                if (col + 1 >= kvEnd) { s[j][1] = -1e30f; s[j][3] = -1e30f; }
            }
        }

        float mx0 = -1e30f, mx1 = -1e30f;
#pragma unroll
        for (int j = 0; j < 8; j++) {
            mx0 = fmaxf(mx0, fmaxf(s[j][0], s[j][1]));
            mx1 = fmaxf(mx1, fmaxf(s[j][2], s[j][3]));
        }
        mx0 = fmaxf(mx0, __shfl_xor_sync(0xffffffffu, mx0, 1));
        mx0 = fmaxf(mx0, __shfl_xor_sync(0xffffffffu, mx0, 2));
        mx1 = fmaxf(mx1, __shfl_xor_sync(0xffffffffu, mx1, 1));
        mx1 = fmaxf(mx1, __shfl_xor_sync(0xffffffffu, mx1, 2));
        float mn0 = fmaxf(m0, mx0), mn1 = fmaxf(m1, mx1);
        float a0 = __expf(m0 - mn0), a1 = __expf(m1 - mn1);
        float ps0 = 0.f, ps1 = 0.f;
#pragma unroll
        for (int j = 0; j < 8; j++) {
            s[j][0] = __expf(s[j][0] - mn0);
            s[j][1] = __expf(s[j][1] - mn0);
            s[j][2] = __expf(s[j][2] - mn1);
            s[j][3] = __expf(s[j][3] - mn1);
            ps0 += s[j][0] + s[j][1];
            ps1 += s[j][2] + s[j][3];
        }
        ps0 += __shfl_xor_sync(0xffffffffu, ps0, 1);
        ps0 += __shfl_xor_sync(0xffffffffu, ps0, 2);
        ps1 += __shfl_xor_sync(0xffffffffu, ps1, 1);
        ps1 += __shfl_xor_sync(0xffffffffu, ps1, 2);
        sum0 = sum0 * a0 + ps0;
        sum1 = sum1 * a1 + ps1;
        m0 = mn0; m1 = mn1;
#pragma unroll
        for (int j = 0; j < 8; j++) {
            acc[j][0] *= a0; acc[j][1] *= a0;
            acc[j][2] *= a1; acc[j][3] *= a1;
        }

#pragma unroll
        for (int kb = 0; kb < 4; kb++) {
            int j0 = 2 * kb, j1 = 2 * kb + 1;
            uint32_t Ah[4], Al[4];
            Ah[0] = pack_bf(s[j0][0], s[j0][1]);  Al[0] = lo_pack(s[j0][0], s[j0][1]);
            Ah[1] = pack_bf(s[j0][2], s[j0][3]);  Al[1] = lo_pack(s[j0][2], s[j0][3]);
            Ah[2] = pack_bf(s[j1][0], s[j1][1]);  Al[2] = lo_pack(s[j1][0], s[j1][1]);
            Ah[3] = pack_bf(s[j1][2], s[j1][3]);  Al[3] = lo_pack(s[j1][2], s[j1][3]);
#pragma unroll
            for (int jd = 0; jd < 8; jd++) {
                uint32_t bh[2] = { Vh[8 * jd + g][8 * kb + tig], Vh[8 * jd + g][8 * kb + tig + 4] };
                uint32_t bl[2] = { Vl[8 * jd + g][8 * kb + tig], Vl[8 * jd + g][8 * kb + tig + 4] };
                mma_bf16(acc[jd], Ah, bl);
                mma_bf16(acc[jd], Al, bh);
                mma_bf16(acc[jd], Ah, bh);
            }
        }
        __syncthreads();
    }

    if (Opart) {
        float* OP = Opart + (((long)sp * BT) + (long)b * TT + mt * 64) * DD + hh * DHH;
#pragma unroll
        for (int jd = 0; jd < 8; jd++) {
            int col = 8 * jd + 2 * tig;
            float2 v0 = { acc[jd][0], acc[jd][1] };
            float2 v1 = { acc[jd][2], acc[jd][3] };
            *(float2*)&OP[(long)(m0w + g) * DD + col] = v0;
            *(float2*)&OP[(long)(m0w + g + 8) * DD + col] = v1;
        }
        if (tig == 0) {
            long base = (((long)sp * BB + b) * HH + hh) * TT + mt * 64;
            Msum[base + m0w + g]     = make_float2(m0, sum0);
            Msum[base + m0w + g + 8] = make_float2(m1, sum1);
        }
    } else {
        float* O = Ob + ((long)b * TT + mt * 64) * DD + hh * DHH;
        float i0 = 1.f / sum0, i1 = 1.f / sum1;
#pragma unroll
        for (int jd = 0; jd < 8; jd++) {
            int col = 8 * jd + 2 * tig;
            float2 v0 = { acc[jd][0] * i0, acc[jd][1] * i0 };
            float2 v1 = { acc[jd][2] * i1, acc[jd][3] * i1 };
            *(float2*)&O[(long)(m0w + g) * DD + col] = v0;
            *(float2*)&O[(long)(m0w + g + 8) * DD + col] = v1;
        }
    }
}

__global__ __launch_bounds__(256) void flash_merge_kernel(
    const float* __restrict__ Opart, const float2* __restrict__ Msum,
    float* __restrict__ O)
{
    __shared__ float wgt[HH][NSPLIT];
    int row = blockIdx.x;
    int b = row / TT, t = row % TT;
    int tid = threadIdx.x;
    if (tid < HH) {
        int h = tid;
        float ms[NSPLIT], ss[NSPLIT];
        float m = -1e30f;
#pragma unroll
        for (int s = 0; s < NSPLIT; s++) {
            float2 v = Msum[(((long)s * BB + b) * HH + h) * TT + t];
            ms[s] = v.x; ss[s] = v.y;
            m = fmaxf(m, v.x);
        }
        float den = 0.f;
#pragma unroll
        for (int s = 0; s < NSPLIT; s++) den += ss[s] * __expf(ms[s] - m);
        float iden = 1.f / den;
#pragma unroll
        for (int s = 0; s < NSPLIT; s++) wgt[h][s] = __expf(ms[s] - m) * iden;
    }
    __syncthreads();
#pragma unroll
    for (int it = 0; it < 3; it++) {
        int d = tid + it * 256;
        int h = d >> 6;
        float acc = 0.f;
#pragma unroll
        for (int s = 0; s < NSPLIT; s++)
            acc += Opart[(((long)s * BT) + row) * DD + d] * wgt[h][s];
        O[(long)row * DD + d] = acc;
    }
}

// ---------------- elementwise / row kernels ----------------
__global__ __launch_bounds__(256) void embed_kernel(
    const int* __restrict__ tokens, const float* __restrict__ tok_emb,
    const float* __restrict__ pos_emb, float* __restrict__ x)
{
    int row = blockIdx.x;
    int t = row % TT;
    int tok = tokens[row];
    const float* te = tok_emb + (long)tok * DD;
    const float* pe = pos_emb + (long)t * DD;
    float* xr = x + (long)row * DD;
#pragma unroll
    for (int it = 0; it < 3; it++) {
        int j = threadIdx.x + it * 256;
        xr[j] = te[j] + pe[j];
    }
}

__global__ __launch_bounds__(256) void ln_kernel(
    const float* __restrict__ x, float* __restrict__ y,
    const float* __restrict__ g, const float* __restrict__ b)
{
    __shared__ float red[256];
    int row = blockIdx.x;
    const float* xr = x + (long)row * DD;
    float* yr = y + (long)row * DD;
    int tid = threadIdx.x;
    float v0 = xr[tid], v1 = xr[tid + 256], v2 = xr[tid + 512];
    float s = v0 + v1 + v2;
    red[tid] = s; __syncthreads();
    for (int st = 128; st > 0; st >>= 1) { if (tid < st) red[tid] += red[tid + st]; __syncthreads(); }
    float mean = red[0] * (1.f / DD);
    __syncthreads();
    float d0 = v0 - mean, d1 = v1 - mean, d2 = v2 - mean;
    red[tid] = d0 * d0 + d1 * d1 + d2 * d2; __syncthreads();
    for (int st = 128; st > 0; st >>= 1) { if (tid < st) red[tid] += red[tid + st]; __syncthreads(); }
    float inv = rsqrtf(red[0] * (1.f / DD) + 1e-5f);
    yr[tid]       = d0 * inv * g[tid]       + b[tid];
    yr[tid + 256] = d1 * inv * g[tid + 256] + b[tid + 256];
    yr[tid + 512] = d2 * inv * g[tid + 512] + b[tid + 512];
}

// ---------------- host-side launch helpers ----------------
static GemmP base_p() {
    GemmP p;
    p.A = nullptr; p.B0 = p.B1 = p.B2 = nullptr;
    p.C0 = p.C1 = p.C2 = nullptr;
    p.bias0 = p.bias1 = p.bias2 = nullptr;
    p.M = p.N = p.K = 0; p.lda = p.ldb = p.ldc = 0;
    p.Hd = 1; p.segW = 1 << 30; p.act = 0; p.splitK = 1; p.kc = 0;
    p.sA0 = p.sA1 = p.sB0 = p.sB1 = p.sC0 = p.sC1 = p.sBias = 0;
    p.s0 = p.s1 = p.s2 = 1.f;
    return p;
}

template <int NT, int BIG>
static inline void launch_g(GemmP p, int batch, int splitK = 1) {
    p.splitK = splitK;
    constexpr int TBKv = BIG ? 64 : 32;
    int kc = (p.K + splitK - 1) / splitK;
    p.kc = ((kc + TBKv - 1) / TBKv) * TBKv;
    constexpr int BN = BIG ? 128 : 64;
    constexpr int NTHR = BIG ? 512 : 256;
    dim3 grd((p.N + BN - 1) / BN, (p.M + 127) / 128, batch * splitK);
    gemm_bf3_kernel<NT, BIG><<<grd, NTHR>>>(p);
}

extern "C" void kernel_launch(void* const* d_in, const int* in_sizes, int n_in,
                              void* d_out, int out_size)
{
    (void)in_sizes; (void)n_in; (void)out_size;

    const int*   tokens  = (const int*)  d_in[0];
    const float* xa      = (const float*)d_in[1];
    const float* tok_emb = (const float*)d_in[2];
    const float* pos_emb = (const float*)d_in[3];
    const float* Wq      = (const float*)d_in[4];
    const float* bq      = (const float*)d_in[5];
    const float* Wk      = (const float*)d_in[6];
    const float* Wv      = (const float*)d_in[7];
    const float* bv      = (const float*)d_in[8];
    const float* Wo      = (const float*)d_in[9];
    const float* bo      = (const float*)d_in[10];
    const float* ln1_g   = (const float*)d_in[11];
    const float* ln1_b   = (const float*)d_in[12];
    const float* Wcq     = (const float*)d_in[13];
    const float* bcq     = (const float*)d_in[14];
    const float* Wck     = (const float*)d_in[15];
    const float* Wcv     = (const float*)d_in[16];
    const float* bcv     = (const float*)d_in[17];
    const float* Wco     = (const float*)d_in[18];
    const float* bco     = (const float*)d_in[19];
    const float* ln2_g   = (const float*)d_in[20];
    const float* ln2_b   = (const float*)d_in[21];
    const float* W1      = (const float*)d_in[22];
    const float* b1      = (const float*)d_in[23];
    const float* W2      = (const float*)d_in[24];
    const float* b2      = (const float*)d_in[25];
    const float* ln3_g   = (const float*)d_in[26];
    const float* ln3_b   = (const float*)d_in[27];
    const float* lnf_g   = (const float*)d_in[28];
    const float* lnf_b   = (const float*)d_in[29];

    float* out = (float*)d_out;
    float* out_logits = out;
    float* out_chw    = out_logits + (size_t)BB * TT * VV;
    float* out_kv     = out_chw + (size_t)(LL / 2) * HH * TT * TAA;

    float *x, *h, *q, *o, *ckall, *cvall, *hid, *opart;
    float2* msum;
    cudaGetSymbolAddress((void**)&x,     g_x);
    cudaGetSymbolAddress((void**)&h,     g_h);
    cudaGetSymbolAddress((void**)&q,     g_q);
    cudaGetSymbolAddress((void**)&o,     g_o);
    cudaGetSymbolAddress((void**)&ckall, g_ckall);
    cudaGetSymbolAddress((void**)&cvall, g_cvall);
    cudaGetSymbolAddress((void**)&hid,   g_hid);
    cudaGetSymbolAddress((void**)&opart, g_opart);
    cudaGetSymbolAddress((void**)&msum,  g_msum);

    embed_kernel<<<BT, 256>>>(tokens, tok_emb, pos_emb, x);

    const long DTD = (long)TT * DD;
    const long TAD = (long)TAA * DD;
    const size_t XBYTES = (size_t)BT * DD * sizeof(float);
    const int KVCH = ((TAA + NSPLIT * 64 - 1) / (NSPLIT * 64)) * 64;   // 384

    // cross K/V for ALL layers, batched over z=12 (BIG tiles)
    {
        GemmP p = base_p();
        p.A = xa; p.lda = DD;
        p.B0 = Wck; p.ldb = DD; p.sB1 = (long)DD * DD;
        p.C0 = ckall; p.ldc = DD; p.sC1 = (long)BTAD;
        p.M = BB * TAA; p.N = DD; p.K = DD; p.Hd = LL;
        launch_g<0, 1>(p, LL);
        p.B0 = Wcv; p.C0 = cvall;
        p.bias0 = bcv; p.sBias = DD;
        launch_g<0, 1>(p, LL);
    }

    for (int l = 0; l < LL; l++) {
        const float* Wq_l = Wq + (size_t)l * DD * DD;
        const float* Wk_l = Wk + (size_t)l * DD * DD;
        const float* Wv_l = Wv + (size_t)l * DD * DD;
        const float* Wo_l = Wo + (size_t)l * DD * DD;
        const float* Wcq_l = Wcq + (size_t)l * DD * DD;
        const float* Wco_l = Wco + (size_t)l * DD * DD;
        const float* W1_l = W1 + (size_t)l * DD * 4 * DD;
        const float* W2_l = W2 + (size_t)l * 4 * DD * DD;

        float* kout = out_kv + (size_t)(2 * l) * BT * DD;
        float* vout = out_kv + (size_t)(2 * l + 1) * BT * DD;
        float* ck_l = ckall + (size_t)l * BTAD;
        float* cv_l = cvall + (size_t)l * BTAD;

        // ---- self attention ----
        ln_kernel<<<BT, 256>>>(x, h, ln1_g + l * DD, ln1_b + l * DD);
        {   // fused QKV (BIG tiles)
            GemmP p = base_p();
            p.A = h; p.lda = DD;
            p.B0 = Wq_l; p.B1 = Wk_l; p.B2 = Wv_l; p.ldb = DD;
            p.C0 = q; p.C1 = kout; p.C2 = vout; p.ldc = DD;
            p.bias0 = bq + l * DD; p.bias1 = nullptr; p.bias2 = bv + l * DD;
            p.s0 = SCALE_Q; p.s1 = 1.f; p.s2 = 1.f;
            p.segW = DD;
            p.M = BT; p.N = 3 * DD; p.K = DD;
            launch_g<0, 1>(p, 1);
        }
        flash_kernel<<<dim3(TT / 64, BB * HH, 1), 128>>>(
            q, kout, vout, o, nullptr, TT, DTD, 1, nullptr, nullptr, TT);
        {   // x += o @ Wo + bo  (small tiles, split-K atomics)
            GemmP p = base_p();
            p.A = o; p.lda = DD;
            p.B0 = Wo_l; p.ldb = DD;
            p.C0 = x; p.ldc = DD;
            p.bias0 = bo + l * DD;
            p.M = BT; p.N = DD; p.K = DD;
            launch_g<0, 0>(p, 1, 4);
        }

        // ---- cross attention ----
        ln_kernel<<<BT, 256>>>(x, h, ln2_g + l * DD, ln2_b + l * DD);
        cudaMemsetAsync(q, 0, XBYTES);
        {   // q2 (small tiles, split-K atomics)
            GemmP p = base_p();
            p.A = h; p.lda = DD;
            p.B0 = Wcq_l; p.ldb = DD;
            p.C0 = q; p.ldc = DD;
            p.bias0 = bcq + l * DD; p.s0 = SCALE_Q;
            p.M = BT; p.N = DD; p.K = DD;
            launch_g<0, 0>(p, 1, 4);
        }
        {
            float* mir = (l >= LL / 2)
                       ? out_chw + (size_t)(l - LL / 2) * HH * TT * TAA : nullptr;
            flash_kernel<<<dim3(TT / 64, BB * HH, NSPLIT), 128>>>(
                q, ck_l, cv_l, nullptr, mir, TAA, TAD, 0, opart, msum, KVCH);
            flash_merge_kernel<<<BT, 256>>>(opart, msum, o);
        }
        {   // x += o @ Wco + bco  (small tiles, split-K atomics)
            GemmP p = base_p();
            p.A = o; p.lda = DD;
            p.B0 = Wco_l; p.ldb = DD;
            p.C0 = x; p.ldc = DD;
            p.bias0 = bco + l * DD;
            p.M = BT; p.N = DD; p.K = DD;
            launch_g<0, 0>(p, 1, 4);
        }

        // ---- MLP ----
        ln_kernel<<<BT, 256>>>(x, h, ln3_g + l * DD, ln3_b + l * DD);
        {   // hid = gelu(h @ W1 + b1)  (BIG tiles)
            GemmP p = base_p();
            p.A = h; p.lda = DD;
            p.B0 = W1_l; p.ldb = 4 * DD;
            p.C0 = hid; p.ldc = 4 * DD;
            p.bias0 = b1 + (size_t)l * 4 * DD; p.act = 1;
            p.M = BT; p.N = 4 * DD; p.K = DD;
            launch_g<0, 1>(p, 1);
        }
        {   // x += hid @ W2 + b2  (BIG tiles, split-K 8)
            GemmP p = base_p();
            p.A = hid; p.lda = 4 * DD;
            p.B0 = W2_l; p.ldb = DD;
            p.C0 = x; p.ldc = DD;
            p.bias0 = b2 + l * DD;
            p.M = BT; p.N = DD; p.K = 4 * DD;
            launch_g<0, 1>(p, 1, 8);
        }
    }

    // final LN + tied-embedding logits (BIG tiles)
    ln_kernel<<<BT, 256>>>(x, h, lnf_g, lnf_b);
    {
        GemmP p = base_p();
        p.A = h; p.lda = DD;
        p.B0 = tok_emb; p.ldb = DD;
        p.C0 = out_logits; p.ldc = VV;
        p.M = BT; p.N = VV; p.K = DD;
        launch_g<1, 1>(p, 1);
    }
}